// round 1
// baseline (speedup 1.0000x reference)
#include <cuda_runtime.h>

#define Bn 4
#define Cn 256
#define Hn 256
#define On 256
#define Nn 4096
#define Gn 32

// Scratch (device globals; no allocation allowed)
__device__ float g_k [Bn*Hn*Nn];
__device__ float g_q [Bn*Hn*Nn];
__device__ float g_v1[Bn*Hn*Nn];
__device__ float g_v2[Bn*Hn*Nn];
__device__ float g_v [Bn*On*Nn];

// ---------------------------------------------------------------------------
// Projection GEMM: out[b,h,n] = sum_c W[h,c] * X[b,c,n] + bias[h]
// Block tile 64(h) x 64(n), K-chunks of 16, 256 threads, 4x4 register tile.
// ---------------------------------------------------------------------------
__global__ __launch_bounds__(256) void proj_kernel(
    const float* __restrict__ W, const float* __restrict__ bias,
    const float* __restrict__ X, float* __restrict__ out)
{
    __shared__ float As[16][64];   // As[kk][hi]
    __shared__ float Bs[16][64];   // Bs[kk][nj]

    const int tid = threadIdx.x;
    const int n0 = blockIdx.x * 64;
    const int h0 = blockIdx.y * 64;
    const int b  = blockIdx.z;
    const float* Xb = X + (size_t)b * Cn * Nn;

    const int ty = tid >> 4;       // 0..15
    const int tx = tid & 15;       // 0..15

    float acc[4][4] = {};

    for (int c0 = 0; c0 < Cn; c0 += 16) {
        {
            // A tile: 64 rows(h) x 16 cols(c), transposed into As[kk][hi]
            int hi = tid >> 2;
            int c4 = (tid & 3) * 4;
            const float4 w4 = *(const float4*)(W + (size_t)(h0 + hi) * Cn + c0 + c4);
            As[c4 + 0][hi] = w4.x;
            As[c4 + 1][hi] = w4.y;
            As[c4 + 2][hi] = w4.z;
            As[c4 + 3][hi] = w4.w;
            // B tile: 16 rows(c) x 64 cols(n)
            int kk = tid >> 4;
            int n4 = (tid & 15) * 4;
            *(float4*)&Bs[kk][n4] = *(const float4*)(Xb + (size_t)(c0 + kk) * Nn + n0 + n4);
        }
        __syncthreads();
        #pragma unroll
        for (int kk = 0; kk < 16; kk++) {
            float4 a4 = *(const float4*)&As[kk][ty * 4];
            float4 b4 = *(const float4*)&Bs[kk][tx * 4];
            float a[4] = {a4.x, a4.y, a4.z, a4.w};
            float bb[4] = {b4.x, b4.y, b4.z, b4.w};
            #pragma unroll
            for (int r = 0; r < 4; r++)
                #pragma unroll
                for (int c = 0; c < 4; c++)
                    acc[r][c] = fmaf(a[r], bb[c], acc[r][c]);
        }
        __syncthreads();
    }

    float* ob = out + (size_t)b * Hn * Nn;
    #pragma unroll
    for (int r = 0; r < 4; r++) {
        int h = h0 + ty * 4 + r;
        float bv = bias[h];
        float4 o4;
        o4.x = acc[r][0] + bv;
        o4.y = acc[r][1] + bv;
        o4.z = acc[r][2] + bv;
        o4.w = acc[r][3] + bv;
        *(float4*)(ob + (size_t)h * Nn + n0 + tx * 4) = o4;
    }
}

// ---------------------------------------------------------------------------
// Grouped conv1d (groups=32, kw=3, SAME pad) + bias + ReLU: g_v1 -> g_v2
// ---------------------------------------------------------------------------
__global__ __launch_bounds__(256) void gconv_kernel(
    const float* __restrict__ W2, const float* __restrict__ b2)
{
    const int tid = threadIdx.x;
    const int n = blockIdx.x * 256 + tid;
    const int h = blockIdx.y;
    const int b = blockIdx.z;
    const int g = h >> 3;           // 8 out-channels per group

    float w[24];
    #pragma unroll
    for (int j = 0; j < 24; j++) w[j] = W2[h * 24 + j];

    const float* in = g_v1 + ((size_t)b * Hn + g * 8) * Nn;
    float acc = b2[h];
    #pragma unroll
    for (int i = 0; i < 8; i++) {
        const float* row = in + (size_t)i * Nn;
        float xm1 = (n > 0)      ? row[n - 1] : 0.f;
        float x0  = row[n];
        float xp1 = (n < Nn - 1) ? row[n + 1] : 0.f;
        acc = fmaf(w[i * 3 + 0], xm1, acc);
        acc = fmaf(w[i * 3 + 1], x0,  acc);
        acc = fmaf(w[i * 3 + 2], xp1, acc);
    }
    g_v2[((size_t)b * Hn + h) * Nn + n] = fmaxf(acc, 0.f);
}

// ---------------------------------------------------------------------------
// Fused attention: out[b,o,m] = sum_n v[o,n] * exp(l[n,m]) / sum_n exp(l[n,m])
// l[n,m] = sum_h k[h,n] * q[h,m]   (no max subtraction — logits bounded)
// Block: one (b, 64-column m-tile). Full O=256 output panel in registers.
// ---------------------------------------------------------------------------
__global__ __launch_bounds__(256, 2) void attn_kernel(
    const float* __restrict__ gk, const float* __restrict__ gq,
    const float* __restrict__ gv, float* __restrict__ out)
{
    __shared__ float Ks[16][64];        // Ks[kk][ni]
    __shared__ float Qs[16][64];        // Qs[kk][mj]
    __shared__ float Es[64][68];        // exp(logits) tile, padded (68*4 = 272B rows)
    __shared__ float Vs[16][256];       // Vs[nn][o]
    __shared__ float colsum[64];
    __shared__ float colpart[4][64];

    const int tid = threadIdx.x;
    const int m0 = blockIdx.x * 64;
    const int b  = blockIdx.y;
    const int ty = tid >> 4;            // 0..15
    const int tx = tid & 15;            // 0..15

    const float* kb = gk + (size_t)b * Hn * Nn;
    const float* qb = gq + (size_t)b * Hn * Nn;
    const float* vb = gv + (size_t)b * On * Nn;

    if (tid < 64) colsum[tid] = 0.f;

    float acc2[16][4] = {};             // output panel: o = ty*16 + r, m = tx*4 + c

    for (int n0 = 0; n0 < Nn; n0 += 64) {
        // ---- Phase 1: logits tile [64n][64m] over H=256 ----
        float acc1[4][4] = {};          // n = ty*4 + r, m = tx*4 + c
        for (int h0 = 0; h0 < Hn; h0 += 16) {
            __syncthreads();
            {
                int row  = tid >> 4;            // 0..15 (h within chunk)
                int col4 = (tid & 15) * 4;
                *(float4*)&Ks[row][col4] = *(const float4*)(kb + (size_t)(h0 + row) * Nn + n0 + col4);
                *(float4*)&Qs[row][col4] = *(const float4*)(qb + (size_t)(h0 + row) * Nn + m0 + col4);
            }
            __syncthreads();
            #pragma unroll
            for (int kk = 0; kk < 16; kk++) {
                float4 a4 = *(const float4*)&Ks[kk][ty * 4];
                float4 b4 = *(const float4*)&Qs[kk][tx * 4];
                float a[4] = {a4.x, a4.y, a4.z, a4.w};
                float bb[4] = {b4.x, b4.y, b4.z, b4.w};
                #pragma unroll
                for (int r = 0; r < 4; r++)
                    #pragma unroll
                    for (int c = 0; c < 4; c++)
                        acc1[r][c] = fmaf(a[r], bb[c], acc1[r][c]);
            }
        }
        __syncthreads();   // protect Es (previous tile's phase-2 reads are done)
        #pragma unroll
        for (int r = 0; r < 4; r++) {
            float4 e4;
            e4.x = __expf(acc1[r][0]);
            e4.y = __expf(acc1[r][1]);
            e4.z = __expf(acc1[r][2]);
            e4.w = __expf(acc1[r][3]);
            *(float4*)&Es[ty * 4 + r][tx * 4] = e4;
        }
        __syncthreads();
        // ---- column (softmax-denominator) partial sums over this n-tile ----
        {
            int col = tid & 63;
            int seg = tid >> 6;
            float s = 0.f;
            #pragma unroll
            for (int i = 0; i < 16; i++) s += Es[seg * 16 + i][col];
            colpart[seg][col] = s;
        }
        __syncthreads();
        if (tid < 64)
            colsum[tid] += colpart[0][tid] + colpart[1][tid] + colpart[2][tid] + colpart[3][tid];

        // ---- Phase 2: acc2[o,m] += V[o, n-tile] @ Es[n-tile, m] ----
        for (int nc = 0; nc < 4; nc++) {
            __syncthreads();
            {
                const float4* src = (const float4*)(vb + (size_t)tid * Nn + n0 + nc * 16);
                float4 v0 = src[0], v1 = src[1], v2 = src[2], v3 = src[3];
                Vs[ 0][tid] = v0.x; Vs[ 1][tid] = v0.y; Vs[ 2][tid] = v0.z; Vs[ 3][tid] = v0.w;
                Vs[ 4][tid] = v1.x; Vs[ 5][tid] = v1.y; Vs[ 6][tid] = v1.z; Vs[ 7][tid] = v1.w;
                Vs[ 8][tid] = v2.x; Vs[ 9][tid] = v2.y; Vs[10][tid] = v2.z; Vs[11][tid] = v2.w;
                Vs[12][tid] = v3.x; Vs[13][tid] = v3.y; Vs[14][tid] = v3.z; Vs[15][tid] = v3.w;
            }
            __syncthreads();
            #pragma unroll
            for (int nn = 0; nn < 16; nn++) {
                int n = nc * 16 + nn;
                float4 b4 = *(const float4*)&Es[n][tx * 4];
                float bb[4] = {b4.x, b4.y, b4.z, b4.w};
                #pragma unroll
                for (int j = 0; j < 4; j++) {
                    float4 a4 = *(const float4*)&Vs[nn][ty * 16 + j * 4];
                    float a[4] = {a4.x, a4.y, a4.z, a4.w};
                    #pragma unroll
                    for (int e = 0; e < 4; e++)
                        #pragma unroll
                        for (int c = 0; c < 4; c++)
                            acc2[j * 4 + e][c] = fmaf(a[e], bb[c], acc2[j * 4 + e][c]);
                }
            }
        }
    }

    __syncthreads();
    float sc[4];
    #pragma unroll
    for (int c = 0; c < 4; c++) sc[c] = 1.f / colsum[tx * 4 + c];

    float* ob = out + (size_t)b * On * Nn;
    #pragma unroll
    for (int r = 0; r < 16; r++) {
        int o = ty * 16 + r;
        float4 o4;
        o4.x = acc2[r][0] * sc[0];
        o4.y = acc2[r][1] * sc[1];
        o4.z = acc2[r][2] * sc[2];
        o4.w = acc2[r][3] * sc[3];
        *(float4*)(ob + (size_t)o * Nn + m0 + tx * 4) = o4;
    }
}

// ---------------------------------------------------------------------------
extern "C" void kernel_launch(void* const* d_in, const int* in_sizes, int n_in,
                              void* d_out, int out_size)
{
    const float* x  = (const float*)d_in[0];
    const float* Wk = (const float*)d_in[1];
    const float* bk = (const float*)d_in[2];
    const float* Wq = (const float*)d_in[3];
    const float* bq = (const float*)d_in[4];
    const float* W1 = (const float*)d_in[5];
    const float* b1 = (const float*)d_in[6];
    const float* W2 = (const float*)d_in[7];
    const float* b2 = (const float*)d_in[8];
    const float* W3 = (const float*)d_in[9];
    const float* b3 = (const float*)d_in[10];
    float* out = (float*)d_out;

    float *gk, *gq, *gv1, *gv2, *gv;
    cudaGetSymbolAddress((void**)&gk,  g_k);
    cudaGetSymbolAddress((void**)&gq,  g_q);
    cudaGetSymbolAddress((void**)&gv1, g_v1);
    cudaGetSymbolAddress((void**)&gv2, g_v2);
    cudaGetSymbolAddress((void**)&gv,  g_v);

    dim3 pgrid(Nn / 64, Hn / 64, Bn);
    proj_kernel<<<pgrid, 256>>>(Wk, bk, x, gk);
    proj_kernel<<<pgrid, 256>>>(Wq, bq, x, gq);
    proj_kernel<<<pgrid, 256>>>(W1, b1, x, gv1);
    gconv_kernel<<<dim3(Nn / 256, Hn, Bn), 256>>>(W2, b2);
    proj_kernel<<<pgrid, 256>>>(W3, b3, gv2, gv);
    attn_kernel<<<dim3(Nn / 64, Bn), 256>>>(gk, gq, gv, out);
}

// round 5
// speedup vs baseline: 3.1402x; 3.1402x over previous
#include <cuda_runtime.h>
#include <cuda_fp16.h>
#include <cstdint>

#define Bn 4
#define Cn 256
#define Hn 256
#define On 256
#define Nn 4096

// ---------------- scratch (device globals; no allocation allowed) ----------
__device__ float  g_v1 [Bn*Hn*Nn];
__device__ float  g_v2 [Bn*Hn*Nn];
__device__ __half g_kt [(size_t)Bn*Nn*Hn];   // k^T  [b][n][h]  fp16
__device__ __half g_qhi[(size_t)Bn*Nn*Hn];   // q^T hi [b][n][h]
__device__ __half g_qlo[(size_t)Bn*Nn*Hn];   // q^T lo [b][n][h]
__device__ __half g_vh [(size_t)Bn*On*Nn];   // v [b][o][n] fp16

// ---------------- helpers ---------------------------------------------------
__device__ __forceinline__ uint32_t smem_u32(const void* p) {
    uint32_t a;
    asm("{ .reg .u64 t; cvta.to.shared.u64 t, %1; cvt.u32.u64 %0, t; }" : "=r"(a) : "l"(p));
    return a;
}
__device__ __forceinline__ uint32_t packh2(__half a, __half b) {
    __half2 h = __halves2half2(a, b);
    return *reinterpret_cast<const uint32_t*>(&h);
}
__device__ __forceinline__ void ldm4(uint32_t* r, uint32_t addr) {
    asm volatile("ldmatrix.sync.aligned.m8n8.x4.shared.b16 {%0,%1,%2,%3}, [%4];"
                 : "=r"(r[0]), "=r"(r[1]), "=r"(r[2]), "=r"(r[3]) : "r"(addr));
}
__device__ __forceinline__ void mma16816(float* c, const uint32_t* a, uint32_t b0, uint32_t b1) {
    asm volatile("mma.sync.aligned.m16n8k16.row.col.f32.f16.f16.f32 "
                 "{%0,%1,%2,%3}, {%4,%5,%6,%7}, {%8,%9}, {%0,%1,%2,%3};"
                 : "+f"(c[0]), "+f"(c[1]), "+f"(c[2]), "+f"(c[3])
                 : "r"(a[0]), "r"(a[1]), "r"(a[2]), "r"(a[3]), "r"(b0), "r"(b1));
}

// ---------------------------------------------------------------------------
// Projection GEMM (fp32 SIMT): out[h,n] = sum_c W[h,c] X[c,n] + bias[h]
// MODE 0: fp32 out [b][h][n]  | MODE 1: fp16 [b][n][h] | MODE 2: fp16 hi+lo
// MODE 3: fp16 [b][h][n]
// ---------------------------------------------------------------------------
template <int MODE>
__global__ __launch_bounds__(256) void proj_kernel(
    const float* __restrict__ W, const float* __restrict__ bias,
    const float* __restrict__ X, float* __restrict__ out32,
    __half* __restrict__ o16a, __half* __restrict__ o16b)
{
    __shared__ float As[16][64];
    __shared__ float Bs[16][64];

    const int tid = threadIdx.x;
    const int n0 = blockIdx.x * 64;
    const int h0 = blockIdx.y * 64;
    const int b  = blockIdx.z;
    const float* Xb = X + (size_t)b * Cn * Nn;

    const int ty = tid >> 4;
    const int tx = tid & 15;

    float acc[4][4] = {};

    for (int c0 = 0; c0 < Cn; c0 += 16) {
        {
            int hi = tid >> 2;
            int c4 = (tid & 3) * 4;
            const float4 w4 = *(const float4*)(W + (size_t)(h0 + hi) * Cn + c0 + c4);
            As[c4 + 0][hi] = w4.x; As[c4 + 1][hi] = w4.y;
            As[c4 + 2][hi] = w4.z; As[c4 + 3][hi] = w4.w;
            int kk = tid >> 4;
            int n4 = (tid & 15) * 4;
            *(float4*)&Bs[kk][n4] = *(const float4*)(Xb + (size_t)(c0 + kk) * Nn + n0 + n4);
        }
        __syncthreads();
        #pragma unroll
        for (int kk = 0; kk < 16; kk++) {
            float4 a4 = *(const float4*)&As[kk][ty * 4];
            float4 b4 = *(const float4*)&Bs[kk][tx * 4];
            float a[4] = {a4.x, a4.y, a4.z, a4.w};
            float bb[4] = {b4.x, b4.y, b4.z, b4.w};
            #pragma unroll
            for (int r = 0; r < 4; r++)
                #pragma unroll
                for (int c = 0; c < 4; c++)
                    acc[r][c] = fmaf(a[r], bb[c], acc[r][c]);
        }
        __syncthreads();
    }

    float bv[4];
    #pragma unroll
    for (int r = 0; r < 4; r++) bv[r] = bias[h0 + ty * 4 + r];

    if (MODE == 0) {
        float* ob = out32 + (size_t)b * Hn * Nn;
        #pragma unroll
        for (int r = 0; r < 4; r++) {
            float4 o4;
            o4.x = acc[r][0] + bv[r]; o4.y = acc[r][1] + bv[r];
            o4.z = acc[r][2] + bv[r]; o4.w = acc[r][3] + bv[r];
            *(float4*)(ob + (size_t)(h0 + ty * 4 + r) * Nn + n0 + tx * 4) = o4;
        }
    } else if (MODE == 1 || MODE == 2) {
        #pragma unroll
        for (int c = 0; c < 4; c++) {
            int n = n0 + tx * 4 + c;
            size_t base = ((size_t)(b * Nn + n)) * Hn + h0 + ty * 4;
            float v[4];
            #pragma unroll
            for (int r = 0; r < 4; r++) v[r] = acc[r][c] + bv[r];
            __half h[4];
            #pragma unroll
            for (int r = 0; r < 4; r++) h[r] = __float2half_rn(v[r]);
            uint2 u; u.x = packh2(h[0], h[1]); u.y = packh2(h[2], h[3]);
            *(uint2*)(o16a + base) = u;
            if (MODE == 2) {
                __half l[4];
                #pragma unroll
                for (int r = 0; r < 4; r++)
                    l[r] = __float2half_rn(v[r] - __half2float(h[r]));
                uint2 u2; u2.x = packh2(l[0], l[1]); u2.y = packh2(l[2], l[3]);
                *(uint2*)(o16b + base) = u2;
            }
        }
    } else { // MODE 3
        #pragma unroll
        for (int r = 0; r < 4; r++) {
            size_t base = ((size_t)(b * On + h0 + ty * 4 + r)) * Nn + n0 + tx * 4;
            __half h[4];
            #pragma unroll
            for (int c = 0; c < 4; c++) h[c] = __float2half_rn(acc[r][c] + bv[r]);
            uint2 u; u.x = packh2(h[0], h[1]); u.y = packh2(h[2], h[3]);
            *(uint2*)(o16a + base) = u;
        }
    }
}

// ---------------------------------------------------------------------------
// Grouped conv1d (groups=32, kw=3, SAME) + bias + ReLU: g_v1 -> g_v2
// ---------------------------------------------------------------------------
__global__ __launch_bounds__(256) void gconv_kernel(
    const float* __restrict__ W2, const float* __restrict__ b2)
{
    const int tid = threadIdx.x;
    const int n = blockIdx.x * 256 + tid;
    const int h = blockIdx.y;
    const int b = blockIdx.z;
    const int g = h >> 3;

    float w[24];
    #pragma unroll
    for (int j = 0; j < 24; j++) w[j] = W2[h * 24 + j];

    const float* in = g_v1 + ((size_t)b * Hn + g * 8) * Nn;
    float acc = b2[h];
    #pragma unroll
    for (int i = 0; i < 8; i++) {
        const float* row = in + (size_t)i * Nn;
        float xm1 = (n > 0)      ? row[n - 1] : 0.f;
        float x0  = row[n];
        float xp1 = (n < Nn - 1) ? row[n + 1] : 0.f;
        acc = fmaf(w[i * 3 + 0], xm1, acc);
        acc = fmaf(w[i * 3 + 1], x0,  acc);
        acc = fmaf(w[i * 3 + 2], xp1, acc);
    }
    g_v2[((size_t)b * Hn + h) * Nn + n] = fmaxf(acc, 0.f);
}

// ---------------------------------------------------------------------------
// Fused mma.sync (HMMA) attention.
//   D1[m,n] = sum_h (Qhi+Qlo)[m,h] * K[n,h]     (m-tile 64, n-tile 64, K=256)
//   E = exp(D1 - 4); colsum_m += sum_n E
//   D2t[m,o] += sum_n (Ehi+Elo)[m,n] * V[o,n]
//   out[o,m] = D2t[m,o] / colsum_m
// smem rows padded: Q/K rows 528B (264 half), V/E rows 144B (72 half).
// ---------------------------------------------------------------------------
#define OFF_QHI  0
#define OFF_QLO  33792
#define OFF_K    67584
#define OFF_V    101376
#define OFF_EHI  138240
#define OFF_ELO  147456
#define OFF_CS   156672
#define SMEM_TOTAL 157184

__global__ __launch_bounds__(256, 1)
void attn_kernel(const __half* __restrict__ qhi, const __half* __restrict__ qlo,
                 const __half* __restrict__ kt,  const __half* __restrict__ vh,
                 float* __restrict__ out)
{
    extern __shared__ char smem[];
    const int tid  = threadIdx.x;
    const int lane = tid & 31;
    const int w    = tid >> 5;
    const int m0 = blockIdx.x * 64;
    const int b  = blockIdx.y;
    const uint32_t sb = smem_u32(smem);

    const int g = lane >> 2;
    const int t = lane & 3;

    // GEMM1 partition: warp = 16m x 32n
    const int wm  = (w >> 1) * 16;
    const int wn  = (w & 1) * 32;
    // GEMM2 partition: warp = 32m x 64o
    const int wm2 = (w & 1) * 32;
    const int wo2 = (w >> 1) * 64;

    // ---- prologue: persistent Q hi/lo [64 m][256 h], padded rows ----
    #pragma unroll
    for (int buf = 0; buf < 2; buf++) {
        const __half* src = buf ? qlo : qhi;
        const uint32_t dst = buf ? OFF_QLO : OFF_QHI;
        #pragma unroll
        for (int i = 0; i < 8; i++) {
            int ch = tid + i * 256;
            int r = ch >> 5, c = ch & 31;
            *(float4*)(smem + dst + r * 528 + c * 16) =
                *(const float4*)(src + ((size_t)(b * Nn + m0 + r)) * Hn + c * 8);
        }
    }

    // ldmatrix per-lane address components
    const uint32_t aQoff = (uint32_t)((wm + (lane & 15)) * 528 + (lane >> 4) * 16);
    const uint32_t bKoff = (uint32_t)((wn + ((lane >> 4) << 3) + (lane & 7)) * 528 + ((lane >> 3) & 1) * 16);
    const uint32_t bVoff = (uint32_t)((wo2 + ((lane >> 4) << 3) + (lane & 7)) * 144 + ((lane >> 3) & 1) * 16);
    const uint32_t aE0 = (uint32_t)((wm2 + (lane & 15)) * 144 + (lane >> 4) * 16);
    const uint32_t aE1 = aE0 + 16 * 144;

    float acc2[16][4] = {};        // [mi*8 + j*2 + tile][c]  (mi:2, j:4 o16-grp, tile:2)
    float cs0 = 0.f, cs1 = 0.f;

    for (int it = 0; it < 64; it++) {
        const int n0 = it * 64;
        __syncthreads();           // prev iter's smem reads done

        // ---- load K tile [64 n][256 h] ----
        #pragma unroll
        for (int i = 0; i < 8; i++) {
            int ch = tid + i * 256;
            int r = ch >> 5, c = ch & 31;
            *(float4*)(smem + OFF_K + r * 528 + c * 16) =
                *(const float4*)(kt + ((size_t)(b * Nn + n0 + r)) * Hn + c * 8);
        }
        // ---- load V tile [256 o][64 n] ----
        #pragma unroll
        for (int i = 0; i < 8; i++) {
            int ch = tid + i * 256;
            int r = ch >> 3, c = ch & 7;
            *(float4*)(smem + OFF_V + r * 144 + c * 16) =
                *(const float4*)(vh + ((size_t)(b * On + r)) * Nn + n0 + c * 8);
        }
        __syncthreads();

        // ---- GEMM1: acc1[4 n8-tiles] ----
        float acc1[4][4] = {};
        {
            const uint32_t aQh = sb + OFF_QHI + aQoff;
            const uint32_t aQl = sb + OFF_QLO + aQoff;
            const uint32_t bK  = sb + OFF_K + bKoff;
            #pragma unroll
            for (int ks = 0; ks < 16; ks++) {
                uint32_t ah[4], al[4], p[4], q[4];
                ldm4(ah, aQh + ks * 32);
                ldm4(al, aQl + ks * 32);
                ldm4(p, bK + ks * 32);             // n-tiles 0,1
                ldm4(q, bK + 16 * 528 + ks * 32);  // n-tiles 2,3
                mma16816(acc1[0], ah, p[0], p[1]);
                mma16816(acc1[1], ah, p[2], p[3]);
                mma16816(acc1[2], ah, q[0], q[1]);
                mma16816(acc1[3], ah, q[2], q[3]);
                mma16816(acc1[0], al, p[0], p[1]);
                mma16816(acc1[1], al, p[2], p[3]);
                mma16816(acc1[2], al, q[0], q[1]);
                mma16816(acc1[3], al, q[2], q[3]);
            }
        }

        // ---- epilogue: exp, colsum, E hi/lo -> smem ----
        {
            const uint32_t er0 = (uint32_t)((wm + g) * 144);
            const uint32_t er1 = (uint32_t)((wm + g + 8) * 144);
            #pragma unroll
            for (int nt = 0; nt < 4; nt++) {
                float e00 = __expf(acc1[nt][0] - 4.f);
                float e01 = __expf(acc1[nt][1] - 4.f);
                float e10 = __expf(acc1[nt][2] - 4.f);
                float e11 = __expf(acc1[nt][3] - 4.f);
                cs0 += e00 + e01;
                cs1 += e10 + e11;
                __half h00 = __float2half_rn(e00), h01 = __float2half_rn(e01);
                __half h10 = __float2half_rn(e10), h11 = __float2half_rn(e11);
                __half l00 = __float2half_rn(e00 - __half2float(h00));
                __half l01 = __float2half_rn(e01 - __half2float(h01));
                __half l10 = __float2half_rn(e10 - __half2float(h10));
                __half l11 = __float2half_rn(e11 - __half2float(h11));
                const uint32_t colb = (uint32_t)((wn + nt * 8 + 2 * t) * 2);
                *(uint32_t*)(smem + OFF_EHI + er0 + colb) = packh2(h00, h01);
                *(uint32_t*)(smem + OFF_EHI + er1 + colb) = packh2(h10, h11);
                *(uint32_t*)(smem + OFF_ELO + er0 + colb) = packh2(l00, l01);
                *(uint32_t*)(smem + OFF_ELO + er1 + colb) = packh2(l10, l11);
            }
        }
        __syncthreads();

        // ---- GEMM2: acc2 += (Ehi+Elo) * V^T  (warp: 32m x 64o) ----
        {
            const uint32_t eh0 = sb + OFF_EHI + aE0;
            const uint32_t eh1 = sb + OFF_EHI + aE1;
            const uint32_t el0 = sb + OFF_ELO + aE0;
            const uint32_t el1 = sb + OFF_ELO + aE1;
            const uint32_t bV  = sb + OFF_V + bVoff;
            #pragma unroll
            for (int ks = 0; ks < 4; ks++) {
                uint32_t ah0[4], ah1[4], al0[4], al1[4];
                ldm4(ah0, eh0 + ks * 32);
                ldm4(ah1, eh1 + ks * 32);
                ldm4(al0, el0 + ks * 32);
                ldm4(al1, el1 + ks * 32);
                #pragma unroll
                for (int j = 0; j < 4; j++) {   // o16 groups
                    uint32_t bb[4];
                    ldm4(bb, bV + j * (16 * 144) + ks * 32);
                    mma16816(acc2[0 + j * 2 + 0], ah0, bb[0], bb[1]);
                    mma16816(acc2[0 + j * 2 + 1], ah0, bb[2], bb[3]);
                    mma16816(acc2[8 + j * 2 + 0], ah1, bb[0], bb[1]);
                    mma16816(acc2[8 + j * 2 + 1], ah1, bb[2], bb[3]);
                    mma16816(acc2[0 + j * 2 + 0], al0, bb[0], bb[1]);
                    mma16816(acc2[0 + j * 2 + 1], al0, bb[2], bb[3]);
                    mma16816(acc2[8 + j * 2 + 0], al1, bb[0], bb[1]);
                    mma16816(acc2[8 + j * 2 + 1], al1, bb[2], bb[3]);
                }
            }
        }
    }

    // ---- colsum reduce (t-lanes, then warp pairs via smem) ----
    cs0 += __shfl_xor_sync(0xFFFFFFFFu, cs0, 1);
    cs0 += __shfl_xor_sync(0xFFFFFFFFu, cs0, 2);
    cs1 += __shfl_xor_sync(0xFFFFFFFFu, cs1, 1);
    cs1 += __shfl_xor_sync(0xFFFFFFFFu, cs1, 2);
    float* CS = (float*)(smem + OFF_CS);   // [2][64]
    if (t == 0) {
        CS[(w & 1) * 64 + wm + g]     = cs0;
        CS[(w & 1) * 64 + wm + g + 8] = cs1;
    }
    __syncthreads();

    float inv[2][2];
    #pragma unroll
    for (int mi = 0; mi < 2; mi++) {
        int r0 = wm2 + mi * 16 + g;
        inv[mi][0] = 1.f / (CS[r0] + CS[64 + r0]);
        inv[mi][1] = 1.f / (CS[r0 + 8] + CS[64 + r0 + 8]);
    }

    // ---- output: out[b][o][m0+m] = acc2 * inv ----
    #pragma unroll
    for (int mi = 0; mi < 2; mi++) {
        const int mrow0 = wm2 + mi * 16 + g;
        #pragma unroll
        for (int jt = 0; jt < 8; jt++) {   // o8 tiles
            const int o = wo2 + jt * 8 + 2 * t;
            const float* a = acc2[mi * 8 + jt];
            float* p0 = out + ((size_t)(b * On + o)) * Nn + m0;
            float* p1 = p0 + Nn;
            p0[mrow0]     = a[0] * inv[mi][0];
            p1[mrow0]     = a[1] * inv[mi][0];
            p0[mrow0 + 8] = a[2] * inv[mi][1];
            p1[mrow0 + 8] = a[3] * inv[mi][1];
        }
    }
}

// ---------------------------------------------------------------------------
extern "C" void kernel_launch(void* const* d_in, const int* in_sizes, int n_in,
                              void* d_out, int out_size)
{
    const float* x  = (const float*)d_in[0];
    const float* Wk = (const float*)d_in[1];
    const float* bk = (const float*)d_in[2];
    const float* Wq = (const float*)d_in[3];
    const float* bq = (const float*)d_in[4];
    const float* W1 = (const float*)d_in[5];
    const float* b1 = (const float*)d_in[6];
    const float* W2 = (const float*)d_in[7];
    const float* b2 = (const float*)d_in[8];
    const float* W3 = (const float*)d_in[9];
    const float* b3 = (const float*)d_in[10];
    float* out = (float*)d_out;

    float *gv1, *gv2;
    __half *gkt, *gqhi, *gqlo, *gvh;
    cudaGetSymbolAddress((void**)&gv1,  g_v1);
    cudaGetSymbolAddress((void**)&gv2,  g_v2);
    cudaGetSymbolAddress((void**)&gkt,  g_kt);
    cudaGetSymbolAddress((void**)&gqhi, g_qhi);
    cudaGetSymbolAddress((void**)&gqlo, g_qlo);
    cudaGetSymbolAddress((void**)&gvh,  g_vh);

    cudaFuncSetAttribute(attn_kernel, cudaFuncAttributeMaxDynamicSharedMemorySize, SMEM_TOTAL);

    dim3 pgrid(Nn / 64, Hn / 64, Bn);
    proj_kernel<1><<<pgrid, 256>>>(Wk, bk, x, nullptr, gkt, nullptr);
    proj_kernel<2><<<pgrid, 256>>>(Wq, bq, x, nullptr, gqhi, gqlo);
    proj_kernel<0><<<pgrid, 256>>>(W1, b1, x, gv1, nullptr, nullptr);
    gconv_kernel<<<dim3(Nn / 256, Hn, Bn), 256>>>(W2, b2);
    proj_kernel<3><<<pgrid, 256>>>(W3, b3, gv2, nullptr, gvh, nullptr);
    attn_kernel<<<dim3(Nn / 64, Bn), 256, SMEM_TOTAL>>>(gqhi, gqlo, gkt, gvh, out);
}

// round 7
// speedup vs baseline: 5.9804x; 1.9045x over previous
#include <cuda_runtime.h>
#include <cuda_fp16.h>
#include <cstdint>

#define Bn 4
#define Cn 256
#define Hn 256
#define On 256
#define Nn 4096

// ---------------- scratch (device globals) ----------------------------------
__device__ __half g_x16[(size_t)Bn*Cn*Nn];   // x fp16 [b][c][n]
__device__ __half g_whi[4 * Cn * Hn];        // W hi fp16 (Wk,Wq,W1,W3)
__device__ __half g_wlo[4 * Cn * Hn];        // W lo fp16
__device__ __half g_kt [(size_t)Bn*Nn*Hn];   // k^T [b][n][h]
__device__ __half g_qt [(size_t)Bn*Nn*Hn];   // q^T [b][n][h]
__device__ __half g_v1h[(size_t)Bn*Hn*Nn];   // v1 [b][h][n]
__device__ __half g_v2h[(size_t)Bn*Hn*Nn];   // v2 [b][h][n]
__device__ __half g_vh [(size_t)Bn*On*Nn];   // v  [b][o][n]

// ---------------- helpers ----------------------------------------------------
__device__ __forceinline__ uint32_t smem_u32(const void* p) {
    uint32_t a;
    asm("{ .reg .u64 t; cvta.to.shared.u64 t, %1; cvt.u32.u64 %0, t; }" : "=r"(a) : "l"(p));
    return a;
}
__device__ __forceinline__ uint32_t packh2(__half a, __half b) {
    __half2 h = __halves2half2(a, b);
    return *reinterpret_cast<const uint32_t*>(&h);
}
__device__ __forceinline__ void ldm4(uint32_t* r, uint32_t addr) {
    asm volatile("ldmatrix.sync.aligned.m8n8.x4.shared.b16 {%0,%1,%2,%3}, [%4];"
                 : "=r"(r[0]), "=r"(r[1]), "=r"(r[2]), "=r"(r[3]) : "r"(addr));
}
__device__ __forceinline__ void ldm4t(uint32_t* r, uint32_t addr) {
    asm volatile("ldmatrix.sync.aligned.m8n8.x4.trans.shared.b16 {%0,%1,%2,%3}, [%4];"
                 : "=r"(r[0]), "=r"(r[1]), "=r"(r[2]), "=r"(r[3]) : "r"(addr));
}
__device__ __forceinline__ void mma16816(float* c, const uint32_t* a, uint32_t b0, uint32_t b1) {
    asm volatile("mma.sync.aligned.m16n8k16.row.col.f32.f16.f16.f32 "
                 "{%0,%1,%2,%3}, {%4,%5,%6,%7}, {%8,%9}, {%0,%1,%2,%3};"
                 : "+f"(c[0]), "+f"(c[1]), "+f"(c[2]), "+f"(c[3])
                 : "r"(a[0]), "r"(a[1]), "r"(a[2]), "r"(a[3]), "r"(b0), "r"(b1));
}
#define CP16(dst, src) \
    asm volatile("cp.async.cg.shared.global [%0], [%1], 16;" :: "r"(dst), "l"(src))
#define CP_COMMIT() asm volatile("cp.async.commit_group;" ::: "memory")
#define CP_WAIT0()  asm volatile("cp.async.wait_group 0;" ::: "memory")
#define CP_WAIT1()  asm volatile("cp.async.wait_group 1;" ::: "memory")

// ---------------------------------------------------------------------------
// Prep: x fp32 -> fp16 ; weights fp32 -> hi/lo fp16
// ---------------------------------------------------------------------------
__global__ __launch_bounds__(256) void x16_kernel(const float* __restrict__ x) {
    size_t q = (size_t)blockIdx.x * 256 + threadIdx.x;   // quad index
    float4 v = *(const float4*)(x + q * 4);
    uint2 u;
    u.x = packh2(__float2half_rn(v.x), __float2half_rn(v.y));
    u.y = packh2(__float2half_rn(v.z), __float2half_rn(v.w));
    *(uint2*)(g_x16 + q * 4) = u;
}

__global__ __launch_bounds__(256) void wprep_kernel(
    const float* __restrict__ W0, const float* __restrict__ W1,
    const float* __restrict__ W2, const float* __restrict__ W3) {
    int e = blockIdx.x * 256 + threadIdx.x;
    int m = blockIdx.y;
    const float* src = (m == 0) ? W0 : (m == 1) ? W1 : (m == 2) ? W2 : W3;
    float f = src[e];
    __half hi = __float2half_rn(f);
    __half lo = __float2half_rn(f - __half2float(hi));
    g_whi[m * 65536 + e] = hi;
    g_wlo[m * 65536 + e] = lo;
}

// ---------------------------------------------------------------------------
// HMMA projection: out[h,n] = sum_c (Whi+Wlo)[h,c] * X16[c,n] + bias[h]
// CTA tile 128h x 128n, K chunks of 32, cp.async double-buffered.
// smem per buf: Whi[128 rows x 80B], Wlo[128 x 80B], Xs[32 rows x 272B]
// ---------------------------------------------------------------------------
#define PJ_WL    10240
#define PJ_X     20480
#define PJ_BUF   29184
#define PJ_SMEM  58368

__device__ __forceinline__ void proj_issue(
    uint32_t sb, int buf, const __half* whi, const __half* wlo,
    const __half* X, int h0, int n0, int c0, int tid)
{
    uint32_t base = sb + buf * PJ_BUF;
    #pragma unroll
    for (int i = 0; i < 6; i++) {
        int idx = tid + i * 256;
        if (idx < 512) {
            int r = idx >> 4, c = idx & 15;
            CP16(base + PJ_X + r * 272 + c * 16, X + (size_t)(c0 + r) * Nn + n0 + c * 8);
        } else {
            int i2 = idx - 512;
            int part = i2 >> 9, r = (i2 >> 2) & 127, c = i2 & 3;
            const __half* w = part ? wlo : whi;
            CP16(base + part * PJ_WL + r * 80 + c * 16, w + (size_t)(h0 + r) * Cn + c0 + c * 8);
        }
    }
}

// MODE 0 ("N"): out [b][h][n].  MODE 1 ("T"): out [b][n][h].
template <int MODE>
__global__ __launch_bounds__(256, 2) void proj16_kernel(
    const __half* __restrict__ whi, const __half* __restrict__ wlo,
    const float* __restrict__ bias, const __half* __restrict__ X,
    __half* __restrict__ out)
{
    extern __shared__ char smem[];
    const uint32_t sb = smem_u32(smem);
    const int tid = threadIdx.x;
    const int l = tid & 31;
    const int w = tid >> 5;
    const int g = l >> 2;
    const int t = l & 3;
    const int n0 = blockIdx.x * 128;
    const int h0 = blockIdx.y * 128;
    const int b  = blockIdx.z;
    const __half* Xb = X + (size_t)b * Cn * Nn;

    float acc[16][4] = {};   // N: [mi2*8 + j8]  T: [mi4*4 + j4]

    proj_issue(sb, 0, whi, wlo, Xb, h0, n0, 0, tid);
    CP_COMMIT();

    if (MODE == 0) {
        const int wh = (w & 3) * 32;
        const int wn = (w >> 2) * 64;
        const uint32_t aW = (uint32_t)((wh + (l & 15)) * 80 + (l >> 4) * 16);
        const uint32_t bX = (uint32_t)((((l >> 3) & 1) * 8 + (l & 7)) * 272 + (wn + (l >> 4) * 8) * 2);

        for (int ck = 0; ck < 8; ck++) {
            if (ck < 7) { proj_issue(sb, (ck + 1) & 1, whi, wlo, Xb, h0, n0, (ck + 1) * 32, tid);
                          CP_COMMIT(); CP_WAIT1(); }
            else CP_WAIT0();
            __syncthreads();
            const uint32_t bb = sb + (ck & 1) * PJ_BUF;
            #pragma unroll
            for (int ks = 0; ks < 2; ks++) {
                uint32_t q[4][4];
                #pragma unroll
                for (int jj = 0; jj < 4; jj++)
                    ldm4t(q[jj], bb + PJ_X + bX + ks * 4352 + jj * 32);
                #pragma unroll
                for (int part = 0; part < 2; part++) {
                    uint32_t a[2][4];
                    ldm4(a[0], bb + part * PJ_WL + aW + ks * 32);
                    ldm4(a[1], bb + part * PJ_WL + aW + 16 * 80 + ks * 32);
                    #pragma unroll
                    for (int mi = 0; mi < 2; mi++)
                        #pragma unroll
                        for (int jj = 0; jj < 4; jj++) {
                            mma16816(acc[mi * 8 + jj * 2],     a[mi], q[jj][0], q[jj][1]);
                            mma16816(acc[mi * 8 + jj * 2 + 1], a[mi], q[jj][2], q[jj][3]);
                        }
                }
            }
            __syncthreads();
        }
        // epilogue: out[b][h][n]
        #pragma unroll
        for (int mi = 0; mi < 2; mi++) {
            float bv0 = bias[h0 + wh + mi * 16 + g];
            float bv1 = bias[h0 + wh + mi * 16 + g + 8];
            #pragma unroll
            for (int j = 0; j < 8; j++) {
                int h = h0 + wh + mi * 16 + g;
                int n = n0 + wn + j * 8 + 2 * t;
                float* a = acc[mi * 8 + j];
                *(uint32_t*)(out + ((size_t)(b * Hn + h)) * Nn + n) =
                    packh2(__float2half_rn(a[0] + bv0), __float2half_rn(a[1] + bv0));
                *(uint32_t*)(out + ((size_t)(b * Hn + h + 8)) * Nn + n) =
                    packh2(__float2half_rn(a[2] + bv1), __float2half_rn(a[3] + bv1));
            }
        }
    } else {
        const int wn = (w & 1) * 64;
        const int wh = (w >> 1) * 32;
        const uint32_t aX = (uint32_t)(((l >> 4) * 8 + (l & 7)) * 272 + (wn + ((l >> 3) & 1) * 8) * 2);
        const uint32_t bW = (uint32_t)((wh + ((l >> 4) << 3) + (l & 7)) * 80 + ((l >> 3) & 1) * 16);

        for (int ck = 0; ck < 8; ck++) {
            if (ck < 7) { proj_issue(sb, (ck + 1) & 1, whi, wlo, Xb, h0, n0, (ck + 1) * 32, tid);
                          CP_COMMIT(); CP_WAIT1(); }
            else CP_WAIT0();
            __syncthreads();
            const uint32_t bb = sb + (ck & 1) * PJ_BUF;
            #pragma unroll
            for (int ks = 0; ks < 2; ks++) {
                uint32_t a[4][4];
                #pragma unroll
                for (int mi = 0; mi < 4; mi++)
                    ldm4t(a[mi], bb + PJ_X + aX + ks * 4352 + mi * 32);
                #pragma unroll
                for (int part = 0; part < 2; part++)
                    #pragma unroll
                    for (int jj = 0; jj < 2; jj++) {
                        uint32_t qq[4];
                        ldm4(qq, bb + part * PJ_WL + bW + jj * 1280 + ks * 32);
                        #pragma unroll
                        for (int mi = 0; mi < 4; mi++) {
                            mma16816(acc[mi * 4 + jj * 2],     a[mi], qq[0], qq[1]);
                            mma16816(acc[mi * 4 + jj * 2 + 1], a[mi], qq[2], qq[3]);
                        }
                    }
            }
            __syncthreads();
        }
        // epilogue: out[b][n][h]
        float bvj[4][2];
        #pragma unroll
        for (int j = 0; j < 4; j++) {
            bvj[j][0] = bias[h0 + wh + j * 8 + 2 * t];
            bvj[j][1] = bias[h0 + wh + j * 8 + 2 * t + 1];
        }
        #pragma unroll
        for (int mi = 0; mi < 4; mi++) {
            int nr = n0 + wn + mi * 16 + g;
            #pragma unroll
            for (int j = 0; j < 4; j++) {
                float* a = acc[mi * 4 + j];
                int hc = h0 + wh + j * 8 + 2 * t;
                *(uint32_t*)(out + ((size_t)(b * Nn + nr)) * Hn + hc) =
                    packh2(__float2half_rn(a[0] + bvj[j][0]), __float2half_rn(a[1] + bvj[j][1]));
                *(uint32_t*)(out + ((size_t)(b * Nn + nr + 8)) * Hn + hc) =
                    packh2(__float2half_rn(a[2] + bvj[j][0]), __float2half_rn(a[3] + bvj[j][1]));
            }
        }
    }
}

// ---------------------------------------------------------------------------
// Grouped conv1d fp16 (groups=32, kw=3, SAME) + bias + ReLU: g_v1h -> g_v2h
// Block: (512-n chunk, group, batch). 8 input rows staged in smem.
// ---------------------------------------------------------------------------
__global__ __launch_bounds__(256) void gconv16_kernel(
    const float* __restrict__ W2, const float* __restrict__ b2)
{
    __shared__ __half xs[8][536];
    __shared__ float ws[192];
    __shared__ float bs[8];

    const int tid = threadIdx.x;
    const int n0 = blockIdx.x * 512;
    const int gr = blockIdx.y;
    const int b  = blockIdx.z;

    if (tid < 192) ws[tid] = W2[gr * 192 + tid];
    if (tid < 8)   bs[tid] = b2[gr * 8 + tid];

    const __half* in = g_v1h + ((size_t)b * Hn + gr * 8) * Nn;
    for (int idx = tid; idx < 8 * 66; idx += 256) {
        int r = idx / 66, c = idx % 66;
        int gn = n0 - 8 + c * 8;
        if (gn >= 0 && gn + 8 <= Nn) {
            *(uint4*)&xs[r][c * 8] = *(const uint4*)(in + (size_t)r * Nn + gn);
        } else {
            #pragma unroll
            for (int j = 0; j < 8; j++) {
                int n = gn + j;
                xs[r][c * 8 + j] = (n >= 0 && n < Nn) ? in[(size_t)r * Nn + n] : __half(0.f);
            }
        }
    }
    __syncthreads();

    __half* ob = g_v2h + ((size_t)b * Hn + gr * 8) * Nn + n0;
    #pragma unroll
    for (int k = 0; k < 2; k++) {
        int n = tid + k * 256;
        float xm[8], x0[8], xp[8];
        #pragma unroll
        for (int i = 0; i < 8; i++) {
            xm[i] = __half2float(xs[i][8 + n - 1]);
            x0[i] = __half2float(xs[i][8 + n]);
            xp[i] = __half2float(xs[i][8 + n + 1]);
        }
        #pragma unroll
        for (int h = 0; h < 8; h++) {
            float acc = bs[h];
            #pragma unroll
            for (int i = 0; i < 8; i++) {
                acc = fmaf(ws[h * 24 + i * 3 + 0], xm[i], acc);
                acc = fmaf(ws[h * 24 + i * 3 + 1], x0[i], acc);
                acc = fmaf(ws[h * 24 + i * 3 + 2], xp[i], acc);
            }
            ob[(size_t)h * Nn + n] = __float2half_rn(fmaxf(acc, 0.f));
        }
    }
}

// ---------------------------------------------------------------------------
// Fused HMMA attention (single fp16 operands, cp.async double-buffered K/V).
//   D1[m,n] = sum_h Q[m,h] K[n,h];  E = exp(D1-4);  colsum += E
//   D2t[m,o] += sum_n E[m,n] V[o,n];  out[o,m] = D2t/colsum
// ---------------------------------------------------------------------------
#define OFF_Q   0
#define OFF_K   33792
#define OFF_V   101376
#define OFF_E   175104
#define OFF_CS  184320
#define AT_SMEM 184832
#define KBUF    33792
#define VBUF    36864

__device__ __forceinline__ void attn_issue(
    uint32_t sb, int buf, const __half* kb, const __half* vb, int n0, int tid)
{
    uint32_t kd = sb + OFF_K + buf * KBUF;
    uint32_t vd = sb + OFF_V + buf * VBUF;
    #pragma unroll
    for (int i = 0; i < 8; i++) {
        int ch = tid + i * 256;
        int r = ch >> 5, c = ch & 31;
        CP16(kd + r * 528 + c * 16, kb + (size_t)(n0 + r) * Hn + c * 8);
    }
    #pragma unroll
    for (int i = 0; i < 8; i++) {
        int ch = tid + i * 256;
        int r = ch >> 3, c = ch & 7;
        CP16(vd + r * 144 + c * 16, vb + (size_t)r * Nn + n0 + c * 8);
    }
}

__global__ __launch_bounds__(256, 1)
void attn_kernel(const __half* __restrict__ qt, const __half* __restrict__ kt,
                 const __half* __restrict__ vh, float* __restrict__ out)
{
    extern __shared__ char smem[];
    const int tid  = threadIdx.x;
    const int l    = tid & 31;
    const int w    = tid >> 5;
    const int m0 = blockIdx.x * 64;
    const int b  = blockIdx.y;
    const uint32_t sb = smem_u32(smem);
    const int g = l >> 2;
    const int t = l & 3;

    const int wm  = (w >> 1) * 16;   // GEMM1: warp 16m x 32n
    const int wn  = (w & 1) * 32;
    const int wm2 = (w & 1) * 32;    // GEMM2: warp 32m x 64o
    const int wo2 = (w >> 1) * 64;

    const __half* kb = kt + (size_t)b * Nn * Hn;
    const __half* vb = vh + (size_t)b * On * Nn;

    // prologue: persistent Q [64 m][256 h], rows 528B; issue tile 0
    #pragma unroll
    for (int i = 0; i < 8; i++) {
        int ch = tid + i * 256;
        int r = ch >> 5, c = ch & 31;
        *(float4*)(smem + OFF_Q + r * 528 + c * 16) =
            *(const float4*)(qt + ((size_t)(b * Nn + m0 + r)) * Hn + c * 8);
    }
    attn_issue(sb, 0, kb, vb, 0, tid);
    CP_COMMIT();

    const uint32_t aQ  = sb + OFF_Q + (uint32_t)((wm + (l & 15)) * 528 + (l >> 4) * 16);
    const uint32_t bK  = (uint32_t)((wn + ((l >> 4) << 3) + (l & 7)) * 528 + ((l >> 3) & 1) * 16);
    const uint32_t bV  = (uint32_t)((wo2 + ((l >> 4) << 3) + (l & 7)) * 144 + ((l >> 3) & 1) * 16);
    const uint32_t aE0 = sb + OFF_E + (uint32_t)((wm2 + (l & 15)) * 144 + (l >> 4) * 16);
    const uint32_t aE1 = aE0 + 16 * 144;

    float acc2[16][4] = {};
    float cs0 = 0.f, cs1 = 0.f;

    for (int it = 0; it < 64; it++) {
        if (it < 63) {
            attn_issue(sb, (it + 1) & 1, kb, vb, (it + 1) * 64, tid);
            CP_COMMIT(); CP_WAIT1();
        } else CP_WAIT0();
        __syncthreads();

        const uint32_t kbuf = sb + OFF_K + (it & 1) * KBUF;
        const uint32_t vbuf = sb + OFF_V + (it & 1) * VBUF;

        // ---- GEMM1 ----
        float acc1[4][4] = {};
        #pragma unroll
        for (int ks = 0; ks < 16; ks++) {
            uint32_t ah[4], p[4], q[4];
            ldm4(ah, aQ + ks * 32);
            ldm4(p, kbuf + bK + ks * 32);
            ldm4(q, kbuf + bK + 16 * 528 + ks * 32);
            mma16816(acc1[0], ah, p[0], p[1]);
            mma16816(acc1[1], ah, p[2], p[3]);
            mma16816(acc1[2], ah, q[0], q[1]);
            mma16816(acc1[3], ah, q[2], q[3]);
        }

        // ---- epilogue: exp, colsum, E -> smem ----
        {
            const uint32_t er0 = (uint32_t)((wm + g) * 144);
            const uint32_t er1 = (uint32_t)((wm + g + 8) * 144);
            #pragma unroll
            for (int nt = 0; nt < 4; nt++) {
                float e00 = __expf(acc1[nt][0] - 4.f);
                float e01 = __expf(acc1[nt][1] - 4.f);
                float e10 = __expf(acc1[nt][2] - 4.f);
                float e11 = __expf(acc1[nt][3] - 4.f);
                cs0 += e00 + e01;
                cs1 += e10 + e11;
                const uint32_t colb = (uint32_t)((wn + nt * 8 + 2 * t) * 2);
                *(uint32_t*)(smem + OFF_E + er0 + colb) =
                    packh2(__float2half_rn(e00), __float2half_rn(e01));
                *(uint32_t*)(smem + OFF_E + er1 + colb) =
                    packh2(__float2half_rn(e10), __float2half_rn(e11));
            }
        }
        __syncthreads();

        // ---- GEMM2 ----
        #pragma unroll
        for (int ks = 0; ks < 4; ks++) {
            uint32_t ah0[4], ah1[4];
            ldm4(ah0, aE0 + ks * 32);
            ldm4(ah1, aE1 + ks * 32);
            #pragma unroll
            for (int j = 0; j < 4; j++) {
                uint32_t bb[4];
                ldm4(bb, vbuf + bV + j * (16 * 144) + ks * 32);
                mma16816(acc2[0 + j * 2 + 0], ah0, bb[0], bb[1]);
                mma16816(acc2[0 + j * 2 + 1], ah0, bb[2], bb[3]);
                mma16816(acc2[8 + j * 2 + 0], ah1, bb[0], bb[1]);
                mma16816(acc2[8 + j * 2 + 1], ah1, bb[2], bb[3]);
            }
        }
        __syncthreads();   // before next cp.async overwrites buffers
    }

    // ---- colsum reduce ----
    cs0 += __shfl_xor_sync(0xFFFFFFFFu, cs0, 1);
    cs0 += __shfl_xor_sync(0xFFFFFFFFu, cs0, 2);
    cs1 += __shfl_xor_sync(0xFFFFFFFFu, cs1, 1);
    cs1 += __shfl_xor_sync(0xFFFFFFFFu, cs1, 2);
    float* CS = (float*)(smem + OFF_CS);   // [2][64]
    if (t == 0) {
        CS[(w & 1) * 64 + wm + g]     = cs0;
        CS[(w & 1) * 64 + wm + g + 8] = cs1;
    }
    __syncthreads();

    float inv[2][2];
    #pragma unroll
    for (int mi = 0; mi < 2; mi++) {
        int r0 = wm2 + mi * 16 + g;
        inv[mi][0] = 1.f / (CS[r0] + CS[64 + r0]);
        inv[mi][1] = 1.f / (CS[r0 + 8] + CS[64 + r0 + 8]);
    }

    #pragma unroll
    for (int mi = 0; mi < 2; mi++) {
        const int mrow0 = wm2 + mi * 16 + g;
        #pragma unroll
        for (int jt = 0; jt < 8; jt++) {
            const int o = wo2 + jt * 8 + 2 * t;
            const float* a = acc2[mi * 8 + jt];
            float* p0 = out + ((size_t)(b * On + o)) * Nn + m0;
            float* p1 = p0 + Nn;
            p0[mrow0]     = a[0] * inv[mi][0];
            p1[mrow0]     = a[1] * inv[mi][0];
            p0[mrow0 + 8] = a[2] * inv[mi][1];
            p1[mrow0 + 8] = a[3] * inv[mi][1];
        }
    }
}

// ---------------------------------------------------------------------------
extern "C" void kernel_launch(void* const* d_in, const int* in_sizes, int n_in,
                              void* d_out, int out_size)
{
    const float* x  = (const float*)d_in[0];
    const float* Wk = (const float*)d_in[1];
    const float* bk = (const float*)d_in[2];
    const float* Wq = (const float*)d_in[3];
    const float* bq = (const float*)d_in[4];
    const float* W1 = (const float*)d_in[5];
    const float* b1 = (const float*)d_in[6];
    const float* W2 = (const float*)d_in[7];
    const float* b2 = (const float*)d_in[8];
    const float* W3 = (const float*)d_in[9];
    const float* b3 = (const float*)d_in[10];
    float* out = (float*)d_out;

    __half *x16, *whi, *wlo, *ktp, *qtp, *v1h, *v2h, *vhp;
    cudaGetSymbolAddress((void**)&x16, g_x16);
    cudaGetSymbolAddress((void**)&whi, g_whi);
    cudaGetSymbolAddress((void**)&wlo, g_wlo);
    cudaGetSymbolAddress((void**)&ktp, g_kt);
    cudaGetSymbolAddress((void**)&qtp, g_qt);
    cudaGetSymbolAddress((void**)&v1h, g_v1h);
    cudaGetSymbolAddress((void**)&v2h, g_v2h);
    cudaGetSymbolAddress((void**)&vhp, g_vh);

    cudaFuncSetAttribute(proj16_kernel<0>, cudaFuncAttributeMaxDynamicSharedMemorySize, PJ_SMEM);
    cudaFuncSetAttribute(proj16_kernel<1>, cudaFuncAttributeMaxDynamicSharedMemorySize, PJ_SMEM);
    cudaFuncSetAttribute(attn_kernel, cudaFuncAttributeMaxDynamicSharedMemorySize, AT_SMEM);

    x16_kernel<<<4096, 256>>>(x);
    wprep_kernel<<<dim3(256, 4), 256>>>(Wk, Wq, W1, W3);

    dim3 pg(Nn / 128, Hn / 128, Bn);
    proj16_kernel<1><<<pg, 256, PJ_SMEM>>>(whi + 0 * 65536, wlo + 0 * 65536, bk, x16, ktp);
    proj16_kernel<1><<<pg, 256, PJ_SMEM>>>(whi + 1 * 65536, wlo + 1 * 65536, bq, x16, qtp);
    proj16_kernel<0><<<pg, 256, PJ_SMEM>>>(whi + 2 * 65536, wlo + 2 * 65536, b1, x16, v1h);
    gconv16_kernel<<<dim3(Nn / 512, 32, Bn), 256>>>(W2, b2);
    proj16_kernel<0><<<pg, 256, PJ_SMEM>>>(whi + 3 * 65536, wlo + 3 * 65536, b3, v2h, vhp);
    attn_kernel<<<dim3(Nn / 64, Bn), 256, AT_SMEM>>>(qtp, ktp, vhp, out);
}

// round 8
// speedup vs baseline: 6.5832x; 1.1008x over previous
#include <cuda_runtime.h>
#include <cuda_fp16.h>
#include <cstdint>

#define Bn 4
#define Cn 256
#define Hn 256
#define On 256
#define Nn 4096

// ---------------- scratch (device globals) ----------------------------------
__device__ __half g_x16[(size_t)Bn*Cn*Nn];   // x fp16 [b][c][n]
__device__ __half g_whi[4 * Cn * Hn];        // W hi fp16 (Wk,Wq,W1,W3)
__device__ __half g_wlo[4 * Cn * Hn];        // W lo fp16
__device__ __half g_kt [(size_t)Bn*Nn*Hn];   // k^T [b][n][h]
__device__ __half g_qt [(size_t)Bn*Nn*Hn];   // q^T [b][n][h]
__device__ __half g_v1h[(size_t)Bn*Hn*Nn];   // v1 [b][h][n]
__device__ __half g_v2h[(size_t)Bn*Hn*Nn];   // v2 [b][h][n]
__device__ __half g_vh [(size_t)Bn*On*Nn];   // v  [b][o][n]

// ---------------- helpers ----------------------------------------------------
__device__ __forceinline__ uint32_t smem_u32(const void* p) {
    uint32_t a;
    asm("{ .reg .u64 t; cvta.to.shared.u64 t, %1; cvt.u32.u64 %0, t; }" : "=r"(a) : "l"(p));
    return a;
}
__device__ __forceinline__ uint32_t packh2(__half a, __half b) {
    __half2 h = __halves2half2(a, b);
    return *reinterpret_cast<const uint32_t*>(&h);
}
__device__ __forceinline__ void ldm4(uint32_t* r, uint32_t addr) {
    asm volatile("ldmatrix.sync.aligned.m8n8.x4.shared.b16 {%0,%1,%2,%3}, [%4];"
                 : "=r"(r[0]), "=r"(r[1]), "=r"(r[2]), "=r"(r[3]) : "r"(addr));
}
__device__ __forceinline__ void ldm4t(uint32_t* r, uint32_t addr) {
    asm volatile("ldmatrix.sync.aligned.m8n8.x4.trans.shared.b16 {%0,%1,%2,%3}, [%4];"
                 : "=r"(r[0]), "=r"(r[1]), "=r"(r[2]), "=r"(r[3]) : "r"(addr));
}
__device__ __forceinline__ void mma16816(float* c, const uint32_t* a, uint32_t b0, uint32_t b1) {
    asm volatile("mma.sync.aligned.m16n8k16.row.col.f32.f16.f16.f32 "
                 "{%0,%1,%2,%3}, {%4,%5,%6,%7}, {%8,%9}, {%0,%1,%2,%3};"
                 : "+f"(c[0]), "+f"(c[1]), "+f"(c[2]), "+f"(c[3])
                 : "r"(a[0]), "r"(a[1]), "r"(a[2]), "r"(a[3]), "r"(b0), "r"(b1));
}
#define CP16(dst, src) \
    asm volatile("cp.async.cg.shared.global [%0], [%1], 16;" :: "r"(dst), "l"(src))
#define CP_COMMIT() asm volatile("cp.async.commit_group;" ::: "memory")
#define CP_WAIT0()  asm volatile("cp.async.wait_group 0;" ::: "memory")
#define CP_WAIT1()  asm volatile("cp.async.wait_group 1;" ::: "memory")

// ---------------------------------------------------------------------------
// Prep: x fp32 -> fp16 ; weights fp32 -> hi/lo fp16
// ---------------------------------------------------------------------------
__global__ __launch_bounds__(256) void x16_kernel(const float* __restrict__ x) {
    size_t q = (size_t)blockIdx.x * 256 + threadIdx.x;   // quad index
    float4 v = *(const float4*)(x + q * 4);
    uint2 u;
    u.x = packh2(__float2half_rn(v.x), __float2half_rn(v.y));
    u.y = packh2(__float2half_rn(v.z), __float2half_rn(v.w));
    *(uint2*)(g_x16 + q * 4) = u;
}

__global__ __launch_bounds__(256) void wprep_kernel(
    const float* __restrict__ W0, const float* __restrict__ W1,
    const float* __restrict__ W2, const float* __restrict__ W3) {
    int e = blockIdx.x * 256 + threadIdx.x;
    int m = blockIdx.y;
    const float* src = (m == 0) ? W0 : (m == 1) ? W1 : (m == 2) ? W2 : W3;
    float f = src[e];
    __half hi = __float2half_rn(f);
    __half lo = __float2half_rn(f - __half2float(hi));
    g_whi[m * 65536 + e] = hi;
    g_wlo[m * 65536 + e] = lo;
}

// ---------------------------------------------------------------------------
// HMMA projection: out[h,n] = sum_c (Whi+Wlo)[h,c] * X16[c,n] + bias[h]
// CTA tile 128h x 128n, K chunks of 32, cp.async double-buffered.
// ---------------------------------------------------------------------------
#define PJ_WL    10240
#define PJ_X     20480
#define PJ_BUF   29184
#define PJ_SMEM  58368

__device__ __forceinline__ void proj_issue(
    uint32_t sb, int buf, const __half* whi, const __half* wlo,
    const __half* X, int h0, int n0, int c0, int tid)
{
    uint32_t base = sb + buf * PJ_BUF;
    #pragma unroll
    for (int i = 0; i < 6; i++) {
        int idx = tid + i * 256;
        if (idx < 512) {
            int r = idx >> 4, c = idx & 15;
            CP16(base + PJ_X + r * 272 + c * 16, X + (size_t)(c0 + r) * Nn + n0 + c * 8);
        } else {
            int i2 = idx - 512;
            int part = i2 >> 9, r = (i2 >> 2) & 127, c = i2 & 3;
            const __half* w = part ? wlo : whi;
            CP16(base + part * PJ_WL + r * 80 + c * 16, w + (size_t)(h0 + r) * Cn + c0 + c * 8);
        }
    }
}

// MODE 0 ("N"): out [b][h][n].  MODE 1 ("T"): out [b][n][h].
template <int MODE>
__global__ __launch_bounds__(256, 2) void proj16_kernel(
    const __half* __restrict__ whi, const __half* __restrict__ wlo,
    const float* __restrict__ bias, const __half* __restrict__ X,
    __half* __restrict__ out)
{
    extern __shared__ char smem[];
    const uint32_t sb = smem_u32(smem);
    const int tid = threadIdx.x;
    const int l = tid & 31;
    const int w = tid >> 5;
    const int g = l >> 2;
    const int t = l & 3;
    const int n0 = blockIdx.x * 128;
    const int h0 = blockIdx.y * 128;
    const int b  = blockIdx.z;
    const __half* Xb = X + (size_t)b * Cn * Nn;

    float acc[16][4] = {};

    proj_issue(sb, 0, whi, wlo, Xb, h0, n0, 0, tid);
    CP_COMMIT();

    if (MODE == 0) {
        const int wh = (w & 3) * 32;
        const int wn = (w >> 2) * 64;
        const uint32_t aW = (uint32_t)((wh + (l & 15)) * 80 + (l >> 4) * 16);
        const uint32_t bX = (uint32_t)((((l >> 3) & 1) * 8 + (l & 7)) * 272 + (wn + (l >> 4) * 8) * 2);

        for (int ck = 0; ck < 8; ck++) {
            if (ck < 7) { proj_issue(sb, (ck + 1) & 1, whi, wlo, Xb, h0, n0, (ck + 1) * 32, tid);
                          CP_COMMIT(); CP_WAIT1(); }
            else CP_WAIT0();
            __syncthreads();
            const uint32_t bb = sb + (ck & 1) * PJ_BUF;
            #pragma unroll
            for (int ks = 0; ks < 2; ks++) {
                uint32_t q[4][4];
                #pragma unroll
                for (int jj = 0; jj < 4; jj++)
                    ldm4t(q[jj], bb + PJ_X + bX + ks * 4352 + jj * 32);
                #pragma unroll
                for (int part = 0; part < 2; part++) {
                    uint32_t a[2][4];
                    ldm4(a[0], bb + part * PJ_WL + aW + ks * 32);
                    ldm4(a[1], bb + part * PJ_WL + aW + 16 * 80 + ks * 32);
                    #pragma unroll
                    for (int mi = 0; mi < 2; mi++)
                        #pragma unroll
                        for (int jj = 0; jj < 4; jj++) {
                            mma16816(acc[mi * 8 + jj * 2],     a[mi], q[jj][0], q[jj][1]);
                            mma16816(acc[mi * 8 + jj * 2 + 1], a[mi], q[jj][2], q[jj][3]);
                        }
                }
            }
            __syncthreads();
        }
        #pragma unroll
        for (int mi = 0; mi < 2; mi++) {
            float bv0 = bias[h0 + wh + mi * 16 + g];
            float bv1 = bias[h0 + wh + mi * 16 + g + 8];
            #pragma unroll
            for (int j = 0; j < 8; j++) {
                int h = h0 + wh + mi * 16 + g;
                int n = n0 + wn + j * 8 + 2 * t;
                float* a = acc[mi * 8 + j];
                *(uint32_t*)(out + ((size_t)(b * Hn + h)) * Nn + n) =
                    packh2(__float2half_rn(a[0] + bv0), __float2half_rn(a[1] + bv0));
                *(uint32_t*)(out + ((size_t)(b * Hn + h + 8)) * Nn + n) =
                    packh2(__float2half_rn(a[2] + bv1), __float2half_rn(a[3] + bv1));
            }
        }
    } else {
        const int wn = (w & 1) * 64;
        const int wh = (w >> 1) * 32;
        const uint32_t aX = (uint32_t)(((l >> 4) * 8 + (l & 7)) * 272 + (wn + ((l >> 3) & 1) * 8) * 2);
        const uint32_t bW = (uint32_t)((wh + ((l >> 4) << 3) + (l & 7)) * 80 + ((l >> 3) & 1) * 16);

        for (int ck = 0; ck < 8; ck++) {
            if (ck < 7) { proj_issue(sb, (ck + 1) & 1, whi, wlo, Xb, h0, n0, (ck + 1) * 32, tid);
                          CP_COMMIT(); CP_WAIT1(); }
            else CP_WAIT0();
            __syncthreads();
            const uint32_t bb = sb + (ck & 1) * PJ_BUF;
            #pragma unroll
            for (int ks = 0; ks < 2; ks++) {
                uint32_t a[4][4];
                #pragma unroll
                for (int mi = 0; mi < 4; mi++)
                    ldm4t(a[mi], bb + PJ_X + aX + ks * 4352 + mi * 32);
                #pragma unroll
                for (int part = 0; part < 2; part++)
                    #pragma unroll
                    for (int jj = 0; jj < 2; jj++) {
                        uint32_t qq[4];
                        ldm4(qq, bb + part * PJ_WL + bW + jj * 1280 + ks * 32);
                        #pragma unroll
                        for (int mi = 0; mi < 4; mi++) {
                            mma16816(acc[mi * 4 + jj * 2],     a[mi], qq[0], qq[1]);
                            mma16816(acc[mi * 4 + jj * 2 + 1], a[mi], qq[2], qq[3]);
                        }
                    }
            }
            __syncthreads();
        }
        float bvj[4][2];
        #pragma unroll
        for (int j = 0; j < 4; j++) {
            bvj[j][0] = bias[h0 + wh + j * 8 + 2 * t];
            bvj[j][1] = bias[h0 + wh + j * 8 + 2 * t + 1];
        }
        #pragma unroll
        for (int mi = 0; mi < 4; mi++) {
            int nr = n0 + wn + mi * 16 + g;
            #pragma unroll
            for (int j = 0; j < 4; j++) {
                float* a = acc[mi * 4 + j];
                int hc = h0 + wh + j * 8 + 2 * t;
                *(uint32_t*)(out + ((size_t)(b * Nn + nr)) * Hn + hc) =
                    packh2(__float2half_rn(a[0] + bvj[j][0]), __float2half_rn(a[1] + bvj[j][1]));
                *(uint32_t*)(out + ((size_t)(b * Nn + nr + 8)) * Hn + hc) =
                    packh2(__float2half_rn(a[2] + bvj[j][0]), __float2half_rn(a[3] + bvj[j][1]));
            }
        }
    }
}

// ---------------------------------------------------------------------------
// Grouped conv1d fp16 (groups=32, kw=3, SAME) + bias + ReLU: g_v1h -> g_v2h
// ---------------------------------------------------------------------------
__global__ __launch_bounds__(256) void gconv16_kernel(
    const float* __restrict__ W2, const float* __restrict__ b2)
{
    __shared__ __half xs[8][536];
    __shared__ float ws[192];
    __shared__ float bs[8];

    const int tid = threadIdx.x;
    const int n0 = blockIdx.x * 512;
    const int gr = blockIdx.y;
    const int b  = blockIdx.z;

    if (tid < 192) ws[tid] = W2[gr * 192 + tid];
    if (tid < 8)   bs[tid] = b2[gr * 8 + tid];

    const __half* in = g_v1h + ((size_t)b * Hn + gr * 8) * Nn;
    for (int idx = tid; idx < 8 * 66; idx += 256) {
        int r = idx / 66, c = idx % 66;
        int gn = n0 - 8 + c * 8;
        if (gn >= 0 && gn + 8 <= Nn) {
            *(uint4*)&xs[r][c * 8] = *(const uint4*)(in + (size_t)r * Nn + gn);
        } else {
            #pragma unroll
            for (int j = 0; j < 8; j++) {
                int n = gn + j;
                xs[r][c * 8 + j] = (n >= 0 && n < Nn) ? in[(size_t)r * Nn + n] : __half(0.f);
            }
        }
    }
    __syncthreads();

    __half* ob = g_v2h + ((size_t)b * Hn + gr * 8) * Nn + n0;
    #pragma unroll
    for (int k = 0; k < 2; k++) {
        int n = tid + k * 256;
        float xm[8], x0[8], xp[8];
        #pragma unroll
        for (int i = 0; i < 8; i++) {
            xm[i] = __half2float(xs[i][8 + n - 1]);
            x0[i] = __half2float(xs[i][8 + n]);
            xp[i] = __half2float(xs[i][8 + n + 1]);
        }
        #pragma unroll
        for (int h = 0; h < 8; h++) {
            float acc = bs[h];
            #pragma unroll
            for (int i = 0; i < 8; i++) {
                acc = fmaf(ws[h * 24 + i * 3 + 0], xm[i], acc);
                acc = fmaf(ws[h * 24 + i * 3 + 1], x0[i], acc);
                acc = fmaf(ws[h * 24 + i * 3 + 2], xp[i], acc);
            }
            ob[(size_t)h * Nn + n] = __float2half_rn(fmaxf(acc, 0.f));
        }
    }
}

// ---------------------------------------------------------------------------
// Fused HMMA attention, software-pipelined:
// per iteration: GEMM2(it) + GEMM1(it+1) back-to-back, epilogue(it+1),
// one __syncthreads. K/V cp.async double-buffered (K one tile ahead),
// E double-buffered.
// ---------------------------------------------------------------------------
#define OFF_Q   0
#define OFF_K   33792
#define OFF_V   101376
#define OFF_E   175104
#define OFF_CS  193536
#define AT_SMEM 194048
#define KBUF    33792
#define VBUF    36864
#define EBUF    9216

__device__ __forceinline__ void issue_k(uint32_t sb, int buf, const __half* kb, int n0, int tid) {
    uint32_t kd = sb + OFF_K + buf * KBUF;
    #pragma unroll
    for (int i = 0; i < 8; i++) {
        int ch = tid + i * 256;
        int r = ch >> 5, c = ch & 31;
        CP16(kd + r * 528 + c * 16, kb + (size_t)(n0 + r) * Hn + c * 8);
    }
}
__device__ __forceinline__ void issue_v(uint32_t sb, int buf, const __half* vb, int n0, int tid) {
    uint32_t vd = sb + OFF_V + buf * VBUF;
    #pragma unroll
    for (int i = 0; i < 8; i++) {
        int ch = tid + i * 256;
        int r = ch >> 3, c = ch & 7;
        CP16(vd + r * 144 + c * 16, vb + (size_t)r * Nn + n0 + c * 8);
    }
}

#define GEMM1_BODY(kbase) do {                                              \
    _Pragma("unroll")                                                       \
    for (int ks = 0; ks < 16; ks++) {                                       \
        uint32_t ah[4], p[4], q[4];                                         \
        ldm4(ah, aQ + ks * 32);                                             \
        ldm4(p, (kbase) + bKoff + ks * 32);                                 \
        ldm4(q, (kbase) + bKoff + 16 * 528 + ks * 32);                      \
        mma16816(acc1[0], ah, p[0], p[1]);                                  \
        mma16816(acc1[1], ah, p[2], p[3]);                                  \
        mma16816(acc1[2], ah, q[0], q[1]);                                  \
        mma16816(acc1[3], ah, q[2], q[3]);                                  \
    } } while (0)

#define EPI_BODY(ebase) do {                                                \
    _Pragma("unroll")                                                       \
    for (int nt = 0; nt < 4; nt++) {                                        \
        float e00 = __expf(acc1[nt][0] - 4.f);                              \
        float e01 = __expf(acc1[nt][1] - 4.f);                              \
        float e10 = __expf(acc1[nt][2] - 4.f);                              \
        float e11 = __expf(acc1[nt][3] - 4.f);                              \
        cs0 += e00 + e01;                                                   \
        cs1 += e10 + e11;                                                   \
        const uint32_t colb = (uint32_t)((wn + nt * 8 + 2 * t) * 2);        \
        *(uint32_t*)(smem + (ebase) + er0 + colb) =                         \
            packh2(__float2half_rn(e00), __float2half_rn(e01));             \
        *(uint32_t*)(smem + (ebase) + er1 + colb) =                         \
            packh2(__float2half_rn(e10), __float2half_rn(e11));             \
    } } while (0)

#define GEMM2_BODY(ebase, vbase) do {                                       \
    _Pragma("unroll")                                                       \
    for (int ks = 0; ks < 4; ks++) {                                        \
        uint32_t ah0[4], ah1[4];                                            \
        ldm4(ah0, (ebase) + aEoff + ks * 32);                               \
        ldm4(ah1, (ebase) + aEoff + 16 * 144 + ks * 32);                    \
        _Pragma("unroll")                                                   \
        for (int j = 0; j < 4; j++) {                                       \
            uint32_t bb[4];                                                 \
            ldm4(bb, (vbase) + bVoff + j * (16 * 144) + ks * 32);           \
            mma16816(acc2[0 + j * 2 + 0], ah0, bb[0], bb[1]);               \
            mma16816(acc2[0 + j * 2 + 1], ah0, bb[2], bb[3]);               \
            mma16816(acc2[8 + j * 2 + 0], ah1, bb[0], bb[1]);               \
            mma16816(acc2[8 + j * 2 + 1], ah1, bb[2], bb[3]);               \
        }                                                                   \
    } } while (0)

__global__ __launch_bounds__(256, 1)
void attn_kernel(const __half* __restrict__ qt, const __half* __restrict__ kt,
                 const __half* __restrict__ vh, float* __restrict__ out)
{
    extern __shared__ char smem[];
    const int tid  = threadIdx.x;
    const int l    = tid & 31;
    const int w    = tid >> 5;
    const int m0 = blockIdx.x * 64;
    const int b  = blockIdx.y;
    const uint32_t sb = smem_u32(smem);
    const int g = l >> 2;
    const int t = l & 3;

    const int wm  = (w >> 1) * 16;   // GEMM1: warp 16m x 32n
    const int wn  = (w & 1) * 32;
    const int wm2 = (w & 1) * 32;    // GEMM2: warp 32m x 64o
    const int wo2 = (w >> 1) * 64;

    const __half* kb = kt + (size_t)b * Nn * Hn;
    const __half* vb = vh + (size_t)b * On * Nn;

    // prologue: persistent Q [64 m][256 h]
    #pragma unroll
    for (int i = 0; i < 8; i++) {
        int ch = tid + i * 256;
        int r = ch >> 5, c = ch & 31;
        *(float4*)(smem + OFF_Q + r * 528 + c * 16) =
            *(const float4*)(qt + ((size_t)(b * Nn + m0 + r)) * Hn + c * 8);
    }
    issue_k(sb, 0, kb, 0, tid);
    issue_v(sb, 0, vb, 0, tid);
    CP_COMMIT();
    issue_k(sb, 1, kb, 64, tid);
    CP_COMMIT();

    const uint32_t aQ    = sb + OFF_Q + (uint32_t)((wm + (l & 15)) * 528 + (l >> 4) * 16);
    const uint32_t bKoff = (uint32_t)((wn + ((l >> 4) << 3) + (l & 7)) * 528 + ((l >> 3) & 1) * 16);
    const uint32_t bVoff = (uint32_t)((wo2 + ((l >> 4) << 3) + (l & 7)) * 144 + ((l >> 3) & 1) * 16);
    const uint32_t aEoff = (uint32_t)((wm2 + (l & 15)) * 144 + (l >> 4) * 16);
    const uint32_t er0   = (uint32_t)((wm + g) * 144);
    const uint32_t er1   = (uint32_t)((wm + g + 8) * 144);

    float acc2[16][4] = {};
    float cs0 = 0.f, cs1 = 0.f;
    float acc1[4][4];

    // ---- pipeline prologue: GEMM1(0) + epi(0) -> Ebuf0 ----
    CP_WAIT0();
    __syncthreads();
    #pragma unroll
    for (int i = 0; i < 4; i++)
        #pragma unroll
        for (int j = 0; j < 4; j++) acc1[i][j] = 0.f;
    GEMM1_BODY(sb + OFF_K + 0 * KBUF);
    EPI_BODY(OFF_E + 0 * EBUF);
    __syncthreads();

    // ---- main loop: it = 0..62 ----
    for (int it = 0; it < 63; it++) {
        // prefetch: V(it+1), K(it+2)
        issue_v(sb, (it + 1) & 1, vb, (it + 1) * 64, tid);
        if (it + 2 < 64) issue_k(sb, it & 1, kb, (it + 2) * 64, tid);
        CP_COMMIT();

        // GEMM2(it) + GEMM1(it+1): one uninterrupted HMMA stretch
        GEMM2_BODY(sb + OFF_E + (it & 1) * EBUF, sb + OFF_V + (it & 1) * VBUF);
        #pragma unroll
        for (int i = 0; i < 4; i++)
            #pragma unroll
            for (int j = 0; j < 4; j++) acc1[i][j] = 0.f;
        GEMM1_BODY(sb + OFF_K + ((it + 1) & 1) * KBUF);

        // epilogue(it+1) -> Ebuf[(it+1)&1]
        EPI_BODY(OFF_E + ((it + 1) & 1) * EBUF);

        CP_WAIT0();
        __syncthreads();
    }

    // ---- tail: GEMM2(63) ----
    GEMM2_BODY(sb + OFF_E + 1 * EBUF, sb + OFF_V + 1 * VBUF);

    // ---- colsum reduce ----
    cs0 += __shfl_xor_sync(0xFFFFFFFFu, cs0, 1);
    cs0 += __shfl_xor_sync(0xFFFFFFFFu, cs0, 2);
    cs1 += __shfl_xor_sync(0xFFFFFFFFu, cs1, 1);
    cs1 += __shfl_xor_sync(0xFFFFFFFFu, cs1, 2);
    float* CS = (float*)(smem + OFF_CS);   // [2][64]
    if (t == 0) {
        CS[(w & 1) * 64 + wm + g]     = cs0;
        CS[(w & 1) * 64 + wm + g + 8] = cs1;
    }
    __syncthreads();

    float inv[2][2];
    #pragma unroll
    for (int mi = 0; mi < 2; mi++) {
        int r0 = wm2 + mi * 16 + g;
        inv[mi][0] = 1.f / (CS[r0] + CS[64 + r0]);
        inv[mi][1] = 1.f / (CS[r0 + 8] + CS[64 + r0 + 8]);
    }

    #pragma unroll
    for (int mi = 0; mi < 2; mi++) {
        const int mrow0 = wm2 + mi * 16 + g;
        #pragma unroll
        for (int jt = 0; jt < 8; jt++) {
            const int o = wo2 + jt * 8 + 2 * t;
            const float* a = acc2[mi * 8 + jt];
            float* p0 = out + ((size_t)(b * On + o)) * Nn + m0;
            float* p1 = p0 + Nn;
            p0[mrow0]     = a[0] * inv[mi][0];
            p1[mrow0]     = a[1] * inv[mi][0];
            p0[mrow0 + 8] = a[2] * inv[mi][1];
            p1[mrow0 + 8] = a[3] * inv[mi][1];
        }
    }
}

// ---------------------------------------------------------------------------
extern "C" void kernel_launch(void* const* d_in, const int* in_sizes, int n_in,
                              void* d_out, int out_size)
{
    const float* x  = (const float*)d_in[0];
    const float* Wk = (const float*)d_in[1];
    const float* bk = (const float*)d_in[2];
    const float* Wq = (const float*)d_in[3];
    const float* bq = (const float*)d_in[4];
    const float* W1 = (const float*)d_in[5];
    const float* b1 = (const float*)d_in[6];
    const float* W2 = (const float*)d_in[7];
    const float* b2 = (const float*)d_in[8];
    const float* W3 = (const float*)d_in[9];
    const float* b3 = (const float*)d_in[10];
    float* out = (float*)d_out;

    __half *x16, *whi, *wlo, *ktp, *qtp, *v1h, *v2h, *vhp;
    cudaGetSymbolAddress((void**)&x16, g_x16);
    cudaGetSymbolAddress((void**)&whi, g_whi);
    cudaGetSymbolAddress((void**)&wlo, g_wlo);
    cudaGetSymbolAddress((void**)&ktp, g_kt);
    cudaGetSymbolAddress((void**)&qtp, g_qt);
    cudaGetSymbolAddress((void**)&v1h, g_v1h);
    cudaGetSymbolAddress((void**)&v2h, g_v2h);
    cudaGetSymbolAddress((void**)&vhp, g_vh);

    cudaFuncSetAttribute(proj16_kernel<0>, cudaFuncAttributeMaxDynamicSharedMemorySize, PJ_SMEM);
    cudaFuncSetAttribute(proj16_kernel<1>, cudaFuncAttributeMaxDynamicSharedMemorySize, PJ_SMEM);
    cudaFuncSetAttribute(attn_kernel, cudaFuncAttributeMaxDynamicSharedMemorySize, AT_SMEM);

    x16_kernel<<<4096, 256>>>(x);
    wprep_kernel<<<dim3(256, 4), 256>>>(Wk, Wq, W1, W3);

    dim3 pg(Nn / 128, Hn / 128, Bn);
    proj16_kernel<1><<<pg, 256, PJ_SMEM>>>(whi + 0 * 65536, wlo + 0 * 65536, bk, x16, ktp);
    proj16_kernel<1><<<pg, 256, PJ_SMEM>>>(whi + 1 * 65536, wlo + 1 * 65536, bq, x16, qtp);
    proj16_kernel<0><<<pg, 256, PJ_SMEM>>>(whi + 2 * 65536, wlo + 2 * 65536, b1, x16, v1h);
    gconv16_kernel<<<dim3(Nn / 512, 32, Bn), 256>>>(W2, b2);
    proj16_kernel<0><<<pg, 256, PJ_SMEM>>>(whi + 3 * 65536, wlo + 3 * 65536, b3, v2h, vhp);
    attn_kernel<<<dim3(Nn / 64, Bn), 256, AT_SMEM>>>(qtp, ktp, vhp, out);
}

// round 9
// speedup vs baseline: 7.2810x; 1.1060x over previous
#include <cuda_runtime.h>
#include <cuda_fp16.h>
#include <cstdint>

#define Bn 4
#define Cn 256
#define Hn 256
#define On 256
#define Nn 4096

// ---------------- scratch (device globals) ----------------------------------
__device__ __half g_x16[(size_t)Bn*Cn*Nn];   // x fp16 [b][c][n]
__device__ __half g_whi[4 * Cn * Hn];        // W hi fp16 (Wk,Wq,W1,W3)
__device__ __half g_wlo[4 * Cn * Hn];        // W lo fp16
__device__ __half g_kt [(size_t)Bn*Nn*Hn];   // k^T [b][n][h]
__device__ __half g_qt [(size_t)Bn*Nn*Hn];   // q^T [b][n][h] (scaled by log2e)
__device__ __half g_v1h[(size_t)Bn*Hn*Nn];   // v1 [b][h][n]
__device__ __half g_v2h[(size_t)Bn*Hn*Nn];   // v2 [b][h][n]
__device__ __half g_vh [(size_t)Bn*On*Nn];   // v  [b][o][n]

// ---------------- helpers ----------------------------------------------------
__device__ __forceinline__ uint32_t smem_u32(const void* p) {
    uint32_t a;
    asm("{ .reg .u64 t; cvta.to.shared.u64 t, %1; cvt.u32.u64 %0, t; }" : "=r"(a) : "l"(p));
    return a;
}
__device__ __forceinline__ uint32_t packh2(__half a, __half b) {
    __half2 h = __halves2half2(a, b);
    return *reinterpret_cast<const uint32_t*>(&h);
}
__device__ __forceinline__ float ex2(float x) {
    float r;
    asm("ex2.approx.f32 %0, %1;" : "=f"(r) : "f"(x));
    return r;
}
__device__ __forceinline__ void ldm4(uint32_t* r, uint32_t addr) {
    asm volatile("ldmatrix.sync.aligned.m8n8.x4.shared.b16 {%0,%1,%2,%3}, [%4];"
                 : "=r"(r[0]), "=r"(r[1]), "=r"(r[2]), "=r"(r[3]) : "r"(addr));
}
__device__ __forceinline__ void ldm4t(uint32_t* r, uint32_t addr) {
    asm volatile("ldmatrix.sync.aligned.m8n8.x4.trans.shared.b16 {%0,%1,%2,%3}, [%4];"
                 : "=r"(r[0]), "=r"(r[1]), "=r"(r[2]), "=r"(r[3]) : "r"(addr));
}
__device__ __forceinline__ void mma16816(float* c, const uint32_t* a, uint32_t b0, uint32_t b1) {
    asm volatile("mma.sync.aligned.m16n8k16.row.col.f32.f16.f16.f32 "
                 "{%0,%1,%2,%3}, {%4,%5,%6,%7}, {%8,%9}, {%0,%1,%2,%3};"
                 : "+f"(c[0]), "+f"(c[1]), "+f"(c[2]), "+f"(c[3])
                 : "r"(a[0]), "r"(a[1]), "r"(a[2]), "r"(a[3]), "r"(b0), "r"(b1));
}
#define CP16(dst, src) \
    asm volatile("cp.async.cg.shared.global [%0], [%1], 16;" :: "r"(dst), "l"(src))
#define CP_COMMIT() asm volatile("cp.async.commit_group;" ::: "memory")
#define CP_WAIT0()  asm volatile("cp.async.wait_group 0;" ::: "memory")
#define CP_WAIT1()  asm volatile("cp.async.wait_group 1;" ::: "memory")

// ---------------------------------------------------------------------------
// Prep: x fp32 -> fp16 ; weights fp32 -> hi/lo fp16
// ---------------------------------------------------------------------------
__global__ __launch_bounds__(256) void x16_kernel(const float* __restrict__ x) {
    size_t q = (size_t)blockIdx.x * 256 + threadIdx.x;
    float4 v = *(const float4*)(x + q * 4);
    uint2 u;
    u.x = packh2(__float2half_rn(v.x), __float2half_rn(v.y));
    u.y = packh2(__float2half_rn(v.z), __float2half_rn(v.w));
    *(uint2*)(g_x16 + q * 4) = u;
}

__global__ __launch_bounds__(256) void wprep_kernel(
    const float* __restrict__ W0, const float* __restrict__ W1,
    const float* __restrict__ W2, const float* __restrict__ W3) {
    int e = blockIdx.x * 256 + threadIdx.x;
    int m = blockIdx.y;
    const float* src = (m == 0) ? W0 : (m == 1) ? W1 : (m == 2) ? W2 : W3;
    float f = src[e];
    __half hi = __float2half_rn(f);
    __half lo = __float2half_rn(f - __half2float(hi));
    g_whi[m * 65536 + e] = hi;
    g_wlo[m * 65536 + e] = lo;
}

// ---------------------------------------------------------------------------
// HMMA projection: out[h,n] = (sum_c (Whi+Wlo)[h,c] X16[c,n] + bias[h]) * scale
// CTA tile 128h x 128n, K chunks of 32, 3-stage cp.async ring, 1 sync/chunk.
// ---------------------------------------------------------------------------
#define PJ_WL    10240
#define PJ_X     20480
#define PJ_BUF   29184
#define PJ_SMEM  87552

__device__ __forceinline__ void proj_issue(
    uint32_t sb, int buf, const __half* whi, const __half* wlo,
    const __half* X, int h0, int n0, int c0, int tid)
{
    uint32_t base = sb + buf * PJ_BUF;
    #pragma unroll
    for (int i = 0; i < 6; i++) {
        int idx = tid + i * 256;
        if (idx < 512) {
            int r = idx >> 4, c = idx & 15;
            CP16(base + PJ_X + r * 272 + c * 16, X + (size_t)(c0 + r) * Nn + n0 + c * 8);
        } else {
            int i2 = idx - 512;
            int part = i2 >> 9, r = (i2 >> 2) & 127, c = i2 & 3;
            const __half* w = part ? wlo : whi;
            CP16(base + part * PJ_WL + r * 80 + c * 16, w + (size_t)(h0 + r) * Cn + c0 + c * 8);
        }
    }
}

// MODE 0 ("N"): out [b][h][n].  MODE 1 ("T"): out [b][n][h].
template <int MODE>
__global__ __launch_bounds__(256, 2) void proj16_kernel(
    const __half* __restrict__ whi, const __half* __restrict__ wlo,
    const float* __restrict__ bias, const __half* __restrict__ X,
    __half* __restrict__ out, float scale)
{
    extern __shared__ char smem[];
    const uint32_t sb = smem_u32(smem);
    const int tid = threadIdx.x;
    const int l = tid & 31;
    const int w = tid >> 5;
    const int g = l >> 2;
    const int t = l & 3;
    const int n0 = blockIdx.x * 128;
    const int h0 = blockIdx.y * 128;
    const int b  = blockIdx.z;
    const __half* Xb = X + (size_t)b * Cn * Nn;

    float acc[16][4] = {};

    proj_issue(sb, 0, whi, wlo, Xb, h0, n0, 0, tid);
    CP_COMMIT();
    proj_issue(sb, 1, whi, wlo, Xb, h0, n0, 32, tid);
    CP_COMMIT();

    if (MODE == 0) {
        const int wh = (w & 3) * 32;
        const int wn = (w >> 2) * 64;
        const uint32_t aW = (uint32_t)((wh + (l & 15)) * 80 + (l >> 4) * 16);
        const uint32_t bX = (uint32_t)((((l >> 3) & 1) * 8 + (l & 7)) * 272 + (wn + (l >> 4) * 8) * 2);

        for (int ck = 0; ck < 8; ck++) {
            if (ck < 6) CP_WAIT1(); else CP_WAIT0();
            __syncthreads();
            if (ck <= 5) { proj_issue(sb, (ck + 2) % 3, whi, wlo, Xb, h0, n0, (ck + 2) * 32, tid);
                           CP_COMMIT(); }
            const uint32_t bb = sb + (ck % 3) * PJ_BUF;
            #pragma unroll
            for (int ks = 0; ks < 2; ks++) {
                uint32_t q[4][4];
                #pragma unroll
                for (int jj = 0; jj < 4; jj++)
                    ldm4t(q[jj], bb + PJ_X + bX + ks * 4352 + jj * 32);
                #pragma unroll
                for (int part = 0; part < 2; part++) {
                    uint32_t a[2][4];
                    ldm4(a[0], bb + part * PJ_WL + aW + ks * 32);
                    ldm4(a[1], bb + part * PJ_WL + aW + 16 * 80 + ks * 32);
                    #pragma unroll
                    for (int mi = 0; mi < 2; mi++)
                        #pragma unroll
                        for (int jj = 0; jj < 4; jj++) {
                            mma16816(acc[mi * 8 + jj * 2],     a[mi], q[jj][0], q[jj][1]);
                            mma16816(acc[mi * 8 + jj * 2 + 1], a[mi], q[jj][2], q[jj][3]);
                        }
                }
            }
        }
        #pragma unroll
        for (int mi = 0; mi < 2; mi++) {
            float bv0 = bias[h0 + wh + mi * 16 + g];
            float bv1 = bias[h0 + wh + mi * 16 + g + 8];
            #pragma unroll
            for (int j = 0; j < 8; j++) {
                int h = h0 + wh + mi * 16 + g;
                int n = n0 + wn + j * 8 + 2 * t;
                float* a = acc[mi * 8 + j];
                *(uint32_t*)(out + ((size_t)(b * Hn + h)) * Nn + n) =
                    packh2(__float2half_rn((a[0] + bv0) * scale), __float2half_rn((a[1] + bv0) * scale));
                *(uint32_t*)(out + ((size_t)(b * Hn + h + 8)) * Nn + n) =
                    packh2(__float2half_rn((a[2] + bv1) * scale), __float2half_rn((a[3] + bv1) * scale));
            }
        }
    } else {
        const int wn = (w & 1) * 64;
        const int wh = (w >> 1) * 32;
        const uint32_t aX = (uint32_t)(((l >> 4) * 8 + (l & 7)) * 272 + (wn + ((l >> 3) & 1) * 8) * 2);
        const uint32_t bW = (uint32_t)((wh + ((l >> 4) << 3) + (l & 7)) * 80 + ((l >> 3) & 1) * 16);

        for (int ck = 0; ck < 8; ck++) {
            if (ck < 6) CP_WAIT1(); else CP_WAIT0();
            __syncthreads();
            if (ck <= 5) { proj_issue(sb, (ck + 2) % 3, whi, wlo, Xb, h0, n0, (ck + 2) * 32, tid);
                           CP_COMMIT(); }
            const uint32_t bb = sb + (ck % 3) * PJ_BUF;
            #pragma unroll
            for (int ks = 0; ks < 2; ks++) {
                uint32_t a[4][4];
                #pragma unroll
                for (int mi = 0; mi < 4; mi++)
                    ldm4t(a[mi], bb + PJ_X + aX + ks * 4352 + mi * 32);
                #pragma unroll
                for (int part = 0; part < 2; part++)
                    #pragma unroll
                    for (int jj = 0; jj < 2; jj++) {
                        uint32_t qq[4];
                        ldm4(qq, bb + part * PJ_WL + bW + jj * 1280 + ks * 32);
                        #pragma unroll
                        for (int mi = 0; mi < 4; mi++) {
                            mma16816(acc[mi * 4 + jj * 2],     a[mi], qq[0], qq[1]);
                            mma16816(acc[mi * 4 + jj * 2 + 1], a[mi], qq[2], qq[3]);
                        }
                    }
            }
        }
        float bvj[4][2];
        #pragma unroll
        for (int j = 0; j < 4; j++) {
            bvj[j][0] = bias[h0 + wh + j * 8 + 2 * t];
            bvj[j][1] = bias[h0 + wh + j * 8 + 2 * t + 1];
        }
        #pragma unroll
        for (int mi = 0; mi < 4; mi++) {
            int nr = n0 + wn + mi * 16 + g;
            #pragma unroll
            for (int j = 0; j < 4; j++) {
                float* a = acc[mi * 4 + j];
                int hc = h0 + wh + j * 8 + 2 * t;
                *(uint32_t*)(out + ((size_t)(b * Nn + nr)) * Hn + hc) =
                    packh2(__float2half_rn((a[0] + bvj[j][0]) * scale), __float2half_rn((a[1] + bvj[j][1]) * scale));
                *(uint32_t*)(out + ((size_t)(b * Nn + nr + 8)) * Hn + hc) =
                    packh2(__float2half_rn((a[2] + bvj[j][0]) * scale), __float2half_rn((a[3] + bvj[j][1]) * scale));
            }
        }
    }
}

// ---------------------------------------------------------------------------
// Grouped conv1d fp16 (groups=32, kw=3, SAME) + bias + ReLU: g_v1h -> g_v2h
// ---------------------------------------------------------------------------
__global__ __launch_bounds__(256) void gconv16_kernel(
    const float* __restrict__ W2, const float* __restrict__ b2)
{
    __shared__ __half xs[8][536];
    __shared__ float ws[192];
    __shared__ float bs[8];

    const int tid = threadIdx.x;
    const int n0 = blockIdx.x * 512;
    const int gr = blockIdx.y;
    const int b  = blockIdx.z;

    if (tid < 192) ws[tid] = W2[gr * 192 + tid];
    if (tid < 8)   bs[tid] = b2[gr * 8 + tid];

    const __half* in = g_v1h + ((size_t)b * Hn + gr * 8) * Nn;
    for (int idx = tid; idx < 8 * 66; idx += 256) {
        int r = idx / 66, c = idx % 66;
        int gn = n0 - 8 + c * 8;
        if (gn >= 0 && gn + 8 <= Nn) {
            *(uint4*)&xs[r][c * 8] = *(const uint4*)(in + (size_t)r * Nn + gn);
        } else {
            #pragma unroll
            for (int j = 0; j < 8; j++) {
                int n = gn + j;
                xs[r][c * 8 + j] = (n >= 0 && n < Nn) ? in[(size_t)r * Nn + n] : __half(0.f);
            }
        }
    }
    __syncthreads();

    __half* ob = g_v2h + ((size_t)b * Hn + gr * 8) * Nn + n0;
    #pragma unroll
    for (int k = 0; k < 2; k++) {
        int n = tid + k * 256;
        float xm[8], x0[8], xp[8];
        #pragma unroll
        for (int i = 0; i < 8; i++) {
            xm[i] = __half2float(xs[i][8 + n - 1]);
            x0[i] = __half2float(xs[i][8 + n]);
            xp[i] = __half2float(xs[i][8 + n + 1]);
        }
        #pragma unroll
        for (int h = 0; h < 8; h++) {
            float acc = bs[h];
            #pragma unroll
            for (int i = 0; i < 8; i++) {
                acc = fmaf(ws[h * 24 + i * 3 + 0], xm[i], acc);
                acc = fmaf(ws[h * 24 + i * 3 + 1], x0[i], acc);
                acc = fmaf(ws[h * 24 + i * 3 + 2], xp[i], acc);
            }
            ob[(size_t)h * Nn + n] = __float2half_rn(fmaxf(acc, 0.f));
        }
    }
}

// ---------------------------------------------------------------------------
// Fused HMMA attention, software-pipelined, Q fragments in registers.
// q is pre-scaled by log2e, so E = 2^(l' - 4*log2e) = e^(l-4).
// ---------------------------------------------------------------------------
#define OFF_Q   0
#define OFF_K   33792
#define OFF_V   101376
#define OFF_E   175104
#define OFF_CS  193536
#define AT_SMEM 194048
#define KBUF    33792
#define VBUF    36864
#define EBUF    9216
#define EXP_BIAS 5.7707802f   /* 4 * log2(e) */

__device__ __forceinline__ void issue_k(uint32_t sb, int buf, const __half* kb, int n0, int tid) {
    uint32_t kd = sb + OFF_K + buf * KBUF;
    #pragma unroll
    for (int i = 0; i < 8; i++) {
        int ch = tid + i * 256;
        int r = ch >> 5, c = ch & 31;
        CP16(kd + r * 528 + c * 16, kb + (size_t)(n0 + r) * Hn + c * 8);
    }
}
__device__ __forceinline__ void issue_v(uint32_t sb, int buf, const __half* vb, int n0, int tid) {
    uint32_t vd = sb + OFF_V + buf * VBUF;
    #pragma unroll
    for (int i = 0; i < 8; i++) {
        int ch = tid + i * 256;
        int r = ch >> 3, c = ch & 7;
        CP16(vd + r * 144 + c * 16, vb + (size_t)r * Nn + n0 + c * 8);
    }
}

#define GEMM1_BODY(kbase) do {                                              \
    _Pragma("unroll")                                                       \
    for (int ks = 0; ks < 16; ks++) {                                       \
        uint32_t p[4], q[4];                                                \
        ldm4(p, (kbase) + bKoff + ks * 32);                                 \
        ldm4(q, (kbase) + bKoff + 16 * 528 + ks * 32);                      \
        mma16816(acc1[0], qf[ks], p[0], p[1]);                              \
        mma16816(acc1[1], qf[ks], p[2], p[3]);                              \
        mma16816(acc1[2], qf[ks], q[0], q[1]);                              \
        mma16816(acc1[3], qf[ks], q[2], q[3]);                              \
    } } while (0)

#define EPI_BODY(ebase) do {                                                \
    _Pragma("unroll")                                                       \
    for (int nt = 0; nt < 4; nt++) {                                        \
        float e00 = ex2(acc1[nt][0] - EXP_BIAS);                            \
        float e01 = ex2(acc1[nt][1] - EXP_BIAS);                            \
        float e10 = ex2(acc1[nt][2] - EXP_BIAS);                            \
        float e11 = ex2(acc1[nt][3] - EXP_BIAS);                            \
        cs0 += e00 + e01;                                                   \
        cs1 += e10 + e11;                                                   \
        const uint32_t colb = (uint32_t)((wn + nt * 8 + 2 * t) * 2);        \
        *(uint32_t*)(smem + (ebase) + er0 + colb) =                         \
            packh2(__float2half_rn(e00), __float2half_rn(e01));             \
        *(uint32_t*)(smem + (ebase) + er1 + colb) =                         \
            packh2(__float2half_rn(e10), __float2half_rn(e11));             \
    } } while (0)

#define GEMM2_BODY(ebase, vbase) do {                                       \
    _Pragma("unroll")                                                       \
    for (int ks = 0; ks < 4; ks++) {                                        \
        uint32_t ah0[4], ah1[4];                                            \
        ldm4(ah0, (ebase) + aEoff + ks * 32);                               \
        ldm4(ah1, (ebase) + aEoff + 16 * 144 + ks * 32);                    \
        _Pragma("unroll")                                                   \
        for (int j = 0; j < 4; j++) {                                       \
            uint32_t bb[4];                                                 \
            ldm4(bb, (vbase) + bVoff + j * (16 * 144) + ks * 32);           \
            mma16816(acc2[0 + j * 2 + 0], ah0, bb[0], bb[1]);               \
            mma16816(acc2[0 + j * 2 + 1], ah0, bb[2], bb[3]);               \
            mma16816(acc2[8 + j * 2 + 0], ah1, bb[0], bb[1]);               \
            mma16816(acc2[8 + j * 2 + 1], ah1, bb[2], bb[3]);               \
        }                                                                   \
    } } while (0)

__global__ __launch_bounds__(256, 1)
void attn_kernel(const __half* __restrict__ qt, const __half* __restrict__ kt,
                 const __half* __restrict__ vh, float* __restrict__ out)
{
    extern __shared__ char smem[];
    const int tid  = threadIdx.x;
    const int l    = tid & 31;
    const int w    = tid >> 5;
    const int m0 = blockIdx.x * 64;
    const int b  = blockIdx.y;
    const uint32_t sb = smem_u32(smem);
    const int g = l >> 2;
    const int t = l & 3;

    const int wm  = (w >> 1) * 16;   // GEMM1: warp 16m x 32n
    const int wn  = (w & 1) * 32;
    const int wm2 = (w & 1) * 32;    // GEMM2: warp 32m x 64o
    const int wo2 = (w >> 1) * 64;

    const __half* kb = kt + (size_t)b * Nn * Hn;
    const __half* vb = vh + (size_t)b * On * Nn;

    // prologue: stage Q [64 m][256 h] to smem
    #pragma unroll
    for (int i = 0; i < 8; i++) {
        int ch = tid + i * 256;
        int r = ch >> 5, c = ch & 31;
        *(float4*)(smem + OFF_Q + r * 528 + c * 16) =
            *(const float4*)(qt + ((size_t)(b * Nn + m0 + r)) * Hn + c * 8);
    }
    issue_k(sb, 0, kb, 0, tid);
    issue_v(sb, 0, vb, 0, tid);
    CP_COMMIT();
    issue_k(sb, 1, kb, 64, tid);
    CP_COMMIT();

    const uint32_t aQ    = sb + OFF_Q + (uint32_t)((wm + (l & 15)) * 528 + (l >> 4) * 16);
    const uint32_t bKoff = (uint32_t)((wn + ((l >> 4) << 3) + (l & 7)) * 528 + ((l >> 3) & 1) * 16);
    const uint32_t bVoff = (uint32_t)((wo2 + ((l >> 4) << 3) + (l & 7)) * 144 + ((l >> 3) & 1) * 16);
    const uint32_t aEoff = (uint32_t)((wm2 + (l & 15)) * 144 + (l >> 4) * 16);
    const uint32_t er0   = (uint32_t)((wm + g) * 144);
    const uint32_t er1   = (uint32_t)((wm + g + 8) * 144);

    float acc2[16][4] = {};
    float cs0 = 0.f, cs1 = 0.f;
    float acc1[4][4];

    // ---- pipeline prologue ----
    CP_WAIT0();
    __syncthreads();

    // Load persistent Q fragments into registers (16 ks x 4 regs)
    uint32_t qf[16][4];
    #pragma unroll
    for (int ks = 0; ks < 16; ks++) ldm4(qf[ks], aQ + ks * 32);

    #pragma unroll
    for (int i = 0; i < 4; i++)
        #pragma unroll
        for (int j = 0; j < 4; j++) acc1[i][j] = 0.f;
    GEMM1_BODY(sb + OFF_K + 0 * KBUF);
    EPI_BODY(OFF_E + 0 * EBUF);
    __syncthreads();

    // ---- main loop: it = 0..62 ----
    for (int it = 0; it < 63; it++) {
        issue_v(sb, (it + 1) & 1, vb, (it + 1) * 64, tid);
        if (it + 2 < 64) issue_k(sb, it & 1, kb, (it + 2) * 64, tid);
        CP_COMMIT();

        GEMM2_BODY(sb + OFF_E + (it & 1) * EBUF, sb + OFF_V + (it & 1) * VBUF);
        #pragma unroll
        for (int i = 0; i < 4; i++)
            #pragma unroll
            for (int j = 0; j < 4; j++) acc1[i][j] = 0.f;
        GEMM1_BODY(sb + OFF_K + ((it + 1) & 1) * KBUF);

        EPI_BODY(OFF_E + ((it + 1) & 1) * EBUF);

        CP_WAIT0();
        __syncthreads();
    }

    // ---- tail ----
    GEMM2_BODY(sb + OFF_E + 1 * EBUF, sb + OFF_V + 1 * VBUF);

    // ---- colsum reduce ----
    cs0 += __shfl_xor_sync(0xFFFFFFFFu, cs0, 1);
    cs0 += __shfl_xor_sync(0xFFFFFFFFu, cs0, 2);
    cs1 += __shfl_xor_sync(0xFFFFFFFFu, cs1, 1);
    cs1 += __shfl_xor_sync(0xFFFFFFFFu, cs1, 2);
    float* CS = (float*)(smem + OFF_CS);   // [2][64]
    if (t == 0) {
        CS[(w & 1) * 64 + wm + g]     = cs0;
        CS[(w & 1) * 64 + wm + g + 8] = cs1;
    }
    __syncthreads();

    float inv[2][2];
    #pragma unroll
    for (int mi = 0; mi < 2; mi++) {
        int r0 = wm2 + mi * 16 + g;
        inv[mi][0] = 1.f / (CS[r0] + CS[64 + r0]);
        inv[mi][1] = 1.f / (CS[r0 + 8] + CS[64 + r0 + 8]);
    }

    #pragma unroll
    for (int mi = 0; mi < 2; mi++) {
        const int mrow0 = wm2 + mi * 16 + g;
        #pragma unroll
        for (int jt = 0; jt < 8; jt++) {
            const int o = wo2 + jt * 8 + 2 * t;
            const float* a = acc2[mi * 8 + jt];
            float* p0 = out + ((size_t)(b * On + o)) * Nn + m0;
            float* p1 = p0 + Nn;
            p0[mrow0]     = a[0] * inv[mi][0];
            p1[mrow0]     = a[1] * inv[mi][0];
            p0[mrow0 + 8] = a[2] * inv[mi][1];
            p1[mrow0 + 8] = a[3] * inv[mi][1];
        }
    }
}

// ---------------------------------------------------------------------------
extern "C" void kernel_launch(void* const* d_in, const int* in_sizes, int n_in,
                              void* d_out, int out_size)
{
    const float* x  = (const float*)d_in[0];
    const float* Wk = (const float*)d_in[1];
    const float* bk = (const float*)d_in[2];
    const float* Wq = (const float*)d_in[3];
    const float* bq = (const float*)d_in[4];
    const float* W1 = (const float*)d_in[5];
    const float* b1 = (const float*)d_in[6];
    const float* W2 = (const float*)d_in[7];
    const float* b2 = (const float*)d_in[8];
    const float* W3 = (const float*)d_in[9];
    const float* b3 = (const float*)d_in[10];
    float* out = (float*)d_out;

    __half *x16, *whi, *wlo, *ktp, *qtp, *v1h, *v2h, *vhp;
    cudaGetSymbolAddress((void**)&x16, g_x16);
    cudaGetSymbolAddress((void**)&whi, g_whi);
    cudaGetSymbolAddress((void**)&wlo, g_wlo);
    cudaGetSymbolAddress((void**)&ktp, g_kt);
    cudaGetSymbolAddress((void**)&qtp, g_qt);
    cudaGetSymbolAddress((void**)&v1h, g_v1h);
    cudaGetSymbolAddress((void**)&v2h, g_v2h);
    cudaGetSymbolAddress((void**)&vhp, g_vh);

    cudaFuncSetAttribute(proj16_kernel<0>, cudaFuncAttributeMaxDynamicSharedMemorySize, PJ_SMEM);
    cudaFuncSetAttribute(proj16_kernel<1>, cudaFuncAttributeMaxDynamicSharedMemorySize, PJ_SMEM);
    cudaFuncSetAttribute(attn_kernel, cudaFuncAttributeMaxDynamicSharedMemorySize, AT_SMEM);

    x16_kernel<<<4096, 256>>>(x);
    wprep_kernel<<<dim3(256, 4), 256>>>(Wk, Wq, W1, W3);

    const float LOG2E = 1.4426950408889634f;
    dim3 pg(Nn / 128, Hn / 128, Bn);
    proj16_kernel<1><<<pg, 256, PJ_SMEM>>>(whi + 0 * 65536, wlo + 0 * 65536, bk, x16, ktp, 1.0f);
    proj16_kernel<1><<<pg, 256, PJ_SMEM>>>(whi + 1 * 65536, wlo + 1 * 65536, bq, x16, qtp, LOG2E);
    proj16_kernel<0><<<pg, 256, PJ_SMEM>>>(whi + 2 * 65536, wlo + 2 * 65536, b1, x16, v1h, 1.0f);
    gconv16_kernel<<<dim3(Nn / 512, 32, Bn), 256>>>(W2, b2);
    proj16_kernel<0><<<pg, 256, PJ_SMEM>>>(whi + 3 * 65536, wlo + 3 * 65536, b3, v2h, vhp, 1.0f);
    attn_kernel<<<dim3(Nn / 64, Bn), 256, AT_SMEM>>>(qtp, ktp, vhp, out);
}

// round 10
// speedup vs baseline: 7.8748x; 1.0815x over previous
#include <cuda_runtime.h>
#include <cuda_fp16.h>
#include <cstdint>

#define Bn 4
#define Cn 256
#define Hn 256
#define On 256
#define Nn 4096

// ---------------- scratch (device globals) ----------------------------------
__device__ __half g_x16[(size_t)Bn*Cn*Nn];   // x fp16 [b][c][n]
__device__ __half g_whi[4 * Cn * Hn];        // W fp16 (Wk,Wq,W1,W3)
__device__ __half g_kt [(size_t)Bn*Nn*Hn];   // k^T [b][n][h]
__device__ __half g_qt [(size_t)Bn*Nn*Hn];   // q^T [b][n][h] (scaled by log2e)
__device__ __half g_v1h[(size_t)Bn*Hn*Nn];   // v1 [b][h][n]
__device__ __half g_v2h[(size_t)Bn*Hn*Nn];   // v2 [b][h][n]
__device__ __half g_vh [(size_t)Bn*On*Nn];   // v  [b][o][n]

// ---------------- helpers ----------------------------------------------------
__device__ __forceinline__ uint32_t smem_u32(const void* p) {
    uint32_t a;
    asm("{ .reg .u64 t; cvta.to.shared.u64 t, %1; cvt.u32.u64 %0, t; }" : "=r"(a) : "l"(p));
    return a;
}
__device__ __forceinline__ uint32_t packh2(__half a, __half b) {
    __half2 h = __halves2half2(a, b);
    return *reinterpret_cast<const uint32_t*>(&h);
}
__device__ __forceinline__ float ex2(float x) {
    float r;
    asm("ex2.approx.f32 %0, %1;" : "=f"(r) : "f"(x));
    return r;
}
__device__ __forceinline__ void ldm4(uint32_t* r, uint32_t addr) {
    asm volatile("ldmatrix.sync.aligned.m8n8.x4.shared.b16 {%0,%1,%2,%3}, [%4];"
                 : "=r"(r[0]), "=r"(r[1]), "=r"(r[2]), "=r"(r[3]) : "r"(addr));
}
__device__ __forceinline__ void ldm4t(uint32_t* r, uint32_t addr) {
    asm volatile("ldmatrix.sync.aligned.m8n8.x4.trans.shared.b16 {%0,%1,%2,%3}, [%4];"
                 : "=r"(r[0]), "=r"(r[1]), "=r"(r[2]), "=r"(r[3]) : "r"(addr));
}
__device__ __forceinline__ void mma16816(float* c, const uint32_t* a, uint32_t b0, uint32_t b1) {
    asm volatile("mma.sync.aligned.m16n8k16.row.col.f32.f16.f16.f32 "
                 "{%0,%1,%2,%3}, {%4,%5,%6,%7}, {%8,%9}, {%0,%1,%2,%3};"
                 : "+f"(c[0]), "+f"(c[1]), "+f"(c[2]), "+f"(c[3])
                 : "r"(a[0]), "r"(a[1]), "r"(a[2]), "r"(a[3]), "r"(b0), "r"(b1));
}
#define CP16(dst, src) \
    asm volatile("cp.async.cg.shared.global [%0], [%1], 16;" :: "r"(dst), "l"(src))
#define CP_COMMIT() asm volatile("cp.async.commit_group;" ::: "memory")
#define CP_WAIT0()  asm volatile("cp.async.wait_group 0;" ::: "memory")
#define CP_WAIT1()  asm volatile("cp.async.wait_group 1;" ::: "memory")

// ---------------------------------------------------------------------------
// Prep: x fp32 -> fp16 ; weights fp32 -> fp16
// ---------------------------------------------------------------------------
__global__ __launch_bounds__(256) void x16_kernel(const float* __restrict__ x) {
    size_t q = (size_t)blockIdx.x * 256 + threadIdx.x;
    float4 v = *(const float4*)(x + q * 4);
    uint2 u;
    u.x = packh2(__float2half_rn(v.x), __float2half_rn(v.y));
    u.y = packh2(__float2half_rn(v.z), __float2half_rn(v.w));
    *(uint2*)(g_x16 + q * 4) = u;
}

__global__ __launch_bounds__(256) void wprep_kernel(
    const float* __restrict__ W0, const float* __restrict__ W1,
    const float* __restrict__ W2, const float* __restrict__ W3) {
    int e = blockIdx.x * 256 + threadIdx.x;
    int m = blockIdx.y;
    const float* src = (m == 0) ? W0 : (m == 1) ? W1 : (m == 2) ? W2 : W3;
    g_whi[m * 65536 + e] = __float2half_rn(src[e]);
}

// ---------------------------------------------------------------------------
// HMMA projection: out[h,n] = (sum_c W[h,c] X16[c,n] + bias[h]) * scale
// CTA tile 128h x 128n, K chunks of 32, 3-stage cp.async ring, 1 sync/chunk.
// smem per buf: W[128 rows x 80B] + X[32 rows x 272B]
// DUAL=1: gridDim.z = 8, p = z>>2 selects (A,B) weight/bias/out/scale sets.
// ---------------------------------------------------------------------------
#define PJ_X     10240
#define PJ_BUF   18944
#define PJ_SMEM  56832

__device__ __forceinline__ void proj_issue(
    uint32_t sb, int buf, const __half* whi,
    const __half* X, int h0, int n0, int c0, int tid)
{
    uint32_t base = sb + buf * PJ_BUF;
    #pragma unroll
    for (int i = 0; i < 4; i++) {
        int idx = tid + i * 256;
        if (idx < 512) {
            int r = idx >> 4, c = idx & 15;
            CP16(base + PJ_X + r * 272 + c * 16, X + (size_t)(c0 + r) * Nn + n0 + c * 8);
        } else {
            int i2 = idx - 512;
            int r = i2 >> 2, c = i2 & 3;
            CP16(base + r * 80 + c * 16, whi + (size_t)(h0 + r) * Cn + c0 + c * 8);
        }
    }
}

// MODE 0 ("N"): out [b][h][n].  MODE 1 ("T"): out [b][n][h].
template <int MODE, int DUAL>
__global__ __launch_bounds__(256, 2) void proj16_kernel(
    const __half* __restrict__ whiA, const float* __restrict__ biasA,
    const __half* __restrict__ X, __half* __restrict__ outA, float scaleA,
    const __half* __restrict__ whiB, const float* __restrict__ biasB,
    __half* __restrict__ outB, float scaleB)
{
    extern __shared__ char smem[];
    const uint32_t sb = smem_u32(smem);
    const int tid = threadIdx.x;
    const int l = tid & 31;
    const int w = tid >> 5;
    const int g = l >> 2;
    const int t = l & 3;
    const int n0 = blockIdx.x * 128;
    const int h0 = blockIdx.y * 128;
    const int p  = DUAL ? (blockIdx.z >> 2) : 0;
    const int b  = DUAL ? (blockIdx.z & 3) : blockIdx.z;
    const __half* whi  = (DUAL && p) ? whiB  : whiA;
    const float*  bias = (DUAL && p) ? biasB : biasA;
    __half*       out  = (DUAL && p) ? outB  : outA;
    const float   scale= (DUAL && p) ? scaleB: scaleA;
    const __half* Xb = X + (size_t)b * Cn * Nn;

    float acc[16][4] = {};

    proj_issue(sb, 0, whi, Xb, h0, n0, 0, tid);
    CP_COMMIT();
    proj_issue(sb, 1, whi, Xb, h0, n0, 32, tid);
    CP_COMMIT();

    if (MODE == 0) {
        const int wh = (w & 3) * 32;
        const int wn = (w >> 2) * 64;
        const uint32_t aW = (uint32_t)((wh + (l & 15)) * 80 + (l >> 4) * 16);
        const uint32_t bX = (uint32_t)((((l >> 3) & 1) * 8 + (l & 7)) * 272 + (wn + (l >> 4) * 8) * 2);

        for (int ck = 0; ck < 8; ck++) {
            if (ck < 6) CP_WAIT1(); else CP_WAIT0();
            __syncthreads();
            if (ck <= 5) { proj_issue(sb, (ck + 2) % 3, whi, Xb, h0, n0, (ck + 2) * 32, tid);
                           CP_COMMIT(); }
            const uint32_t bb = sb + (ck % 3) * PJ_BUF;
            #pragma unroll
            for (int ks = 0; ks < 2; ks++) {
                uint32_t q[4][4];
                #pragma unroll
                for (int jj = 0; jj < 4; jj++)
                    ldm4t(q[jj], bb + PJ_X + bX + ks * 4352 + jj * 32);
                uint32_t a[2][4];
                ldm4(a[0], bb + aW + ks * 32);
                ldm4(a[1], bb + aW + 16 * 80 + ks * 32);
                #pragma unroll
                for (int mi = 0; mi < 2; mi++)
                    #pragma unroll
                    for (int jj = 0; jj < 4; jj++) {
                        mma16816(acc[mi * 8 + jj * 2],     a[mi], q[jj][0], q[jj][1]);
                        mma16816(acc[mi * 8 + jj * 2 + 1], a[mi], q[jj][2], q[jj][3]);
                    }
            }
        }
        #pragma unroll
        for (int mi = 0; mi < 2; mi++) {
            float bv0 = bias[h0 + wh + mi * 16 + g];
            float bv1 = bias[h0 + wh + mi * 16 + g + 8];
            #pragma unroll
            for (int j = 0; j < 8; j++) {
                int h = h0 + wh + mi * 16 + g;
                int n = n0 + wn + j * 8 + 2 * t;
                float* a = acc[mi * 8 + j];
                *(uint32_t*)(out + ((size_t)(b * Hn + h)) * Nn + n) =
                    packh2(__float2half_rn((a[0] + bv0) * scale), __float2half_rn((a[1] + bv0) * scale));
                *(uint32_t*)(out + ((size_t)(b * Hn + h + 8)) * Nn + n) =
                    packh2(__float2half_rn((a[2] + bv1) * scale), __float2half_rn((a[3] + bv1) * scale));
            }
        }
    } else {
        const int wn = (w & 1) * 64;
        const int wh = (w >> 1) * 32;
        const uint32_t aX = (uint32_t)(((l >> 4) * 8 + (l & 7)) * 272 + (wn + ((l >> 3) & 1) * 8) * 2);
        const uint32_t bW = (uint32_t)((wh + ((l >> 4) << 3) + (l & 7)) * 80 + ((l >> 3) & 1) * 16);

        for (int ck = 0; ck < 8; ck++) {
            if (ck < 6) CP_WAIT1(); else CP_WAIT0();
            __syncthreads();
            if (ck <= 5) { proj_issue(sb, (ck + 2) % 3, whi, Xb, h0, n0, (ck + 2) * 32, tid);
                           CP_COMMIT(); }
            const uint32_t bb = sb + (ck % 3) * PJ_BUF;
            #pragma unroll
            for (int ks = 0; ks < 2; ks++) {
                uint32_t a[4][4];
                #pragma unroll
                for (int mi = 0; mi < 4; mi++)
                    ldm4t(a[mi], bb + PJ_X + aX + ks * 4352 + mi * 32);
                #pragma unroll
                for (int jj = 0; jj < 2; jj++) {
                    uint32_t qq[4];
                    ldm4(qq, bb + bW + jj * 1280 + ks * 32);
                    #pragma unroll
                    for (int mi = 0; mi < 4; mi++) {
                        mma16816(acc[mi * 4 + jj * 2],     a[mi], qq[0], qq[1]);
                        mma16816(acc[mi * 4 + jj * 2 + 1], a[mi], qq[2], qq[3]);
                    }
                }
            }
        }
        float bvj[4][2];
        #pragma unroll
        for (int j = 0; j < 4; j++) {
            bvj[j][0] = bias[h0 + wh + j * 8 + 2 * t];
            bvj[j][1] = bias[h0 + wh + j * 8 + 2 * t + 1];
        }
        #pragma unroll
        for (int mi = 0; mi < 4; mi++) {
            int nr = n0 + wn + mi * 16 + g;
            #pragma unroll
            for (int j = 0; j < 4; j++) {
                float* a = acc[mi * 4 + j];
                int hc = h0 + wh + j * 8 + 2 * t;
                *(uint32_t*)(out + ((size_t)(b * Nn + nr)) * Hn + hc) =
                    packh2(__float2half_rn((a[0] + bvj[j][0]) * scale), __float2half_rn((a[1] + bvj[j][1]) * scale));
                *(uint32_t*)(out + ((size_t)(b * Nn + nr + 8)) * Hn + hc) =
                    packh2(__float2half_rn((a[2] + bvj[j][0]) * scale), __float2half_rn((a[3] + bvj[j][1]) * scale));
            }
        }
    }
}

// ---------------------------------------------------------------------------
// Grouped conv1d fp16 (groups=32, kw=3, SAME) + bias + ReLU: g_v1h -> g_v2h
// ---------------------------------------------------------------------------
__global__ __launch_bounds__(256) void gconv16_kernel(
    const float* __restrict__ W2, const float* __restrict__ b2)
{
    __shared__ __half xs[8][536];
    __shared__ float ws[192];
    __shared__ float bs[8];

    const int tid = threadIdx.x;
    const int n0 = blockIdx.x * 512;
    const int gr = blockIdx.y;
    const int b  = blockIdx.z;

    if (tid < 192) ws[tid] = W2[gr * 192 + tid];
    if (tid < 8)   bs[tid] = b2[gr * 8 + tid];

    const __half* in = g_v1h + ((size_t)b * Hn + gr * 8) * Nn;
    for (int idx = tid; idx < 8 * 66; idx += 256) {
        int r = idx / 66, c = idx % 66;
        int gn = n0 - 8 + c * 8;
        if (gn >= 0 && gn + 8 <= Nn) {
            *(uint4*)&xs[r][c * 8] = *(const uint4*)(in + (size_t)r * Nn + gn);
        } else {
            #pragma unroll
            for (int j = 0; j < 8; j++) {
                int n = gn + j;
                xs[r][c * 8 + j] = (n >= 0 && n < Nn) ? in[(size_t)r * Nn + n] : __half(0.f);
            }
        }
    }
    __syncthreads();

    __half* ob = g_v2h + ((size_t)b * Hn + gr * 8) * Nn + n0;
    #pragma unroll
    for (int k = 0; k < 2; k++) {
        int n = tid + k * 256;
        float xm[8], x0[8], xp[8];
        #pragma unroll
        for (int i = 0; i < 8; i++) {
            xm[i] = __half2float(xs[i][8 + n - 1]);
            x0[i] = __half2float(xs[i][8 + n]);
            xp[i] = __half2float(xs[i][8 + n + 1]);
        }
        #pragma unroll
        for (int h = 0; h < 8; h++) {
            float acc = bs[h];
            #pragma unroll
            for (int i = 0; i < 8; i++) {
                acc = fmaf(ws[h * 24 + i * 3 + 0], xm[i], acc);
                acc = fmaf(ws[h * 24 + i * 3 + 1], x0[i], acc);
                acc = fmaf(ws[h * 24 + i * 3 + 2], xp[i], acc);
            }
            ob[(size_t)h * Nn + n] = __float2half_rn(fmaxf(acc, 0.f));
        }
    }
}

// ---------------------------------------------------------------------------
// Fused HMMA attention, software-pipelined, Q fragments in registers.
// q is pre-scaled by log2e, so E = 2^(l' - 4*log2e) = e^(l-4).
// ---------------------------------------------------------------------------
#define OFF_Q   0
#define OFF_K   33792
#define OFF_V   101376
#define OFF_E   175104
#define OFF_CS  193536
#define AT_SMEM 194048
#define KBUF    33792
#define VBUF    36864
#define EBUF    9216
#define EXP_BIAS 5.7707802f   /* 4 * log2(e) */

__device__ __forceinline__ void issue_k(uint32_t sb, int buf, const __half* kb, int n0, int tid) {
    uint32_t kd = sb + OFF_K + buf * KBUF;
    #pragma unroll
    for (int i = 0; i < 8; i++) {
        int ch = tid + i * 256;
        int r = ch >> 5, c = ch & 31;
        CP16(kd + r * 528 + c * 16, kb + (size_t)(n0 + r) * Hn + c * 8);
    }
}
__device__ __forceinline__ void issue_v(uint32_t sb, int buf, const __half* vb, int n0, int tid) {
    uint32_t vd = sb + OFF_V + buf * VBUF;
    #pragma unroll
    for (int i = 0; i < 8; i++) {
        int ch = tid + i * 256;
        int r = ch >> 3, c = ch & 7;
        CP16(vd + r * 144 + c * 16, vb + (size_t)r * Nn + n0 + c * 8);
    }
}

#define GEMM1_BODY(kbase) do {                                              \
    _Pragma("unroll")                                                       \
    for (int ks = 0; ks < 16; ks++) {                                       \
        uint32_t p[4], q[4];                                                \
        ldm4(p, (kbase) + bKoff + ks * 32);                                 \
        ldm4(q, (kbase) + bKoff + 16 * 528 + ks * 32);                      \
        mma16816(acc1[0], qf[ks], p[0], p[1]);                              \
        mma16816(acc1[1], qf[ks], p[2], p[3]);                              \
        mma16816(acc1[2], qf[ks], q[0], q[1]);                              \
        mma16816(acc1[3], qf[ks], q[2], q[3]);                              \
    } } while (0)

#define EPI_BODY(ebase) do {                                                \
    _Pragma("unroll")                                                       \
    for (int nt = 0; nt < 4; nt++) {                                        \
        float e00 = ex2(acc1[nt][0] - EXP_BIAS);                            \
        float e01 = ex2(acc1[nt][1] - EXP_BIAS);                            \
        float e10 = ex2(acc1[nt][2] - EXP_BIAS);                            \
        float e11 = ex2(acc1[nt][3] - EXP_BIAS);                            \
        cs0 += e00 + e01;                                                   \
        cs1 += e10 + e11;                                                   \
        const uint32_t colb = (uint32_t)((wn + nt * 8 + 2 * t) * 2);        \
        *(uint32_t*)(smem + (ebase) + er0 + colb) =                         \
            packh2(__float2half_rn(e00), __float2half_rn(e01));             \
        *(uint32_t*)(smem + (ebase) + er1 + colb) =                         \
            packh2(__float2half_rn(e10), __float2half_rn(e11));             \
    } } while (0)

#define GEMM2_BODY(ebase, vbase) do {                                       \
    _Pragma("unroll")                                                       \
    for (int ks = 0; ks < 4; ks++) {                                        \
        uint32_t ah0[4], ah1[4];                                            \
        ldm4(ah0, (ebase) + aEoff + ks * 32);                               \
        ldm4(ah1, (ebase) + aEoff + 16 * 144 + ks * 32);                    \
        _Pragma("unroll")                                                   \
        for (int j = 0; j < 4; j++) {                                       \
            uint32_t bb[4];                                                 \
            ldm4(bb, (vbase) + bVoff + j * (16 * 144) + ks * 32);           \
            mma16816(acc2[0 + j * 2 + 0], ah0, bb[0], bb[1]);               \
            mma16816(acc2[0 + j * 2 + 1], ah0, bb[2], bb[3]);               \
            mma16816(acc2[8 + j * 2 + 0], ah1, bb[0], bb[1]);               \
            mma16816(acc2[8 + j * 2 + 1], ah1, bb[2], bb[3]);               \
        }                                                                   \
    } } while (0)

__global__ __launch_bounds__(256, 1)
void attn_kernel(const __half* __restrict__ qt, const __half* __restrict__ kt,
                 const __half* __restrict__ vh, float* __restrict__ out)
{
    extern __shared__ char smem[];
    const int tid  = threadIdx.x;
    const int l    = tid & 31;
    const int w    = tid >> 5;
    const int m0 = blockIdx.x * 64;
    const int b  = blockIdx.y;
    const uint32_t sb = smem_u32(smem);
    const int g = l >> 2;
    const int t = l & 3;

    const int wm  = (w >> 1) * 16;   // GEMM1: warp 16m x 32n
    const int wn  = (w & 1) * 32;
    const int wm2 = (w & 1) * 32;    // GEMM2: warp 32m x 64o
    const int wo2 = (w >> 1) * 64;

    const __half* kb = kt + (size_t)b * Nn * Hn;
    const __half* vb = vh + (size_t)b * On * Nn;

    // prologue: stage Q [64 m][256 h] to smem
    #pragma unroll
    for (int i = 0; i < 8; i++) {
        int ch = tid + i * 256;
        int r = ch >> 5, c = ch & 31;
        *(float4*)(smem + OFF_Q + r * 528 + c * 16) =
            *(const float4*)(qt + ((size_t)(b * Nn + m0 + r)) * Hn + c * 8);
    }
    issue_k(sb, 0, kb, 0, tid);
    issue_v(sb, 0, vb, 0, tid);
    CP_COMMIT();
    issue_k(sb, 1, kb, 64, tid);
    CP_COMMIT();

    const uint32_t aQ    = sb + OFF_Q + (uint32_t)((wm + (l & 15)) * 528 + (l >> 4) * 16);
    const uint32_t bKoff = (uint32_t)((wn + ((l >> 4) << 3) + (l & 7)) * 528 + ((l >> 3) & 1) * 16);
    const uint32_t bVoff = (uint32_t)((wo2 + ((l >> 4) << 3) + (l & 7)) * 144 + ((l >> 3) & 1) * 16);
    const uint32_t aEoff = (uint32_t)((wm2 + (l & 15)) * 144 + (l >> 4) * 16);
    const uint32_t er0   = (uint32_t)((wm + g) * 144);
    const uint32_t er1   = (uint32_t)((wm + g + 8) * 144);

    float acc2[16][4] = {};
    float cs0 = 0.f, cs1 = 0.f;
    float acc1[4][4];

    // ---- pipeline prologue ----
    CP_WAIT0();
    __syncthreads();

    uint32_t qf[16][4];
    #pragma unroll
    for (int ks = 0; ks < 16; ks++) ldm4(qf[ks], aQ + ks * 32);

    #pragma unroll
    for (int i = 0; i < 4; i++)
        #pragma unroll
        for (int j = 0; j < 4; j++) acc1[i][j] = 0.f;
    GEMM1_BODY(sb + OFF_K + 0 * KBUF);
    EPI_BODY(OFF_E + 0 * EBUF);
    __syncthreads();

    // ---- main loop: it = 0..62 ----
    for (int it = 0; it < 63; it++) {
        issue_v(sb, (it + 1) & 1, vb, (it + 1) * 64, tid);
        if (it + 2 < 64) issue_k(sb, it & 1, kb, (it + 2) * 64, tid);
        CP_COMMIT();

        GEMM2_BODY(sb + OFF_E + (it & 1) * EBUF, sb + OFF_V + (it & 1) * VBUF);
        #pragma unroll
        for (int i = 0; i < 4; i++)
            #pragma unroll
            for (int j = 0; j < 4; j++) acc1[i][j] = 0.f;
        GEMM1_BODY(sb + OFF_K + ((it + 1) & 1) * KBUF);

        EPI_BODY(OFF_E + ((it + 1) & 1) * EBUF);

        CP_WAIT0();
        __syncthreads();
    }

    // ---- tail ----
    GEMM2_BODY(sb + OFF_E + 1 * EBUF, sb + OFF_V + 1 * VBUF);

    // ---- colsum reduce ----
    cs0 += __shfl_xor_sync(0xFFFFFFFFu, cs0, 1);
    cs0 += __shfl_xor_sync(0xFFFFFFFFu, cs0, 2);
    cs1 += __shfl_xor_sync(0xFFFFFFFFu, cs1, 1);
    cs1 += __shfl_xor_sync(0xFFFFFFFFu, cs1, 2);
    float* CS = (float*)(smem + OFF_CS);   // [2][64]
    if (t == 0) {
        CS[(w & 1) * 64 + wm + g]     = cs0;
        CS[(w & 1) * 64 + wm + g + 8] = cs1;
    }
    __syncthreads();

    float inv[2][2];
    #pragma unroll
    for (int mi = 0; mi < 2; mi++) {
        int r0 = wm2 + mi * 16 + g;
        inv[mi][0] = 1.f / (CS[r0] + CS[64 + r0]);
        inv[mi][1] = 1.f / (CS[r0 + 8] + CS[64 + r0 + 8]);
    }

    #pragma unroll
    for (int mi = 0; mi < 2; mi++) {
        const int mrow0 = wm2 + mi * 16 + g;
        #pragma unroll
        for (int jt = 0; jt < 8; jt++) {
            const int o = wo2 + jt * 8 + 2 * t;
            const float* a = acc2[mi * 8 + jt];
            float* p0 = out + ((size_t)(b * On + o)) * Nn + m0;
            float* p1 = p0 + Nn;
            p0[mrow0]     = a[0] * inv[mi][0];
            p1[mrow0]     = a[1] * inv[mi][0];
            p0[mrow0 + 8] = a[2] * inv[mi][1];
            p1[mrow0 + 8] = a[3] * inv[mi][1];
        }
    }
}

// ---------------------------------------------------------------------------
extern "C" void kernel_launch(void* const* d_in, const int* in_sizes, int n_in,
                              void* d_out, int out_size)
{
    const float* x  = (const float*)d_in[0];
    const float* Wk = (const float*)d_in[1];
    const float* bk = (const float*)d_in[2];
    const float* Wq = (const float*)d_in[3];
    const float* bq = (const float*)d_in[4];
    const float* W1 = (const float*)d_in[5];
    const float* b1 = (const float*)d_in[6];
    const float* W2 = (const float*)d_in[7];
    const float* b2 = (const float*)d_in[8];
    const float* W3 = (const float*)d_in[9];
    const float* b3 = (const float*)d_in[10];
    float* out = (float*)d_out;

    __half *x16, *whi, *ktp, *qtp, *v1h, *v2h, *vhp;
    cudaGetSymbolAddress((void**)&x16, g_x16);
    cudaGetSymbolAddress((void**)&whi, g_whi);
    cudaGetSymbolAddress((void**)&ktp, g_kt);
    cudaGetSymbolAddress((void**)&qtp, g_qt);
    cudaGetSymbolAddress((void**)&v1h, g_v1h);
    cudaGetSymbolAddress((void**)&v2h, g_v2h);
    cudaGetSymbolAddress((void**)&vhp, g_vh);

    cudaFuncSetAttribute(proj16_kernel<0,0>, cudaFuncAttributeMaxDynamicSharedMemorySize, PJ_SMEM);
    cudaFuncSetAttribute(proj16_kernel<1,1>, cudaFuncAttributeMaxDynamicSharedMemorySize, PJ_SMEM);
    cudaFuncSetAttribute(attn_kernel, cudaFuncAttributeMaxDynamicSharedMemorySize, AT_SMEM);

    x16_kernel<<<4096, 256>>>(x);
    wprep_kernel<<<dim3(256, 4), 256>>>(Wk, Wq, W1, W3);

    const float LOG2E = 1.4426950408889634f;
    // merged k + q projection (gridDim.z = 8: z>>2 selects k vs q)
    proj16_kernel<1,1><<<dim3(Nn / 128, Hn / 128, 2 * Bn), 256, PJ_SMEM>>>(
        whi + 0 * 65536, bk, x16, ktp, 1.0f,
        whi + 1 * 65536, bq, qtp, LOG2E);
    proj16_kernel<0,0><<<dim3(Nn / 128, Hn / 128, Bn), 256, PJ_SMEM>>>(
        whi + 2 * 65536, b1, x16, v1h, 1.0f,
        nullptr, nullptr, nullptr, 0.f);
    gconv16_kernel<<<dim3(Nn / 512, 32, Bn), 256>>>(W2, b2);
    proj16_kernel<0,0><<<dim3(Nn / 128, Hn / 128, Bn), 256, PJ_SMEM>>>(
        whi + 3 * 65536, b3, v2h, vhp, 1.0f,
        nullptr, nullptr, nullptr, 0.f);
    attn_kernel<<<dim3(Nn / 64, Bn), 256, AT_SMEM>>>(qtp, ktp, vhp, out);
}

// round 11
// speedup vs baseline: 8.8016x; 1.1177x over previous
#include <cuda_runtime.h>
#include <cuda_fp16.h>
#include <cstdint>

#define Bn 4
#define Cn 256
#define Hn 256
#define On 256
#define Nn 4096

// ---------------- scratch (device globals) ----------------------------------
__device__ __half g_x16[(size_t)Bn*Cn*Nn];   // x fp16 [b][c][n]
__device__ __half g_whi[4 * Cn * Hn];        // W fp16 (Wk,Wq,W1,W3)
__device__ __half g_kt [(size_t)Bn*Nn*Hn];   // k^T [b][n][h]
__device__ __half g_qt [(size_t)Bn*Nn*Hn];   // q^T [b][n][h] (scaled by log2e)
__device__ __half g_v1h[(size_t)Bn*Hn*Nn];   // v1 [b][h][n]
__device__ __half g_v2h[(size_t)Bn*Hn*Nn];   // v2 [b][h][n]
__device__ __half g_vh [(size_t)Bn*On*Nn];   // v  [b][o][n]

// ---------------- helpers ----------------------------------------------------
__device__ __forceinline__ uint32_t smem_u32(const void* p) {
    uint32_t a;
    asm("{ .reg .u64 t; cvta.to.shared.u64 t, %1; cvt.u32.u64 %0, t; }" : "=r"(a) : "l"(p));
    return a;
}
__device__ __forceinline__ uint32_t packh2(__half a, __half b) {
    __half2 h = __halves2half2(a, b);
    return *reinterpret_cast<const uint32_t*>(&h);
}
__device__ __forceinline__ float ex2(float x) {
    float r;
    asm("ex2.approx.f32 %0, %1;" : "=f"(r) : "f"(x));
    return r;
}
__device__ __forceinline__ void ldm4(uint32_t* r, uint32_t addr) {
    asm volatile("ldmatrix.sync.aligned.m8n8.x4.shared.b16 {%0,%1,%2,%3}, [%4];"
                 : "=r"(r[0]), "=r"(r[1]), "=r"(r[2]), "=r"(r[3]) : "r"(addr));
}
__device__ __forceinline__ void ldm4t(uint32_t* r, uint32_t addr) {
    asm volatile("ldmatrix.sync.aligned.m8n8.x4.trans.shared.b16 {%0,%1,%2,%3}, [%4];"
                 : "=r"(r[0]), "=r"(r[1]), "=r"(r[2]), "=r"(r[3]) : "r"(addr));
}
__device__ __forceinline__ void mma16816(float* c, const uint32_t* a, uint32_t b0, uint32_t b1) {
    asm volatile("mma.sync.aligned.m16n8k16.row.col.f32.f16.f16.f32 "
                 "{%0,%1,%2,%3}, {%4,%5,%6,%7}, {%8,%9}, {%0,%1,%2,%3};"
                 : "+f"(c[0]), "+f"(c[1]), "+f"(c[2]), "+f"(c[3])
                 : "r"(a[0]), "r"(a[1]), "r"(a[2]), "r"(a[3]), "r"(b0), "r"(b1));
}
#define CP16(dst, src) \
    asm volatile("cp.async.cg.shared.global [%0], [%1], 16;" :: "r"(dst), "l"(src))
#define CP_COMMIT() asm volatile("cp.async.commit_group;" ::: "memory")
#define CP_WAIT0()  asm volatile("cp.async.wait_group 0;" ::: "memory")
#define CP_WAIT1()  asm volatile("cp.async.wait_group 1;" ::: "memory")
#define CP_WAIT2()  asm volatile("cp.async.wait_group 2;" ::: "memory")

// ---------------------------------------------------------------------------
// Prep: x fp32 -> fp16 ; weights fp32 -> fp16
// ---------------------------------------------------------------------------
__global__ __launch_bounds__(256) void x16_kernel(const float* __restrict__ x) {
    size_t q = (size_t)blockIdx.x * 256 + threadIdx.x;
    float4 v = *(const float4*)(x + q * 4);
    uint2 u;
    u.x = packh2(__float2half_rn(v.x), __float2half_rn(v.y));
    u.y = packh2(__float2half_rn(v.z), __float2half_rn(v.w));
    *(uint2*)(g_x16 + q * 4) = u;
}

__global__ __launch_bounds__(256) void wprep_kernel(
    const float* __restrict__ W0, const float* __restrict__ W1,
    const float* __restrict__ W2, const float* __restrict__ W3) {
    int e = blockIdx.x * 256 + threadIdx.x;
    int m = blockIdx.y;
    const float* src = (m == 0) ? W0 : (m == 1) ? W1 : (m == 2) ? W2 : W3;
    g_whi[m * 65536 + e] = __float2half_rn(src[e]);
}

// ---------------------------------------------------------------------------
// HMMA projection (unchanged from R9)
// ---------------------------------------------------------------------------
#define PJ_X     10240
#define PJ_BUF   18944
#define PJ_SMEM  56832

__device__ __forceinline__ void proj_issue(
    uint32_t sb, int buf, const __half* whi,
    const __half* X, int h0, int n0, int c0, int tid)
{
    uint32_t base = sb + buf * PJ_BUF;
    #pragma unroll
    for (int i = 0; i < 4; i++) {
        int idx = tid + i * 256;
        if (idx < 512) {
            int r = idx >> 4, c = idx & 15;
            CP16(base + PJ_X + r * 272 + c * 16, X + (size_t)(c0 + r) * Nn + n0 + c * 8);
        } else {
            int i2 = idx - 512;
            int r = i2 >> 2, c = i2 & 3;
            CP16(base + r * 80 + c * 16, whi + (size_t)(h0 + r) * Cn + c0 + c * 8);
        }
    }
}

template <int MODE, int DUAL>
__global__ __launch_bounds__(256, 2) void proj16_kernel(
    const __half* __restrict__ whiA, const float* __restrict__ biasA,
    const __half* __restrict__ X, __half* __restrict__ outA, float scaleA,
    const __half* __restrict__ whiB, const float* __restrict__ biasB,
    __half* __restrict__ outB, float scaleB)
{
    extern __shared__ char smem[];
    const uint32_t sb = smem_u32(smem);
    const int tid = threadIdx.x;
    const int l = tid & 31;
    const int w = tid >> 5;
    const int g = l >> 2;
    const int t = l & 3;
    const int n0 = blockIdx.x * 128;
    const int h0 = blockIdx.y * 128;
    const int p  = DUAL ? (blockIdx.z >> 2) : 0;
    const int b  = DUAL ? (blockIdx.z & 3) : blockIdx.z;
    const __half* whi  = (DUAL && p) ? whiB  : whiA;
    const float*  bias = (DUAL && p) ? biasB : biasA;
    __half*       out  = (DUAL && p) ? outB  : outA;
    const float   scale= (DUAL && p) ? scaleB: scaleA;
    const __half* Xb = X + (size_t)b * Cn * Nn;

    float acc[16][4] = {};

    proj_issue(sb, 0, whi, Xb, h0, n0, 0, tid);
    CP_COMMIT();
    proj_issue(sb, 1, whi, Xb, h0, n0, 32, tid);
    CP_COMMIT();

    if (MODE == 0) {
        const int wh = (w & 3) * 32;
        const int wn = (w >> 2) * 64;
        const uint32_t aW = (uint32_t)((wh + (l & 15)) * 80 + (l >> 4) * 16);
        const uint32_t bX = (uint32_t)((((l >> 3) & 1) * 8 + (l & 7)) * 272 + (wn + (l >> 4) * 8) * 2);

        for (int ck = 0; ck < 8; ck++) {
            if (ck < 6) CP_WAIT1(); else CP_WAIT0();
            __syncthreads();
            if (ck <= 5) { proj_issue(sb, (ck + 2) % 3, whi, Xb, h0, n0, (ck + 2) * 32, tid);
                           CP_COMMIT(); }
            const uint32_t bb = sb + (ck % 3) * PJ_BUF;
            #pragma unroll
            for (int ks = 0; ks < 2; ks++) {
                uint32_t q[4][4];
                #pragma unroll
                for (int jj = 0; jj < 4; jj++)
                    ldm4t(q[jj], bb + PJ_X + bX + ks * 4352 + jj * 32);
                uint32_t a[2][4];
                ldm4(a[0], bb + aW + ks * 32);
                ldm4(a[1], bb + aW + 16 * 80 + ks * 32);
                #pragma unroll
                for (int mi = 0; mi < 2; mi++)
                    #pragma unroll
                    for (int jj = 0; jj < 4; jj++) {
                        mma16816(acc[mi * 8 + jj * 2],     a[mi], q[jj][0], q[jj][1]);
                        mma16816(acc[mi * 8 + jj * 2 + 1], a[mi], q[jj][2], q[jj][3]);
                    }
            }
        }
        #pragma unroll
        for (int mi = 0; mi < 2; mi++) {
            float bv0 = bias[h0 + wh + mi * 16 + g];
            float bv1 = bias[h0 + wh + mi * 16 + g + 8];
            #pragma unroll
            for (int j = 0; j < 8; j++) {
                int h = h0 + wh + mi * 16 + g;
                int n = n0 + wn + j * 8 + 2 * t;
                float* a = acc[mi * 8 + j];
                *(uint32_t*)(out + ((size_t)(b * Hn + h)) * Nn + n) =
                    packh2(__float2half_rn((a[0] + bv0) * scale), __float2half_rn((a[1] + bv0) * scale));
                *(uint32_t*)(out + ((size_t)(b * Hn + h + 8)) * Nn + n) =
                    packh2(__float2half_rn((a[2] + bv1) * scale), __float2half_rn((a[3] + bv1) * scale));
            }
        }
    } else {
        const int wn = (w & 1) * 64;
        const int wh = (w >> 1) * 32;
        const uint32_t aX = (uint32_t)(((l >> 4) * 8 + (l & 7)) * 272 + (wn + ((l >> 3) & 1) * 8) * 2);
        const uint32_t bW = (uint32_t)((wh + ((l >> 4) << 3) + (l & 7)) * 80 + ((l >> 3) & 1) * 16);

        for (int ck = 0; ck < 8; ck++) {
            if (ck < 6) CP_WAIT1(); else CP_WAIT0();
            __syncthreads();
            if (ck <= 5) { proj_issue(sb, (ck + 2) % 3, whi, Xb, h0, n0, (ck + 2) * 32, tid);
                           CP_COMMIT(); }
            const uint32_t bb = sb + (ck % 3) * PJ_BUF;
            #pragma unroll
            for (int ks = 0; ks < 2; ks++) {
                uint32_t a[4][4];
                #pragma unroll
                for (int mi = 0; mi < 4; mi++)
                    ldm4t(a[mi], bb + PJ_X + aX + ks * 4352 + mi * 32);
                #pragma unroll
                for (int jj = 0; jj < 2; jj++) {
                    uint32_t qq[4];
                    ldm4(qq, bb + bW + jj * 1280 + ks * 32);
                    #pragma unroll
                    for (int mi = 0; mi < 4; mi++) {
                        mma16816(acc[mi * 4 + jj * 2],     a[mi], qq[0], qq[1]);
                        mma16816(acc[mi * 4 + jj * 2 + 1], a[mi], qq[2], qq[3]);
                    }
                }
            }
        }
        float bvj[4][2];
        #pragma unroll
        for (int j = 0; j < 4; j++) {
            bvj[j][0] = bias[h0 + wh + j * 8 + 2 * t];
            bvj[j][1] = bias[h0 + wh + j * 8 + 2 * t + 1];
        }
        #pragma unroll
        for (int mi = 0; mi < 4; mi++) {
            int nr = n0 + wn + mi * 16 + g;
            #pragma unroll
            for (int j = 0; j < 4; j++) {
                float* a = acc[mi * 4 + j];
                int hc = h0 + wh + j * 8 + 2 * t;
                *(uint32_t*)(out + ((size_t)(b * Nn + nr)) * Hn + hc) =
                    packh2(__float2half_rn((a[0] + bvj[j][0]) * scale), __float2half_rn((a[1] + bvj[j][1]) * scale));
                *(uint32_t*)(out + ((size_t)(b * Nn + nr + 8)) * Hn + hc) =
                    packh2(__float2half_rn((a[2] + bvj[j][0]) * scale), __float2half_rn((a[3] + bvj[j][1]) * scale));
            }
        }
    }
}

// ---------------------------------------------------------------------------
// Grouped conv1d fp16 (unchanged)
// ---------------------------------------------------------------------------
__global__ __launch_bounds__(256) void gconv16_kernel(
    const float* __restrict__ W2, const float* __restrict__ b2)
{
    __shared__ __half xs[8][536];
    __shared__ float ws[192];
    __shared__ float bs[8];

    const int tid = threadIdx.x;
    const int n0 = blockIdx.x * 512;
    const int gr = blockIdx.y;
    const int b  = blockIdx.z;

    if (tid < 192) ws[tid] = W2[gr * 192 + tid];
    if (tid < 8)   bs[tid] = b2[gr * 8 + tid];

    const __half* in = g_v1h + ((size_t)b * Hn + gr * 8) * Nn;
    for (int idx = tid; idx < 8 * 66; idx += 256) {
        int r = idx / 66, c = idx % 66;
        int gn = n0 - 8 + c * 8;
        if (gn >= 0 && gn + 8 <= Nn) {
            *(uint4*)&xs[r][c * 8] = *(const uint4*)(in + (size_t)r * Nn + gn);
        } else {
            #pragma unroll
            for (int j = 0; j < 8; j++) {
                int n = gn + j;
                xs[r][c * 8 + j] = (n >= 0 && n < Nn) ? in[(size_t)r * Nn + n] : __half(0.f);
            }
        }
    }
    __syncthreads();

    __half* ob = g_v2h + ((size_t)b * Hn + gr * 8) * Nn + n0;
    #pragma unroll
    for (int k = 0; k < 2; k++) {
        int n = tid + k * 256;
        float xm[8], x0[8], xp[8];
        #pragma unroll
        for (int i = 0; i < 8; i++) {
            xm[i] = __half2float(xs[i][8 + n - 1]);
            x0[i] = __half2float(xs[i][8 + n]);
            xp[i] = __half2float(xs[i][8 + n + 1]);
        }
        #pragma unroll
        for (int h = 0; h < 8; h++) {
            float acc = bs[h];
            #pragma unroll
            for (int i = 0; i < 8; i++) {
                acc = fmaf(ws[h * 24 + i * 3 + 0], xm[i], acc);
                acc = fmaf(ws[h * 24 + i * 3 + 1], x0[i], acc);
                acc = fmaf(ws[h * 24 + i * 3 + 2], xp[i], acc);
            }
            ob[(size_t)h * Nn + n] = __float2half_rn(fmaxf(acc, 0.f));
        }
    }
}

// ---------------------------------------------------------------------------
// Fused HMMA attention, m-tile 128, grid = 128 CTAs (1 wave).
//   GEMM1 warp tile 32m x 32n (Q from smem); GEMM2 warp tile 64m x 64o.
//   E single-buffered; K/V cp.async double-buffered (distance 1).
// ---------------------------------------------------------------------------
#define OFF_Q   0
#define OFF_K   67584
#define OFF_V   135168
#define OFF_E   208896
#define OFF_CS  227328
#define AT_SMEM 228352
#define KBUF    33792
#define VBUF    36864
#define EXP_BIAS 5.7707802f   /* 4 * log2(e) */

__device__ __forceinline__ void issue_k(uint32_t sb, int buf, const __half* kb, int n0, int tid) {
    uint32_t kd = sb + OFF_K + buf * KBUF;
    #pragma unroll
    for (int i = 0; i < 8; i++) {
        int ch = tid + i * 256;
        int r = ch >> 5, c = ch & 31;
        CP16(kd + r * 528 + c * 16, kb + (size_t)(n0 + r) * Hn + c * 8);
    }
}
__device__ __forceinline__ void issue_v(uint32_t sb, int buf, const __half* vb, int n0, int tid) {
    uint32_t vd = sb + OFF_V + buf * VBUF;
    #pragma unroll
    for (int i = 0; i < 8; i++) {
        int ch = tid + i * 256;
        int r = ch >> 3, c = ch & 7;
        CP16(vd + r * 144 + c * 16, vb + (size_t)r * Nn + n0 + c * 8);
    }
}

__global__ __launch_bounds__(256, 1)
void attn_kernel(const __half* __restrict__ qt, const __half* __restrict__ kt,
                 const __half* __restrict__ vh, float* __restrict__ out)
{
    extern __shared__ char smem[];
    const int tid  = threadIdx.x;
    const int l    = tid & 31;
    const int w    = tid >> 5;
    const int m0 = blockIdx.x * 128;
    const int b  = blockIdx.y;
    const uint32_t sb = smem_u32(smem);
    const int g = l >> 2;
    const int t = l & 3;

    const int wm1 = (w >> 1) * 32;   // GEMM1: warp 32m x 32n
    const int wn1 = (w & 1) * 32;
    const int wm2 = (w & 1) * 64;    // GEMM2: warp 64m x 64o
    const int wo2 = (w >> 1) * 64;

    const __half* kb = kt + (size_t)b * Nn * Hn;
    const __half* vb = vh + (size_t)b * On * Nn;

    // prologue: stage Q [128 m][256 h] to smem (rows 528B)
    #pragma unroll
    for (int i = 0; i < 16; i++) {
        int ch = tid + i * 256;
        int r = ch >> 5, c = ch & 31;
        *(float4*)(smem + OFF_Q + r * 528 + c * 16) =
            *(const float4*)(qt + ((size_t)(b * Nn + m0 + r)) * Hn + c * 8);
    }
    issue_k(sb, 0, kb, 0, tid);
    CP_COMMIT();
    issue_v(sb, 0, vb, 0, tid);
    CP_COMMIT();

    // ldmatrix addresses
    const uint32_t aQ    = sb + OFF_Q + (uint32_t)((wm1 + (l & 15)) * 528 + (l >> 4) * 16);
    const uint32_t bKoff = (uint32_t)((wn1 + ((l >> 4) << 3) + (l & 7)) * 528 + ((l >> 3) & 1) * 16);
    const uint32_t aE    = sb + OFF_E + (uint32_t)((wm2 + (l & 15)) * 144 + (l >> 4) * 16);
    const uint32_t bVoff = (uint32_t)((wo2 + ((l >> 4) << 3) + (l & 7)) * 144 + ((l >> 3) & 1) * 16);
    const uint32_t er0   = (uint32_t)((wm1 + g) * 144);

    float acc2[32][4] = {};          // [mt4*8 + ot8][4]
    float cs[2][2] = {};             // [mt][rowhalf]

    for (int it = 0; it < 64; it++) {
        __syncthreads();             // GEMM2(it-1) reads complete everywhere
        if (it + 1 < 64) issue_v(sb, (it + 1) & 1, vb, (it + 1) * 64, tid);
        CP_COMMIT();
        if (it + 1 < 64) issue_k(sb, (it + 1) & 1, kb, (it + 1) * 64, tid);
        CP_COMMIT();
        CP_WAIT2();                  // K(it), V(it) landed
        __syncthreads();

        // ---- GEMM1: D1[32m x 32n] per warp over K=256 ----
        const uint32_t kbuf = sb + OFF_K + (it & 1) * KBUF;
        float acc1[8][4] = {};       // [mt*4 + nt][4]
        #pragma unroll
        for (int ks = 0; ks < 16; ks++) {
            uint32_t a0[4], a1[4], p[4], q[4];
            ldm4(a0, aQ + ks * 32);
            ldm4(a1, aQ + 16 * 528 + ks * 32);
            ldm4(p, kbuf + bKoff + ks * 32);
            ldm4(q, kbuf + bKoff + 16 * 528 + ks * 32);
            mma16816(acc1[0], a0, p[0], p[1]);
            mma16816(acc1[1], a0, p[2], p[3]);
            mma16816(acc1[2], a0, q[0], q[1]);
            mma16816(acc1[3], a0, q[2], q[3]);
            mma16816(acc1[4], a1, p[0], p[1]);
            mma16816(acc1[5], a1, p[2], p[3]);
            mma16816(acc1[6], a1, q[0], q[1]);
            mma16816(acc1[7], a1, q[2], q[3]);
        }

        // ---- epilogue: exp, colsum, E -> smem ----
        #pragma unroll
        for (int mt = 0; mt < 2; mt++) {
            const uint32_t erA = er0 + (uint32_t)(mt * 16 * 144);
            #pragma unroll
            for (int nt = 0; nt < 4; nt++) {
                float* a = acc1[mt * 4 + nt];
                float e00 = ex2(a[0] - EXP_BIAS);
                float e01 = ex2(a[1] - EXP_BIAS);
                float e10 = ex2(a[2] - EXP_BIAS);
                float e11 = ex2(a[3] - EXP_BIAS);
                cs[mt][0] += e00 + e01;
                cs[mt][1] += e10 + e11;
                const uint32_t colb = (uint32_t)((wn1 + nt * 8 + 2 * t) * 2);
                *(uint32_t*)(smem + OFF_E + erA + colb) =
                    packh2(__float2half_rn(e00), __float2half_rn(e01));
                *(uint32_t*)(smem + OFF_E + erA + 8 * 144 + colb) =
                    packh2(__float2half_rn(e10), __float2half_rn(e11));
            }
        }
        __syncthreads();             // E visible

        // ---- GEMM2: D2t[64m x 64o] per warp over n-tile 64 ----
        const uint32_t vbuf = sb + OFF_V + (it & 1) * VBUF;
        #pragma unroll
        for (int ks = 0; ks < 4; ks++) {
            uint32_t af[4][4];
            #pragma unroll
            for (int mt = 0; mt < 4; mt++)
                ldm4(af[mt], aE + mt * (16 * 144) + ks * 32);
            #pragma unroll
            for (int j = 0; j < 4; j++) {      // o16 groups
                uint32_t bbv[4];
                ldm4(bbv, vbuf + bVoff + j * (16 * 144) + ks * 32);
                #pragma unroll
                for (int mt = 0; mt < 4; mt++) {
                    mma16816(acc2[mt * 8 + j * 2],     af[mt], bbv[0], bbv[1]);
                    mma16816(acc2[mt * 8 + j * 2 + 1], af[mt], bbv[2], bbv[3]);
                }
            }
        }
    }

    // ---- colsum reduce ----
    float* CS = (float*)(smem + OFF_CS);   // [2][128] (n-half, m-row)
    #pragma unroll
    for (int mt = 0; mt < 2; mt++)
        #pragma unroll
        for (int h = 0; h < 2; h++) {
            float v = cs[mt][h];
            v += __shfl_xor_sync(0xFFFFFFFFu, v, 1);
            v += __shfl_xor_sync(0xFFFFFFFFu, v, 2);
            if (t == 0) CS[(w & 1) * 128 + wm1 + mt * 16 + g + h * 8] = v;
        }
    __syncthreads();

    float inv[4][2];
    #pragma unroll
    for (int mt = 0; mt < 4; mt++) {
        int r = wm2 + mt * 16 + g;
        inv[mt][0] = 1.f / (CS[r] + CS[128 + r]);
        inv[mt][1] = 1.f / (CS[r + 8] + CS[128 + r + 8]);
    }

    // ---- output: out[b][o][m0 + m] ----
    #pragma unroll
    for (int mt = 0; mt < 4; mt++) {
        const int mcol = wm2 + mt * 16 + g;
        #pragma unroll
        for (int ot = 0; ot < 8; ot++) {
            const int o = wo2 + ot * 8 + 2 * t;
            const float* a = acc2[mt * 8 + ot];
            float* p0 = out + ((size_t)(b * On + o)) * Nn + m0;
            float* p1 = p0 + Nn;
            p0[mcol]     = a[0] * inv[mt][0];
            p1[mcol]     = a[1] * inv[mt][0];
            p0[mcol + 8] = a[2] * inv[mt][1];
            p1[mcol + 8] = a[3] * inv[mt][1];
        }
    }
}

// ---------------------------------------------------------------------------
extern "C" void kernel_launch(void* const* d_in, const int* in_sizes, int n_in,
                              void* d_out, int out_size)
{
    const float* x  = (const float*)d_in[0];
    const float* Wk = (const float*)d_in[1];
    const float* bk = (const float*)d_in[2];
    const float* Wq = (const float*)d_in[3];
    const float* bq = (const float*)d_in[4];
    const float* W1 = (const float*)d_in[5];
    const float* b1 = (const float*)d_in[6];
    const float* W2 = (const float*)d_in[7];
    const float* b2 = (const float*)d_in[8];
    const float* W3 = (const float*)d_in[9];
    const float* b3 = (const float*)d_in[10];
    float* out = (float*)d_out;

    __half *x16, *whi, *ktp, *qtp, *v1h, *v2h, *vhp;
    cudaGetSymbolAddress((void**)&x16, g_x16);
    cudaGetSymbolAddress((void**)&whi, g_whi);
    cudaGetSymbolAddress((void**)&ktp, g_kt);
    cudaGetSymbolAddress((void**)&qtp, g_qt);
    cudaGetSymbolAddress((void**)&v1h, g_v1h);
    cudaGetSymbolAddress((void**)&v2h, g_v2h);
    cudaGetSymbolAddress((void**)&vhp, g_vh);

    cudaFuncSetAttribute(proj16_kernel<0,0>, cudaFuncAttributeMaxDynamicSharedMemorySize, PJ_SMEM);
    cudaFuncSetAttribute(proj16_kernel<1,1>, cudaFuncAttributeMaxDynamicSharedMemorySize, PJ_SMEM);
    cudaFuncSetAttribute(attn_kernel, cudaFuncAttributeMaxDynamicSharedMemorySize, AT_SMEM);

    x16_kernel<<<4096, 256>>>(x);
    wprep_kernel<<<dim3(256, 4), 256>>>(Wk, Wq, W1, W3);

    const float LOG2E = 1.4426950408889634f;
    proj16_kernel<1,1><<<dim3(Nn / 128, Hn / 128, 2 * Bn), 256, PJ_SMEM>>>(
        whi + 0 * 65536, bk, x16, ktp, 1.0f,
        whi + 1 * 65536, bq, qtp, LOG2E);
    proj16_kernel<0,0><<<dim3(Nn / 128, Hn / 128, Bn), 256, PJ_SMEM>>>(
        whi + 2 * 65536, b1, x16, v1h, 1.0f,
        nullptr, nullptr, nullptr, 0.f);
    gconv16_kernel<<<dim3(Nn / 512, 32, Bn), 256>>>(W2, b2);
    proj16_kernel<0,0><<<dim3(Nn / 128, Hn / 128, Bn), 256, PJ_SMEM>>>(
        whi + 3 * 65536, b3, v2h, vhp, 1.0f,
        nullptr, nullptr, nullptr, 0.f);
    attn_kernel<<<dim3(Nn / 128, Bn), 256, AT_SMEM>>>(qtp, ktp, vhp, out);
}

// round 12
// speedup vs baseline: 9.7376x; 1.1063x over previous
#include <cuda_runtime.h>
#include <cuda_fp16.h>
#include <cstdint>

#define Bn 4
#define Cn 256
#define Hn 256
#define On 256
#define Nn 4096

// ---------------- scratch (device globals) ----------------------------------
__device__ __half g_x16[(size_t)Bn*Cn*Nn];   // x fp16 [b][c][n]
__device__ __half g_whi[4 * Cn * Hn];        // W fp16 (Wk,Wq,W1,W3)
__device__ __half g_kt [(size_t)Bn*Nn*Hn];   // k^T [b][n][h]
__device__ __half g_qt [(size_t)Bn*Nn*Hn];   // q^T [b][n][h] (scaled by log2e)
__device__ __half g_v1h[(size_t)Bn*Hn*Nn];   // v1 [b][h][n]
__device__ __half g_v2h[(size_t)Bn*Hn*Nn];   // v2 [b][h][n]
__device__ __half g_vh [(size_t)Bn*On*Nn];   // v  [b][o][n]

// ---------------- helpers ----------------------------------------------------
__device__ __forceinline__ uint32_t smem_u32(const void* p) {
    uint32_t a;
    asm("{ .reg .u64 t; cvta.to.shared.u64 t, %1; cvt.u32.u64 %0, t; }" : "=r"(a) : "l"(p));
    return a;
}
__device__ __forceinline__ uint32_t packh2(__half a, __half b) {
    __half2 h = __halves2half2(a, b);
    return *reinterpret_cast<const uint32_t*>(&h);
}
__device__ __forceinline__ float ex2(float x) {
    float r;
    asm("ex2.approx.f32 %0, %1;" : "=f"(r) : "f"(x));
    return r;
}
__device__ __forceinline__ void ldm4(uint32_t* r, uint32_t addr) {
    asm volatile("ldmatrix.sync.aligned.m8n8.x4.shared.b16 {%0,%1,%2,%3}, [%4];"
                 : "=r"(r[0]), "=r"(r[1]), "=r"(r[2]), "=r"(r[3]) : "r"(addr));
}
__device__ __forceinline__ void ldm4t(uint32_t* r, uint32_t addr) {
    asm volatile("ldmatrix.sync.aligned.m8n8.x4.trans.shared.b16 {%0,%1,%2,%3}, [%4];"
                 : "=r"(r[0]), "=r"(r[1]), "=r"(r[2]), "=r"(r[3]) : "r"(addr));
}
__device__ __forceinline__ void mma16816(float* c, const uint32_t* a, uint32_t b0, uint32_t b1) {
    asm volatile("mma.sync.aligned.m16n8k16.row.col.f32.f16.f16.f32 "
                 "{%0,%1,%2,%3}, {%4,%5,%6,%7}, {%8,%9}, {%0,%1,%2,%3};"
                 : "+f"(c[0]), "+f"(c[1]), "+f"(c[2]), "+f"(c[3])
                 : "r"(a[0]), "r"(a[1]), "r"(a[2]), "r"(a[3]), "r"(b0), "r"(b1));
}
#define CP16(dst, src) \
    asm volatile("cp.async.cg.shared.global [%0], [%1], 16;" :: "r"(dst), "l"(src))
#define CP_COMMIT() asm volatile("cp.async.commit_group;" ::: "memory")
#define CP_WAIT0()  asm volatile("cp.async.wait_group 0;" ::: "memory")
#define CP_WAIT1()  asm volatile("cp.async.wait_group 1;" ::: "memory")

// ---------------------------------------------------------------------------
// Prep: x fp32 -> fp16 ; weights fp32 -> fp16
// ---------------------------------------------------------------------------
__global__ __launch_bounds__(256) void x16_kernel(const float* __restrict__ x) {
    size_t q = (size_t)blockIdx.x * 256 + threadIdx.x;
    float4 v = *(const float4*)(x + q * 4);
    uint2 u;
    u.x = packh2(__float2half_rn(v.x), __float2half_rn(v.y));
    u.y = packh2(__float2half_rn(v.z), __float2half_rn(v.w));
    *(uint2*)(g_x16 + q * 4) = u;
}

__global__ __launch_bounds__(256) void wprep_kernel(
    const float* __restrict__ W0, const float* __restrict__ W1,
    const float* __restrict__ W2, const float* __restrict__ W3) {
    int e = blockIdx.x * 256 + threadIdx.x;
    int m = blockIdx.y;
    const float* src = (m == 0) ? W0 : (m == 1) ? W1 : (m == 2) ? W2 : W3;
    g_whi[m * 65536 + e] = __float2half_rn(src[e]);
}

// ---------------------------------------------------------------------------
// HMMA projection (unchanged from R10)
// ---------------------------------------------------------------------------
#define PJ_X     10240
#define PJ_BUF   18944
#define PJ_SMEM  56832

__device__ __forceinline__ void proj_issue(
    uint32_t sb, int buf, const __half* whi,
    const __half* X, int h0, int n0, int c0, int tid)
{
    uint32_t base = sb + buf * PJ_BUF;
    #pragma unroll
    for (int i = 0; i < 4; i++) {
        int idx = tid + i * 256;
        if (idx < 512) {
            int r = idx >> 4, c = idx & 15;
            CP16(base + PJ_X + r * 272 + c * 16, X + (size_t)(c0 + r) * Nn + n0 + c * 8);
        } else {
            int i2 = idx - 512;
            int r = i2 >> 2, c = i2 & 3;
            CP16(base + r * 80 + c * 16, whi + (size_t)(h0 + r) * Cn + c0 + c * 8);
        }
    }
}

template <int MODE, int DUAL>
__global__ __launch_bounds__(256, 2) void proj16_kernel(
    const __half* __restrict__ whiA, const float* __restrict__ biasA,
    const __half* __restrict__ X, __half* __restrict__ outA, float scaleA,
    const __half* __restrict__ whiB, const float* __restrict__ biasB,
    __half* __restrict__ outB, float scaleB)
{
    extern __shared__ char smem[];
    const uint32_t sb = smem_u32(smem);
    const int tid = threadIdx.x;
    const int l = tid & 31;
    const int w = tid >> 5;
    const int g = l >> 2;
    const int t = l & 3;
    const int n0 = blockIdx.x * 128;
    const int h0 = blockIdx.y * 128;
    const int p  = DUAL ? (blockIdx.z >> 2) : 0;
    const int b  = DUAL ? (blockIdx.z & 3) : blockIdx.z;
    const __half* whi  = (DUAL && p) ? whiB  : whiA;
    const float*  bias = (DUAL && p) ? biasB : biasA;
    __half*       out  = (DUAL && p) ? outB  : outA;
    const float   scale= (DUAL && p) ? scaleB: scaleA;
    const __half* Xb = X + (size_t)b * Cn * Nn;

    float acc[16][4] = {};

    proj_issue(sb, 0, whi, Xb, h0, n0, 0, tid);
    CP_COMMIT();
    proj_issue(sb, 1, whi, Xb, h0, n0, 32, tid);
    CP_COMMIT();

    if (MODE == 0) {
        const int wh = (w & 3) * 32;
        const int wn = (w >> 2) * 64;
        const uint32_t aW = (uint32_t)((wh + (l & 15)) * 80 + (l >> 4) * 16);
        const uint32_t bX = (uint32_t)((((l >> 3) & 1) * 8 + (l & 7)) * 272 + (wn + (l >> 4) * 8) * 2);

        for (int ck = 0; ck < 8; ck++) {
            if (ck < 6) CP_WAIT1(); else CP_WAIT0();
            __syncthreads();
            if (ck <= 5) { proj_issue(sb, (ck + 2) % 3, whi, Xb, h0, n0, (ck + 2) * 32, tid);
                           CP_COMMIT(); }
            const uint32_t bb = sb + (ck % 3) * PJ_BUF;
            #pragma unroll
            for (int ks = 0; ks < 2; ks++) {
                uint32_t q[4][4];
                #pragma unroll
                for (int jj = 0; jj < 4; jj++)
                    ldm4t(q[jj], bb + PJ_X + bX + ks * 4352 + jj * 32);
                uint32_t a[2][4];
                ldm4(a[0], bb + aW + ks * 32);
                ldm4(a[1], bb + aW + 16 * 80 + ks * 32);
                #pragma unroll
                for (int mi = 0; mi < 2; mi++)
                    #pragma unroll
                    for (int jj = 0; jj < 4; jj++) {
                        mma16816(acc[mi * 8 + jj * 2],     a[mi], q[jj][0], q[jj][1]);
                        mma16816(acc[mi * 8 + jj * 2 + 1], a[mi], q[jj][2], q[jj][3]);
                    }
            }
        }
        #pragma unroll
        for (int mi = 0; mi < 2; mi++) {
            float bv0 = bias[h0 + wh + mi * 16 + g];
            float bv1 = bias[h0 + wh + mi * 16 + g + 8];
            #pragma unroll
            for (int j = 0; j < 8; j++) {
                int h = h0 + wh + mi * 16 + g;
                int n = n0 + wn + j * 8 + 2 * t;
                float* a = acc[mi * 8 + j];
                *(uint32_t*)(out + ((size_t)(b * Hn + h)) * Nn + n) =
                    packh2(__float2half_rn((a[0] + bv0) * scale), __float2half_rn((a[1] + bv0) * scale));
                *(uint32_t*)(out + ((size_t)(b * Hn + h + 8)) * Nn + n) =
                    packh2(__float2half_rn((a[2] + bv1) * scale), __float2half_rn((a[3] + bv1) * scale));
            }
        }
    } else {
        const int wn = (w & 1) * 64;
        const int wh = (w >> 1) * 32;
        const uint32_t aX = (uint32_t)(((l >> 4) * 8 + (l & 7)) * 272 + (wn + ((l >> 3) & 1) * 8) * 2);
        const uint32_t bW = (uint32_t)((wh + ((l >> 4) << 3) + (l & 7)) * 80 + ((l >> 3) & 1) * 16);

        for (int ck = 0; ck < 8; ck++) {
            if (ck < 6) CP_WAIT1(); else CP_WAIT0();
            __syncthreads();
            if (ck <= 5) { proj_issue(sb, (ck + 2) % 3, whi, Xb, h0, n0, (ck + 2) * 32, tid);
                           CP_COMMIT(); }
            const uint32_t bb = sb + (ck % 3) * PJ_BUF;
            #pragma unroll
            for (int ks = 0; ks < 2; ks++) {
                uint32_t a[4][4];
                #pragma unroll
                for (int mi = 0; mi < 4; mi++)
                    ldm4t(a[mi], bb + PJ_X + aX + ks * 4352 + mi * 32);
                #pragma unroll
                for (int jj = 0; jj < 2; jj++) {
                    uint32_t qq[4];
                    ldm4(qq, bb + bW + jj * 1280 + ks * 32);
                    #pragma unroll
                    for (int mi = 0; mi < 4; mi++) {
                        mma16816(acc[mi * 4 + jj * 2],     a[mi], qq[0], qq[1]);
                        mma16816(acc[mi * 4 + jj * 2 + 1], a[mi], qq[2], qq[3]);
                    }
                }
            }
        }
        float bvj[4][2];
        #pragma unroll
        for (int j = 0; j < 4; j++) {
            bvj[j][0] = bias[h0 + wh + j * 8 + 2 * t];
            bvj[j][1] = bias[h0 + wh + j * 8 + 2 * t + 1];
        }
        #pragma unroll
        for (int mi = 0; mi < 4; mi++) {
            int nr = n0 + wn + mi * 16 + g;
            #pragma unroll
            for (int j = 0; j < 4; j++) {
                float* a = acc[mi * 4 + j];
                int hc = h0 + wh + j * 8 + 2 * t;
                *(uint32_t*)(out + ((size_t)(b * Nn + nr)) * Hn + hc) =
                    packh2(__float2half_rn((a[0] + bvj[j][0]) * scale), __float2half_rn((a[1] + bvj[j][1]) * scale));
                *(uint32_t*)(out + ((size_t)(b * Nn + nr + 8)) * Hn + hc) =
                    packh2(__float2half_rn((a[2] + bvj[j][0]) * scale), __float2half_rn((a[3] + bvj[j][1]) * scale));
            }
        }
    }
}

// ---------------------------------------------------------------------------
// Grouped conv1d fp16 (unchanged)
// ---------------------------------------------------------------------------
__global__ __launch_bounds__(256) void gconv16_kernel(
    const float* __restrict__ W2, const float* __restrict__ b2)
{
    __shared__ __half xs[8][536];
    __shared__ float ws[192];
    __shared__ float bs[8];

    const int tid = threadIdx.x;
    const int n0 = blockIdx.x * 512;
    const int gr = blockIdx.y;
    const int b  = blockIdx.z;

    if (tid < 192) ws[tid] = W2[gr * 192 + tid];
    if (tid < 8)   bs[tid] = b2[gr * 8 + tid];

    const __half* in = g_v1h + ((size_t)b * Hn + gr * 8) * Nn;
    for (int idx = tid; idx < 8 * 66; idx += 256) {
        int r = idx / 66, c = idx % 66;
        int gn = n0 - 8 + c * 8;
        if (gn >= 0 && gn + 8 <= Nn) {
            *(uint4*)&xs[r][c * 8] = *(const uint4*)(in + (size_t)r * Nn + gn);
        } else {
            #pragma unroll
            for (int j = 0; j < 8; j++) {
                int n = gn + j;
                xs[r][c * 8 + j] = (n >= 0 && n < Nn) ? in[(size_t)r * Nn + n] : __half(0.f);
            }
        }
    }
    __syncthreads();

    __half* ob = g_v2h + ((size_t)b * Hn + gr * 8) * Nn + n0;
    #pragma unroll
    for (int k = 0; k < 2; k++) {
        int n = tid + k * 256;
        float xm[8], x0[8], xp[8];
        #pragma unroll
        for (int i = 0; i < 8; i++) {
            xm[i] = __half2float(xs[i][8 + n - 1]);
            x0[i] = __half2float(xs[i][8 + n]);
            xp[i] = __half2float(xs[i][8 + n + 1]);
        }
        #pragma unroll
        for (int h = 0; h < 8; h++) {
            float acc = bs[h];
            #pragma unroll
            for (int i = 0; i < 8; i++) {
                acc = fmaf(ws[h * 24 + i * 3 + 0], xm[i], acc);
                acc = fmaf(ws[h * 24 + i * 3 + 1], x0[i], acc);
                acc = fmaf(ws[h * 24 + i * 3 + 2], xp[i], acc);
            }
            ob[(size_t)h * Nn + n] = __float2half_rn(fmaxf(acc, 0.f));
        }
    }
}

// ---------------------------------------------------------------------------
// Fused HMMA attention, m-tile 128, 1 wave, software-pipelined, XOR-swizzled
// smem tiles (chunk c ^= r&7, 16B chunks). One __syncthreads per iteration.
//   GEMM1 warp 32m x 32n; GEMM2 warp 64m x 64o. K/V/E double-buffered.
// ---------------------------------------------------------------------------
#define OFF_Q   0
#define OFF_K   65536
#define OFF_V   131072
#define OFF_E   196608
#define OFF_CS  229376
#define AT_SMEM 230400
#define KBUF    32768
#define VBUF    32768
#define EBUF    16384
#define EXP_BIAS 5.7707802f   /* 4 * log2(e) */

__device__ __forceinline__ void issue_k(uint32_t sb, int buf, const __half* kb, int n0, int tid) {
    uint32_t kd = sb + OFF_K + buf * KBUF;
    #pragma unroll
    for (int i = 0; i < 8; i++) {
        int ch = tid + i * 256;
        int r = ch >> 5, c = ch & 31;
        CP16(kd + r * 512 + ((c ^ (r & 7)) << 4), kb + (size_t)(n0 + r) * Hn + c * 8);
    }
}
__device__ __forceinline__ void issue_v(uint32_t sb, int buf, const __half* vb, int n0, int tid) {
    uint32_t vd = sb + OFF_V + buf * VBUF;
    #pragma unroll
    for (int i = 0; i < 8; i++) {
        int ch = tid + i * 256;
        int r = ch >> 3, c = ch & 7;
        CP16(vd + r * 128 + ((c ^ (r & 7)) << 4), vb + (size_t)r * Nn + n0 + c * 8);
    }
}

#define GEMM1_BODY(kbase) do {                                              \
    _Pragma("unroll")                                                       \
    for (int ks = 0; ks < 16; ks++) {                                       \
        uint32_t a0[4], a1[4], p[4], q[4];                                  \
        ldm4(a0, qrow + (((ks * 2) ^ mq) << 4));                            \
        ldm4(a1, qrow + 16 * 512 + (((ks * 2) ^ mq) << 4));                 \
        ldm4(p, (kbase) + krow_off + (((ks * 2) ^ mk) << 4));               \
        ldm4(q, (kbase) + krow_off + 16 * 512 + (((ks * 2) ^ mk) << 4));    \
        mma16816(acc1[0], a0, p[0], p[1]);                                  \
        mma16816(acc1[1], a0, p[2], p[3]);                                  \
        mma16816(acc1[2], a0, q[0], q[1]);                                  \
        mma16816(acc1[3], a0, q[2], q[3]);                                  \
        mma16816(acc1[4], a1, p[0], p[1]);                                  \
        mma16816(acc1[5], a1, p[2], p[3]);                                  \
        mma16816(acc1[6], a1, q[0], q[1]);                                  \
        mma16816(acc1[7], a1, q[2], q[3]);                                  \
    } } while (0)

#define EPI_BODY(ebase) do {                                                \
    _Pragma("unroll")                                                       \
    for (int mt = 0; mt < 2; mt++) {                                        \
        const uint32_t erA = eRow0 + (uint32_t)(mt * 2048);                 \
        _Pragma("unroll")                                                   \
        for (int nt = 0; nt < 4; nt++) {                                    \
            float* a = acc1[mt * 4 + nt];                                   \
            float e00 = ex2(a[0] - EXP_BIAS);                               \
            float e01 = ex2(a[1] - EXP_BIAS);                               \
            float e10 = ex2(a[2] - EXP_BIAS);                               \
            float e11 = ex2(a[3] - EXP_BIAS);                               \
            cs[mt][0] += e00 + e01;                                         \
            cs[mt][1] += e10 + e11;                                         \
            const uint32_t cof = ((eCh ^ (uint32_t)nt) << 4);               \
            *(uint32_t*)(smem + (ebase) + erA + cof) =                      \
                packh2(__float2half_rn(e00), __float2half_rn(e01));         \
            *(uint32_t*)(smem + (ebase) + erA + 1024 + cof) =               \
                packh2(__float2half_rn(e10), __float2half_rn(e11));         \
        }                                                                   \
    } } while (0)

#define GEMM2_BODY(ebase, vbase) do {                                       \
    _Pragma("unroll")                                                       \
    for (int ks = 0; ks < 4; ks++) {                                        \
        uint32_t af[4][4];                                                  \
        _Pragma("unroll")                                                   \
        for (int mt = 0; mt < 4; mt++)                                      \
            ldm4(af[mt], (ebase) + erow_off + mt * 2048 + (((ks * 2) ^ me) << 4)); \
        _Pragma("unroll")                                                   \
        for (int j = 0; j < 4; j++) {                                       \
            uint32_t bbv[4];                                                \
            ldm4(bbv, (vbase) + vrow_off + j * 2048 + (((ks * 2) ^ mv) << 4)); \
            _Pragma("unroll")                                               \
            for (int mt = 0; mt < 4; mt++) {                                \
                mma16816(acc2[mt * 8 + j * 2],     af[mt], bbv[0], bbv[1]); \
                mma16816(acc2[mt * 8 + j * 2 + 1], af[mt], bbv[2], bbv[3]); \
            }                                                               \
        }                                                                   \
    } } while (0)

__global__ __launch_bounds__(256, 1)
void attn_kernel(const __half* __restrict__ qt, const __half* __restrict__ kt,
                 const __half* __restrict__ vh, float* __restrict__ out)
{
    extern __shared__ char smem[];
    const int tid  = threadIdx.x;
    const int l    = tid & 31;
    const int w    = tid >> 5;
    const int m0 = blockIdx.x * 128;
    const int b  = blockIdx.y;
    const uint32_t sb = smem_u32(smem);
    const int g = l >> 2;
    const int t = l & 3;

    const int wm1 = (w >> 1) * 32;   // GEMM1: warp 32m x 32n
    const int wn1 = (w & 1) * 32;
    const int wm2 = (w & 1) * 64;    // GEMM2: warp 64m x 64o
    const int wo2 = (w >> 1) * 64;

    const __half* kb = kt + (size_t)b * Nn * Hn;
    const __half* vb = vh + (size_t)b * On * Nn;

    // prologue: stage Q [128 m][256 h], swizzled 512B rows
    #pragma unroll
    for (int i = 0; i < 16; i++) {
        int ch = tid + i * 256;
        int r = ch >> 5, c = ch & 31;
        *(float4*)(smem + OFF_Q + r * 512 + ((c ^ (r & 7)) << 4)) =
            *(const float4*)(qt + ((size_t)(b * Nn + m0 + r)) * Hn + c * 8);
    }
    issue_k(sb, 0, kb, 0, tid);
    issue_v(sb, 0, vb, 0, tid);
    CP_COMMIT();
    issue_k(sb, 1, kb, 64, tid);
    CP_COMMIT();

    // per-lane swizzled address components
    const uint32_t qrow = sb + OFF_Q + (uint32_t)((wm1 + (l & 15)) * 512);
    const uint32_t mq   = (uint32_t)(((l >> 4) & 1) ^ (l & 7));
    const uint32_t krow_off = (uint32_t)((wn1 + ((l >> 4) << 3) + (l & 7)) * 512);
    const uint32_t mk   = (uint32_t)(((l >> 3) & 1) ^ (l & 7));
    const uint32_t erow_off = (uint32_t)((wm2 + (l & 15)) * 128);
    const uint32_t me   = (uint32_t)(((l >> 4) & 1) ^ (l & 7));
    const uint32_t vrow_off = (uint32_t)((wo2 + ((l >> 4) << 3) + (l & 7)) * 128);
    const uint32_t mv   = (uint32_t)(((l >> 3) & 1) ^ (l & 7));
    const uint32_t eRow0 = (uint32_t)((wm1 + g) * 128 + 4 * t);
    const uint32_t eCh   = (uint32_t)((wn1 >> 3) ^ g);

    float acc2[32][4] = {};          // [mt4*8 + ot8][4]
    float cs[2][2] = {};
    float acc1[8][4];

    // ---- pipeline prologue: GEMM1(0) + EPI(0) -> E0 ----
    CP_WAIT0();
    __syncthreads();
    #pragma unroll
    for (int i = 0; i < 8; i++)
        #pragma unroll
        for (int j = 0; j < 4; j++) acc1[i][j] = 0.f;
    GEMM1_BODY(sb + OFF_K + 0 * KBUF);
    EPI_BODY(OFF_E + 0 * EBUF);
    __syncthreads();

    // ---- main loop: it = 0..62 ----
    for (int it = 0; it < 63; it++) {
        issue_v(sb, (it + 1) & 1, vb, (it + 1) * 64, tid);
        if (it + 2 < 64) issue_k(sb, it & 1, kb, (it + 2) * 64, tid);
        CP_COMMIT();

        // GEMM2(it) + GEMM1(it+1): uninterrupted HMMA stretch
        GEMM2_BODY(sb + OFF_E + (it & 1) * EBUF, sb + OFF_V + (it & 1) * VBUF);
        #pragma unroll
        for (int i = 0; i < 8; i++)
            #pragma unroll
            for (int j = 0; j < 4; j++) acc1[i][j] = 0.f;
        GEMM1_BODY(sb + OFF_K + ((it + 1) & 1) * KBUF);

        EPI_BODY(OFF_E + ((it + 1) & 1) * EBUF);

        CP_WAIT0();
        __syncthreads();
    }

    // ---- tail: GEMM2(63) ----
    GEMM2_BODY(sb + OFF_E + 1 * EBUF, sb + OFF_V + 1 * VBUF);

    // ---- colsum reduce ----
    float* CS = (float*)(smem + OFF_CS);   // [2][128]
    #pragma unroll
    for (int mt = 0; mt < 2; mt++)
        #pragma unroll
        for (int h = 0; h < 2; h++) {
            float v = cs[mt][h];
            v += __shfl_xor_sync(0xFFFFFFFFu, v, 1);
            v += __shfl_xor_sync(0xFFFFFFFFu, v, 2);
            if (t == 0) CS[(w & 1) * 128 + wm1 + mt * 16 + g + h * 8] = v;
        }
    __syncthreads();

    float inv[4][2];
    #pragma unroll
    for (int mt = 0; mt < 4; mt++) {
        int r = wm2 + mt * 16 + g;
        inv[mt][0] = 1.f / (CS[r] + CS[128 + r]);
        inv[mt][1] = 1.f / (CS[r + 8] + CS[128 + r + 8]);
    }

    // ---- output ----
    #pragma unroll
    for (int mt = 0; mt < 4; mt++) {
        const int mcol = wm2 + mt * 16 + g;
        #pragma unroll
        for (int ot = 0; ot < 8; ot++) {
            const int o = wo2 + ot * 8 + 2 * t;
            const float* a = acc2[mt * 8 + ot];
            float* p0 = out + ((size_t)(b * On + o)) * Nn + m0;
            float* p1 = p0 + Nn;
            p0[mcol]     = a[0] * inv[mt][0];
            p1[mcol]     = a[1] * inv[mt][0];
            p0[mcol + 8] = a[2] * inv[mt][1];
            p1[mcol + 8] = a[3] * inv[mt][1];
        }
    }
}

// ---------------------------------------------------------------------------
extern "C" void kernel_launch(void* const* d_in, const int* in_sizes, int n_in,
                              void* d_out, int out_size)
{
    const float* x  = (const float*)d_in[0];
    const float* Wk = (const float*)d_in[1];
    const float* bk = (const float*)d_in[2];
    const float* Wq = (const float*)d_in[3];
    const float* bq = (const float*)d_in[4];
    const float* W1 = (const float*)d_in[5];
    const float* b1 = (const float*)d_in[6];
    const float* W2 = (const float*)d_in[7];
    const float* b2 = (const float*)d_in[8];
    const float* W3 = (const float*)d_in[9];
    const float* b3 = (const float*)d_in[10];
    float* out = (float*)d_out;

    __half *x16, *whi, *ktp, *qtp, *v1h, *v2h, *vhp;
    cudaGetSymbolAddress((void**)&x16, g_x16);
    cudaGetSymbolAddress((void**)&whi, g_whi);
    cudaGetSymbolAddress((void**)&ktp, g_kt);
    cudaGetSymbolAddress((void**)&qtp, g_qt);
    cudaGetSymbolAddress((void**)&v1h, g_v1h);
    cudaGetSymbolAddress((void**)&v2h, g_v2h);
    cudaGetSymbolAddress((void**)&vhp, g_vh);

    cudaFuncSetAttribute(proj16_kernel<0,0>, cudaFuncAttributeMaxDynamicSharedMemorySize, PJ_SMEM);
    cudaFuncSetAttribute(proj16_kernel<1,1>, cudaFuncAttributeMaxDynamicSharedMemorySize, PJ_SMEM);
    cudaFuncSetAttribute(attn_kernel, cudaFuncAttributeMaxDynamicSharedMemorySize, AT_SMEM);

    x16_kernel<<<4096, 256>>>(x);
    wprep_kernel<<<dim3(256, 4), 256>>>(Wk, Wq, W1, W3);

    const float LOG2E = 1.4426950408889634f;
    proj16_kernel<1,1><<<dim3(Nn / 128, Hn / 128, 2 * Bn), 256, PJ_SMEM>>>(
        whi + 0 * 65536, bk, x16, ktp, 1.0f,
        whi + 1 * 65536, bq, qtp, LOG2E);
    proj16_kernel<0,0><<<dim3(Nn / 128, Hn / 128, Bn), 256, PJ_SMEM>>>(
        whi + 2 * 65536, b1, x16, v1h, 1.0f,
        nullptr, nullptr, nullptr, 0.f);
    gconv16_kernel<<<dim3(Nn / 512, 32, Bn), 256>>>(W2, b2);
    proj16_kernel<0,0><<<dim3(Nn / 128, Hn / 128, Bn), 256, PJ_SMEM>>>(
        whi + 3 * 65536, b3, v2h, vhp, 1.0f,
        nullptr, nullptr, nullptr, 0.f);
    attn_kernel<<<dim3(Nn / 128, Bn), 256, AT_SMEM>>>(qtp, ktp, vhp, out);
}

// round 13
// speedup vs baseline: 9.9118x; 1.0179x over previous
#include <cuda_runtime.h>
#include <cuda_fp16.h>
#include <cstdint>

#define Bn 4
#define Cn 256
#define Hn 256
#define On 256
#define Nn 4096

// ---------------- scratch (device globals) ----------------------------------
__device__ __half g_x16[(size_t)Bn*Cn*Nn];   // x fp16 [b][c][n]
__device__ __half g_whi[4 * Cn * Hn];        // W fp16 (Wk,Wq,W1,W3)
__device__ __half g_kt [(size_t)Bn*Nn*Hn];   // k^T [b][n][h]
__device__ __half g_qt [(size_t)Bn*Nn*Hn];   // q^T [b][n][h] (scaled by log2e)
__device__ __half g_v1h[(size_t)Bn*Hn*Nn];   // v1 [b][h][n]
__device__ __half g_v2h[(size_t)Bn*Hn*Nn];   // v2 [b][h][n]
__device__ __half g_vh [(size_t)Bn*On*Nn];   // v  [b][o][n]

// ---------------- helpers ----------------------------------------------------
__device__ __forceinline__ uint32_t smem_u32(const void* p) {
    uint32_t a;
    asm("{ .reg .u64 t; cvta.to.shared.u64 t, %1; cvt.u32.u64 %0, t; }" : "=r"(a) : "l"(p));
    return a;
}
__device__ __forceinline__ uint32_t packh2(__half a, __half b) {
    __half2 h = __halves2half2(a, b);
    return *reinterpret_cast<const uint32_t*>(&h);
}
// pack two f32 -> f16x2 in ONE cvt (lo = first arg)
__device__ __forceinline__ uint32_t pack2(float lo, float hi) {
    uint32_t r;
    asm("cvt.rn.f16x2.f32 %0, %1, %2;" : "=r"(r) : "f"(hi), "f"(lo));
    return r;
}
__device__ __forceinline__ float ex2(float x) {
    float r;
    asm("ex2.approx.f32 %0, %1;" : "=f"(r) : "f"(x));
    return r;
}
__device__ __forceinline__ void ldm4(uint32_t* r, uint32_t addr) {
    asm volatile("ldmatrix.sync.aligned.m8n8.x4.shared.b16 {%0,%1,%2,%3}, [%4];"
                 : "=r"(r[0]), "=r"(r[1]), "=r"(r[2]), "=r"(r[3]) : "r"(addr));
}
__device__ __forceinline__ void ldm4t(uint32_t* r, uint32_t addr) {
    asm volatile("ldmatrix.sync.aligned.m8n8.x4.trans.shared.b16 {%0,%1,%2,%3}, [%4];"
                 : "=r"(r[0]), "=r"(r[1]), "=r"(r[2]), "=r"(r[3]) : "r"(addr));
}
__device__ __forceinline__ void mma16816(float* c, const uint32_t* a, uint32_t b0, uint32_t b1) {
    asm volatile("mma.sync.aligned.m16n8k16.row.col.f32.f16.f16.f32 "
                 "{%0,%1,%2,%3}, {%4,%5,%6,%7}, {%8,%9}, {%0,%1,%2,%3};"
                 : "+f"(c[0]), "+f"(c[1]), "+f"(c[2]), "+f"(c[3])
                 : "r"(a[0]), "r"(a[1]), "r"(a[2]), "r"(a[3]), "r"(b0), "r"(b1));
}
#define CP16(dst, src) \
    asm volatile("cp.async.cg.shared.global [%0], [%1], 16;" :: "r"(dst), "l"(src))
#define CP_COMMIT() asm volatile("cp.async.commit_group;" ::: "memory")
#define CP_WAIT0()  asm volatile("cp.async.wait_group 0;" ::: "memory")
#define CP_WAIT1()  asm volatile("cp.async.wait_group 1;" ::: "memory")

// ---------------------------------------------------------------------------
// Prep: x fp32 -> fp16 ; weights fp32 -> fp16
// ---------------------------------------------------------------------------
__global__ __launch_bounds__(256) void x16_kernel(const float* __restrict__ x) {
    size_t q = (size_t)blockIdx.x * 256 + threadIdx.x;
    float4 v = *(const float4*)(x + q * 4);
    uint2 u;
    u.x = packh2(__float2half_rn(v.x), __float2half_rn(v.y));
    u.y = packh2(__float2half_rn(v.z), __float2half_rn(v.w));
    *(uint2*)(g_x16 + q * 4) = u;
}

__global__ __launch_bounds__(256) void wprep_kernel(
    const float* __restrict__ W0, const float* __restrict__ W1,
    const float* __restrict__ W2, const float* __restrict__ W3) {
    int e = blockIdx.x * 256 + threadIdx.x;
    int m = blockIdx.y;
    const float* src = (m == 0) ? W0 : (m == 1) ? W1 : (m == 2) ? W2 : W3;
    g_whi[m * 65536 + e] = __float2half_rn(src[e]);
}

// ---------------------------------------------------------------------------
// HMMA projection (unchanged)
// ---------------------------------------------------------------------------
#define PJ_X     10240
#define PJ_BUF   18944
#define PJ_SMEM  56832

__device__ __forceinline__ void proj_issue(
    uint32_t sb, int buf, const __half* whi,
    const __half* X, int h0, int n0, int c0, int tid)
{
    uint32_t base = sb + buf * PJ_BUF;
    #pragma unroll
    for (int i = 0; i < 4; i++) {
        int idx = tid + i * 256;
        if (idx < 512) {
            int r = idx >> 4, c = idx & 15;
            CP16(base + PJ_X + r * 272 + c * 16, X + (size_t)(c0 + r) * Nn + n0 + c * 8);
        } else {
            int i2 = idx - 512;
            int r = i2 >> 2, c = i2 & 3;
            CP16(base + r * 80 + c * 16, whi + (size_t)(h0 + r) * Cn + c0 + c * 8);
        }
    }
}

template <int MODE, int DUAL>
__global__ __launch_bounds__(256, 2) void proj16_kernel(
    const __half* __restrict__ whiA, const float* __restrict__ biasA,
    const __half* __restrict__ X, __half* __restrict__ outA, float scaleA,
    const __half* __restrict__ whiB, const float* __restrict__ biasB,
    __half* __restrict__ outB, float scaleB)
{
    extern __shared__ char smem[];
    const uint32_t sb = smem_u32(smem);
    const int tid = threadIdx.x;
    const int l = tid & 31;
    const int w = tid >> 5;
    const int g = l >> 2;
    const int t = l & 3;
    const int n0 = blockIdx.x * 128;
    const int h0 = blockIdx.y * 128;
    const int p  = DUAL ? (blockIdx.z >> 2) : 0;
    const int b  = DUAL ? (blockIdx.z & 3) : blockIdx.z;
    const __half* whi  = (DUAL && p) ? whiB  : whiA;
    const float*  bias = (DUAL && p) ? biasB : biasA;
    __half*       out  = (DUAL && p) ? outB  : outA;
    const float   scale= (DUAL && p) ? scaleB: scaleA;
    const __half* Xb = X + (size_t)b * Cn * Nn;

    float acc[16][4] = {};

    proj_issue(sb, 0, whi, Xb, h0, n0, 0, tid);
    CP_COMMIT();
    proj_issue(sb, 1, whi, Xb, h0, n0, 32, tid);
    CP_COMMIT();

    if (MODE == 0) {
        const int wh = (w & 3) * 32;
        const int wn = (w >> 2) * 64;
        const uint32_t aW = (uint32_t)((wh + (l & 15)) * 80 + (l >> 4) * 16);
        const uint32_t bX = (uint32_t)((((l >> 3) & 1) * 8 + (l & 7)) * 272 + (wn + (l >> 4) * 8) * 2);

        for (int ck = 0; ck < 8; ck++) {
            if (ck < 6) CP_WAIT1(); else CP_WAIT0();
            __syncthreads();
            if (ck <= 5) { proj_issue(sb, (ck + 2) % 3, whi, Xb, h0, n0, (ck + 2) * 32, tid);
                           CP_COMMIT(); }
            const uint32_t bb = sb + (ck % 3) * PJ_BUF;
            #pragma unroll
            for (int ks = 0; ks < 2; ks++) {
                uint32_t q[4][4];
                #pragma unroll
                for (int jj = 0; jj < 4; jj++)
                    ldm4t(q[jj], bb + PJ_X + bX + ks * 4352 + jj * 32);
                uint32_t a[2][4];
                ldm4(a[0], bb + aW + ks * 32);
                ldm4(a[1], bb + aW + 16 * 80 + ks * 32);
                #pragma unroll
                for (int mi = 0; mi < 2; mi++)
                    #pragma unroll
                    for (int jj = 0; jj < 4; jj++) {
                        mma16816(acc[mi * 8 + jj * 2],     a[mi], q[jj][0], q[jj][1]);
                        mma16816(acc[mi * 8 + jj * 2 + 1], a[mi], q[jj][2], q[jj][3]);
                    }
            }
        }
        #pragma unroll
        for (int mi = 0; mi < 2; mi++) {
            float bv0 = bias[h0 + wh + mi * 16 + g];
            float bv1 = bias[h0 + wh + mi * 16 + g + 8];
            #pragma unroll
            for (int j = 0; j < 8; j++) {
                int h = h0 + wh + mi * 16 + g;
                int n = n0 + wn + j * 8 + 2 * t;
                float* a = acc[mi * 8 + j];
                *(uint32_t*)(out + ((size_t)(b * Hn + h)) * Nn + n) =
                    packh2(__float2half_rn((a[0] + bv0) * scale), __float2half_rn((a[1] + bv0) * scale));
                *(uint32_t*)(out + ((size_t)(b * Hn + h + 8)) * Nn + n) =
                    packh2(__float2half_rn((a[2] + bv1) * scale), __float2half_rn((a[3] + bv1) * scale));
            }
        }
    } else {
        const int wn = (w & 1) * 64;
        const int wh = (w >> 1) * 32;
        const uint32_t aX = (uint32_t)(((l >> 4) * 8 + (l & 7)) * 272 + (wn + ((l >> 3) & 1) * 8) * 2);
        const uint32_t bW = (uint32_t)((wh + ((l >> 4) << 3) + (l & 7)) * 80 + ((l >> 3) & 1) * 16);

        for (int ck = 0; ck < 8; ck++) {
            if (ck < 6) CP_WAIT1(); else CP_WAIT0();
            __syncthreads();
            if (ck <= 5) { proj_issue(sb, (ck + 2) % 3, whi, Xb, h0, n0, (ck + 2) * 32, tid);
                           CP_COMMIT(); }
            const uint32_t bb = sb + (ck % 3) * PJ_BUF;
            #pragma unroll
            for (int ks = 0; ks < 2; ks++) {
                uint32_t a[4][4];
                #pragma unroll
                for (int mi = 0; mi < 4; mi++)
                    ldm4t(a[mi], bb + PJ_X + aX + ks * 4352 + mi * 32);
                #pragma unroll
                for (int jj = 0; jj < 2; jj++) {
                    uint32_t qq[4];
                    ldm4(qq, bb + bW + jj * 1280 + ks * 32);
                    #pragma unroll
                    for (int mi = 0; mi < 4; mi++) {
                        mma16816(acc[mi * 4 + jj * 2],     a[mi], qq[0], qq[1]);
                        mma16816(acc[mi * 4 + jj * 2 + 1], a[mi], qq[2], qq[3]);
                    }
                }
            }
        }
        float bvj[4][2];
        #pragma unroll
        for (int j = 0; j < 4; j++) {
            bvj[j][0] = bias[h0 + wh + j * 8 + 2 * t];
            bvj[j][1] = bias[h0 + wh + j * 8 + 2 * t + 1];
        }
        #pragma unroll
        for (int mi = 0; mi < 4; mi++) {
            int nr = n0 + wn + mi * 16 + g;
            #pragma unroll
            for (int j = 0; j < 4; j++) {
                float* a = acc[mi * 4 + j];
                int hc = h0 + wh + j * 8 + 2 * t;
                *(uint32_t*)(out + ((size_t)(b * Nn + nr)) * Hn + hc) =
                    packh2(__float2half_rn((a[0] + bvj[j][0]) * scale), __float2half_rn((a[1] + bvj[j][1]) * scale));
                *(uint32_t*)(out + ((size_t)(b * Nn + nr + 8)) * Hn + hc) =
                    packh2(__float2half_rn((a[2] + bvj[j][0]) * scale), __float2half_rn((a[3] + bvj[j][1]) * scale));
            }
        }
    }
}

// ---------------------------------------------------------------------------
// Grouped conv1d fp16 (unchanged)
// ---------------------------------------------------------------------------
__global__ __launch_bounds__(256) void gconv16_kernel(
    const float* __restrict__ W2, const float* __restrict__ b2)
{
    __shared__ __half xs[8][536];
    __shared__ float ws[192];
    __shared__ float bs[8];

    const int tid = threadIdx.x;
    const int n0 = blockIdx.x * 512;
    const int gr = blockIdx.y;
    const int b  = blockIdx.z;

    if (tid < 192) ws[tid] = W2[gr * 192 + tid];
    if (tid < 8)   bs[tid] = b2[gr * 8 + tid];

    const __half* in = g_v1h + ((size_t)b * Hn + gr * 8) * Nn;
    for (int idx = tid; idx < 8 * 66; idx += 256) {
        int r = idx / 66, c = idx % 66;
        int gn = n0 - 8 + c * 8;
        if (gn >= 0 && gn + 8 <= Nn) {
            *(uint4*)&xs[r][c * 8] = *(const uint4*)(in + (size_t)r * Nn + gn);
        } else {
            #pragma unroll
            for (int j = 0; j < 8; j++) {
                int n = gn + j;
                xs[r][c * 8 + j] = (n >= 0 && n < Nn) ? in[(size_t)r * Nn + n] : __half(0.f);
            }
        }
    }
    __syncthreads();

    __half* ob = g_v2h + ((size_t)b * Hn + gr * 8) * Nn + n0;
    #pragma unroll
    for (int k = 0; k < 2; k++) {
        int n = tid + k * 256;
        float xm[8], x0[8], xp[8];
        #pragma unroll
        for (int i = 0; i < 8; i++) {
            xm[i] = __half2float(xs[i][8 + n - 1]);
            x0[i] = __half2float(xs[i][8 + n]);
            xp[i] = __half2float(xs[i][8 + n + 1]);
        }
        #pragma unroll
        for (int h = 0; h < 8; h++) {
            float acc = bs[h];
            #pragma unroll
            for (int i = 0; i < 8; i++) {
                acc = fmaf(ws[h * 24 + i * 3 + 0], xm[i], acc);
                acc = fmaf(ws[h * 24 + i * 3 + 1], x0[i], acc);
                acc = fmaf(ws[h * 24 + i * 3 + 2], xp[i], acc);
            }
            ob[(size_t)h * Nn + n] = __float2half_rn(fmaxf(acc, 0.f));
        }
    }
}

// ---------------------------------------------------------------------------
// Fused HMMA attention, m-tile 128, 1 wave, software-pipelined, XOR swizzle.
// Iteration: GEMM1(it+1) -> [GEMM2(it) interleaved with EPI(it+1)] -> 1 sync.
// ---------------------------------------------------------------------------
#define OFF_Q   0
#define OFF_K   65536
#define OFF_V   131072
#define OFF_E   196608
#define OFF_CS  229376
#define AT_SMEM 230400
#define KBUF    32768
#define VBUF    32768
#define EBUF    16384
#define EXP_BIAS 5.7707802f   /* 4 * log2(e) */

__device__ __forceinline__ void issue_k(uint32_t sb, int buf, const __half* kb, int n0, int tid) {
    uint32_t kd = sb + OFF_K + buf * KBUF;
    #pragma unroll
    for (int i = 0; i < 8; i++) {
        int ch = tid + i * 256;
        int r = ch >> 5, c = ch & 31;
        CP16(kd + r * 512 + ((c ^ (r & 7)) << 4), kb + (size_t)(n0 + r) * Hn + c * 8);
    }
}
__device__ __forceinline__ void issue_v(uint32_t sb, int buf, const __half* vb, int n0, int tid) {
    uint32_t vd = sb + OFF_V + buf * VBUF;
    #pragma unroll
    for (int i = 0; i < 8; i++) {
        int ch = tid + i * 256;
        int r = ch >> 3, c = ch & 7;
        CP16(vd + r * 128 + ((c ^ (r & 7)) << 4), vb + (size_t)r * Nn + n0 + c * 8);
    }
}

#define GEMM1_BODY(kbase) do {                                              \
    _Pragma("unroll")                                                       \
    for (int ks = 0; ks < 16; ks++) {                                       \
        uint32_t a0[4], a1[4], p[4], q[4];                                  \
        ldm4(a0, qrow + (((ks * 2) ^ mq) << 4));                            \
        ldm4(a1, qrow + 16 * 512 + (((ks * 2) ^ mq) << 4));                 \
        ldm4(p, (kbase) + krow_off + (((ks * 2) ^ mk) << 4));               \
        ldm4(q, (kbase) + krow_off + 16 * 512 + (((ks * 2) ^ mk) << 4));    \
        mma16816(acc1[0], a0, p[0], p[1]);                                  \
        mma16816(acc1[1], a0, p[2], p[3]);                                  \
        mma16816(acc1[2], a0, q[0], q[1]);                                  \
        mma16816(acc1[3], a0, q[2], q[3]);                                  \
        mma16816(acc1[4], a1, p[0], p[1]);                                  \
        mma16816(acc1[5], a1, p[2], p[3]);                                  \
        mma16816(acc1[6], a1, q[0], q[1]);                                  \
        mma16816(acc1[7], a1, q[2], q[3]);                                  \
    } } while (0)

// one epilogue unit u in [0,8): mt = u>>2, nt = u&3
#define EPI_UNIT(ebase, u) do {                                             \
    const int _mt = (u) >> 2, _nt = (u) & 3;                                \
    float* _a = acc1[_mt * 4 + _nt];                                        \
    float e00 = ex2(_a[0] - EXP_BIAS);                                      \
    float e01 = ex2(_a[1] - EXP_BIAS);                                      \
    float e10 = ex2(_a[2] - EXP_BIAS);                                      \
    float e11 = ex2(_a[3] - EXP_BIAS);                                      \
    cs[_mt][0] += e00 + e01;                                                \
    cs[_mt][1] += e10 + e11;                                                \
    const uint32_t _erA = eRow0 + (uint32_t)(_mt * 2048);                   \
    const uint32_t _cof = ((eCh ^ (uint32_t)_nt) << 4);                     \
    *(uint32_t*)(smem + (ebase) + _erA + _cof) = pack2(e00, e01);           \
    *(uint32_t*)(smem + (ebase) + _erA + 1024 + _cof) = pack2(e10, e11);    \
    } while (0)

#define EPI_BODY(ebase) do {                                                \
    EPI_UNIT(ebase, 0); EPI_UNIT(ebase, 1); EPI_UNIT(ebase, 2);             \
    EPI_UNIT(ebase, 3); EPI_UNIT(ebase, 4); EPI_UNIT(ebase, 5);             \
    EPI_UNIT(ebase, 6); EPI_UNIT(ebase, 7); } while (0)

// one GEMM2 ks-chunk
#define G2_CHUNK(ebase, vbase, ks) do {                                     \
    uint32_t af[4][4];                                                      \
    _Pragma("unroll")                                                       \
    for (int mt = 0; mt < 4; mt++)                                          \
        ldm4(af[mt], (ebase) + erow_off + mt * 2048 + ((((ks) * 2) ^ me) << 4)); \
    _Pragma("unroll")                                                       \
    for (int j = 0; j < 4; j++) {                                           \
        uint32_t bbv[4];                                                    \
        ldm4(bbv, (vbase) + vrow_off + j * 2048 + ((((ks) * 2) ^ mv) << 4)); \
        _Pragma("unroll")                                                   \
        for (int mt = 0; mt < 4; mt++) {                                    \
            mma16816(acc2[mt * 8 + j * 2],     af[mt], bbv[0], bbv[1]);     \
            mma16816(acc2[mt * 8 + j * 2 + 1], af[mt], bbv[2], bbv[3]);     \
        }                                                                   \
    } } while (0)

__global__ __launch_bounds__(256, 1)
void attn_kernel(const __half* __restrict__ qt, const __half* __restrict__ kt,
                 const __half* __restrict__ vh, float* __restrict__ out)
{
    extern __shared__ char smem[];
    const int tid  = threadIdx.x;
    const int l    = tid & 31;
    const int w    = tid >> 5;
    const int m0 = blockIdx.x * 128;
    const int b  = blockIdx.y;
    const uint32_t sb = smem_u32(smem);
    const int g = l >> 2;
    const int t = l & 3;

    const int wm1 = (w >> 1) * 32;   // GEMM1: warp 32m x 32n
    const int wn1 = (w & 1) * 32;
    const int wm2 = (w & 1) * 64;    // GEMM2: warp 64m x 64o
    const int wo2 = (w >> 1) * 64;

    const __half* kb = kt + (size_t)b * Nn * Hn;
    const __half* vb = vh + (size_t)b * On * Nn;

    // prologue: stage Q [128 m][256 h], swizzled 512B rows
    #pragma unroll
    for (int i = 0; i < 16; i++) {
        int ch = tid + i * 256;
        int r = ch >> 5, c = ch & 31;
        *(float4*)(smem + OFF_Q + r * 512 + ((c ^ (r & 7)) << 4)) =
            *(const float4*)(qt + ((size_t)(b * Nn + m0 + r)) * Hn + c * 8);
    }
    issue_k(sb, 0, kb, 0, tid);
    issue_v(sb, 0, vb, 0, tid);
    CP_COMMIT();
    issue_k(sb, 1, kb, 64, tid);
    CP_COMMIT();

    // per-lane swizzled address components
    const uint32_t qrow = sb + OFF_Q + (uint32_t)((wm1 + (l & 15)) * 512);
    const uint32_t mq   = (uint32_t)(((l >> 4) & 1) ^ (l & 7));
    const uint32_t krow_off = (uint32_t)((wn1 + ((l >> 4) << 3) + (l & 7)) * 512);
    const uint32_t mk   = (uint32_t)(((l >> 3) & 1) ^ (l & 7));
    const uint32_t erow_off = (uint32_t)((wm2 + (l & 15)) * 128);
    const uint32_t me   = (uint32_t)(((l >> 4) & 1) ^ (l & 7));
    const uint32_t vrow_off = (uint32_t)((wo2 + ((l >> 4) << 3) + (l & 7)) * 128);
    const uint32_t mv   = (uint32_t)(((l >> 3) & 1) ^ (l & 7));
    const uint32_t eRow0 = (uint32_t)((wm1 + g) * 128 + 4 * t);
    const uint32_t eCh   = (uint32_t)((wn1 >> 3) ^ g);

    float acc2[32][4] = {};
    float cs[2][2] = {};
    float acc1[8][4];

    // ---- pipeline prologue: GEMM1(0) + EPI(0) -> E0 ----
    CP_WAIT0();
    __syncthreads();
    #pragma unroll
    for (int i = 0; i < 8; i++)
        #pragma unroll
        for (int j = 0; j < 4; j++) acc1[i][j] = 0.f;
    GEMM1_BODY(sb + OFF_K + 0 * KBUF);
    EPI_BODY(OFF_E + 0 * EBUF);
    __syncthreads();

    // ---- main loop: it = 0..62 ----
    for (int it = 0; it < 63; it++) {
        issue_v(sb, (it + 1) & 1, vb, (it + 1) * 64, tid);
        if (it + 2 < 64) issue_k(sb, it & 1, kb, (it + 2) * 64, tid);
        CP_COMMIT();

        // GEMM1(it+1) first (K(it+1) resident)
        #pragma unroll
        for (int i = 0; i < 8; i++)
            #pragma unroll
            for (int j = 0; j < 4; j++) acc1[i][j] = 0.f;
        GEMM1_BODY(sb + OFF_K + ((it + 1) & 1) * KBUF);

        // GEMM2(it) with EPI(it+1) interleaved (2 units per ks chunk)
        {
            const uint32_t e2 = sb + OFF_E + (it & 1) * EBUF;
            const uint32_t v2 = sb + OFF_V + (it & 1) * VBUF;
            const uint32_t eW = OFF_E + ((it + 1) & 1) * EBUF;
            G2_CHUNK(e2, v2, 0); EPI_UNIT(eW, 0); EPI_UNIT(eW, 1);
            G2_CHUNK(e2, v2, 1); EPI_UNIT(eW, 2); EPI_UNIT(eW, 3);
            G2_CHUNK(e2, v2, 2); EPI_UNIT(eW, 4); EPI_UNIT(eW, 5);
            G2_CHUNK(e2, v2, 3); EPI_UNIT(eW, 6); EPI_UNIT(eW, 7);
        }

        CP_WAIT0();
        __syncthreads();
    }

    // ---- tail: GEMM2(63) ----
    {
        const uint32_t e2 = sb + OFF_E + 1 * EBUF;
        const uint32_t v2 = sb + OFF_V + 1 * VBUF;
        G2_CHUNK(e2, v2, 0); G2_CHUNK(e2, v2, 1);
        G2_CHUNK(e2, v2, 2); G2_CHUNK(e2, v2, 3);
    }

    // ---- colsum reduce ----
    float* CS = (float*)(smem + OFF_CS);   // [2][128]
    #pragma unroll
    for (int mt = 0; mt < 2; mt++)
        #pragma unroll
        for (int h = 0; h < 2; h++) {
            float v = cs[mt][h];
            v += __shfl_xor_sync(0xFFFFFFFFu, v, 1);
            v += __shfl_xor_sync(0xFFFFFFFFu, v, 2);
            if (t == 0) CS[(w & 1) * 128 + wm1 + mt * 16 + g + h * 8] = v;
        }
    __syncthreads();

    float inv[4][2];
    #pragma unroll
    for (int mt = 0; mt < 4; mt++) {
        int r = wm2 + mt * 16 + g;
        inv[mt][0] = 1.f / (CS[r] + CS[128 + r]);
        inv[mt][1] = 1.f / (CS[r + 8] + CS[128 + r + 8]);
    }

    // ---- output ----
    #pragma unroll
    for (int mt = 0; mt < 4; mt++) {
        const int mcol = wm2 + mt * 16 + g;
        #pragma unroll
        for (int ot = 0; ot < 8; ot++) {
            const int o = wo2 + ot * 8 + 2 * t;
            const float* a = acc2[mt * 8 + ot];
            float* p0 = out + ((size_t)(b * On + o)) * Nn + m0;
            float* p1 = p0 + Nn;
            p0[mcol]     = a[0] * inv[mt][0];
            p1[mcol]     = a[1] * inv[mt][0];
            p0[mcol + 8] = a[2] * inv[mt][1];
            p1[mcol + 8] = a[3] * inv[mt][1];
        }
    }
}

// ---------------------------------------------------------------------------
extern "C" void kernel_launch(void* const* d_in, const int* in_sizes, int n_in,
                              void* d_out, int out_size)
{
    const float* x  = (const float*)d_in[0];
    const float* Wk = (const float*)d_in[1];
    const float* bk = (const float*)d_in[2];
    const float* Wq = (const float*)d_in[3];
    const float* bq = (const float*)d_in[4];
    const float* W1 = (const float*)d_in[5];
    const float* b1 = (const float*)d_in[6];
    const float* W2 = (const float*)d_in[7];
    const float* b2 = (const float*)d_in[8];
    const float* W3 = (const float*)d_in[9];
    const float* b3 = (const float*)d_in[10];
    float* out = (float*)d_out;

    __half *x16, *whi, *ktp, *qtp, *v1h, *v2h, *vhp;
    cudaGetSymbolAddress((void**)&x16, g_x16);
    cudaGetSymbolAddress((void**)&whi, g_whi);
    cudaGetSymbolAddress((void**)&ktp, g_kt);
    cudaGetSymbolAddress((void**)&qtp, g_qt);
    cudaGetSymbolAddress((void**)&v1h, g_v1h);
    cudaGetSymbolAddress((void**)&v2h, g_v2h);
    cudaGetSymbolAddress((void**)&vhp, g_vh);

    cudaFuncSetAttribute(proj16_kernel<0,0>, cudaFuncAttributeMaxDynamicSharedMemorySize, PJ_SMEM);
    cudaFuncSetAttribute(proj16_kernel<1,1>, cudaFuncAttributeMaxDynamicSharedMemorySize, PJ_SMEM);
    cudaFuncSetAttribute(attn_kernel, cudaFuncAttributeMaxDynamicSharedMemorySize, AT_SMEM);

    x16_kernel<<<4096, 256>>>(x);
    wprep_kernel<<<dim3(256, 4), 256>>>(Wk, Wq, W1, W3);

    const float LOG2E = 1.4426950408889634f;
    proj16_kernel<1,1><<<dim3(Nn / 128, Hn / 128, 2 * Bn), 256, PJ_SMEM>>>(
        whi + 0 * 65536, bk, x16, ktp, 1.0f,
        whi + 1 * 65536, bq, qtp, LOG2E);
    proj16_kernel<0,0><<<dim3(Nn / 128, Hn / 128, Bn), 256, PJ_SMEM>>>(
        whi + 2 * 65536, b1, x16, v1h, 1.0f,
        nullptr, nullptr, nullptr, 0.f);
    gconv16_kernel<<<dim3(Nn / 512, 32, Bn), 256>>>(W2, b2);
    proj16_kernel<0,0><<<dim3(Nn / 128, Hn / 128, Bn), 256, PJ_SMEM>>>(
        whi + 3 * 65536, b3, v2h, vhp, 1.0f,
        nullptr, nullptr, nullptr, 0.f);
    attn_kernel<<<dim3(Nn / 128, Bn), 256, AT_SMEM>>>(qtp, ktp, vhp, out);
}

// round 14
// speedup vs baseline: 9.9131x; 1.0001x over previous
#include <cuda_runtime.h>
#include <cuda_fp16.h>
#include <cstdint>

#define Bn 4
#define Cn 256
#define Hn 256
#define On 256
#define Nn 4096

// ---------------- scratch (device globals) ----------------------------------
__device__ __half g_x16[(size_t)Bn*Cn*Nn];   // x fp16 [b][c][n]
__device__ __half g_whi[4 * Cn * Hn];        // W fp16 (Wk,Wq,W1,W3)
__device__ __half g_kt [(size_t)Bn*Nn*Hn];   // k^T [b][n][h]
__device__ __half g_qt [(size_t)Bn*Nn*Hn];   // q^T [b][n][h] (scaled by log2e)
__device__ __half g_v1h[(size_t)Bn*Hn*Nn];   // v1 [b][h][n]
__device__ __half g_v2h[(size_t)Bn*Hn*Nn];   // v2 [b][h][n]
__device__ __half g_vh [(size_t)Bn*On*Nn];   // v  [b][o][n]

// ---------------- helpers ----------------------------------------------------
__device__ __forceinline__ uint32_t smem_u32(const void* p) {
    uint32_t a;
    asm("{ .reg .u64 t; cvta.to.shared.u64 t, %1; cvt.u32.u64 %0, t; }" : "=r"(a) : "l"(p));
    return a;
}
__device__ __forceinline__ uint32_t packh2(__half a, __half b) {
    __half2 h = __halves2half2(a, b);
    return *reinterpret_cast<const uint32_t*>(&h);
}
// pack two f32 -> f16x2 in ONE cvt (lo = first arg)
__device__ __forceinline__ uint32_t pack2(float lo, float hi) {
    uint32_t r;
    asm("cvt.rn.f16x2.f32 %0, %1, %2;" : "=r"(r) : "f"(hi), "f"(lo));
    return r;
}
__device__ __forceinline__ float ex2(float x) {
    float r;
    asm("ex2.approx.f32 %0, %1;" : "=f"(r) : "f"(x));
    return r;
}
__device__ __forceinline__ void ldm4(uint32_t* r, uint32_t addr) {
    asm volatile("ldmatrix.sync.aligned.m8n8.x4.shared.b16 {%0,%1,%2,%3}, [%4];"
                 : "=r"(r[0]), "=r"(r[1]), "=r"(r[2]), "=r"(r[3]) : "r"(addr));
}
__device__ __forceinline__ void ldm4t(uint32_t* r, uint32_t addr) {
    asm volatile("ldmatrix.sync.aligned.m8n8.x4.trans.shared.b16 {%0,%1,%2,%3}, [%4];"
                 : "=r"(r[0]), "=r"(r[1]), "=r"(r[2]), "=r"(r[3]) : "r"(addr));
}
__device__ __forceinline__ void mma16816(float* c, const uint32_t* a, uint32_t b0, uint32_t b1) {
    asm volatile("mma.sync.aligned.m16n8k16.row.col.f32.f16.f16.f32 "
                 "{%0,%1,%2,%3}, {%4,%5,%6,%7}, {%8,%9}, {%0,%1,%2,%3};"
                 : "+f"(c[0]), "+f"(c[1]), "+f"(c[2]), "+f"(c[3])
                 : "r"(a[0]), "r"(a[1]), "r"(a[2]), "r"(a[3]), "r"(b0), "r"(b1));
}
#define CP16(dst, src) \
    asm volatile("cp.async.cg.shared.global [%0], [%1], 16;" :: "r"(dst), "l"(src))
#define CP_COMMIT() asm volatile("cp.async.commit_group;" ::: "memory")
#define CP_WAIT0()  asm volatile("cp.async.wait_group 0;" ::: "memory")
#define CP_WAIT1()  asm volatile("cp.async.wait_group 1;" ::: "memory")

// ---------------------------------------------------------------------------
// Prep: x fp32 -> fp16 ; weights fp32 -> fp16
// ---------------------------------------------------------------------------
__global__ __launch_bounds__(256) void x16_kernel(const float* __restrict__ x) {
    size_t q = (size_t)blockIdx.x * 256 + threadIdx.x;
    float4 v = *(const float4*)(x + q * 4);
    uint2 u;
    u.x = packh2(__float2half_rn(v.x), __float2half_rn(v.y));
    u.y = packh2(__float2half_rn(v.z), __float2half_rn(v.w));
    *(uint2*)(g_x16 + q * 4) = u;
}

__global__ __launch_bounds__(256) void wprep_kernel(
    const float* __restrict__ W0, const float* __restrict__ W1,
    const float* __restrict__ W2, const float* __restrict__ W3) {
    int e = blockIdx.x * 256 + threadIdx.x;
    int m = blockIdx.y;
    const float* src = (m == 0) ? W0 : (m == 1) ? W1 : (m == 2) ? W2 : W3;
    g_whi[m * 65536 + e] = __float2half_rn(src[e]);
}

// ---------------------------------------------------------------------------
// HMMA projection, CTA tile 128h x 256n, 1 CTA/SM, K chunks of 32,
// 3-stage cp.async ring, 1 sync/chunk.
// smem per buf: W[128 rows x 80B] (at 0) + X[32 rows x 528B] (at PJ_X)
// ---------------------------------------------------------------------------
#define PJ_X     10240
#define PJ_BUF   27136
#define PJ_SMEM  81408

__device__ __forceinline__ void proj_issue(
    uint32_t sb, int buf, const __half* whi,
    const __half* X, int h0, int n0, int c0, int tid)
{
    uint32_t base = sb + buf * PJ_BUF;
    #pragma unroll
    for (int i = 0; i < 6; i++) {
        int idx = tid + i * 256;
        if (idx < 1024) {
            int r = idx >> 5, c = idx & 31;
            CP16(base + PJ_X + r * 528 + c * 16, X + (size_t)(c0 + r) * Nn + n0 + c * 8);
        } else {
            int i2 = idx - 1024;
            int r = i2 >> 2, c = i2 & 3;
            CP16(base + r * 80 + c * 16, whi + (size_t)(h0 + r) * Cn + c0 + c * 8);
        }
    }
}

// MODE 0 ("N"): out [b][h][n].  MODE 1 ("T"): out [b][n][h].
// DUAL=1: gridDim.z = 8, p = z>>2 selects (A,B) weight/bias/out/scale sets.
template <int MODE, int DUAL>
__global__ __launch_bounds__(256, 1) void proj16_kernel(
    const __half* __restrict__ whiA, const float* __restrict__ biasA,
    const __half* __restrict__ X, __half* __restrict__ outA, float scaleA,
    const __half* __restrict__ whiB, const float* __restrict__ biasB,
    __half* __restrict__ outB, float scaleB)
{
    extern __shared__ char smem[];
    const uint32_t sb = smem_u32(smem);
    const int tid = threadIdx.x;
    const int l = tid & 31;
    const int w = tid >> 5;
    const int g = l >> 2;
    const int t = l & 3;
    const int n0 = blockIdx.x * 256;
    const int h0 = blockIdx.y * 128;
    const int p  = DUAL ? (blockIdx.z >> 2) : 0;
    const int b  = DUAL ? (blockIdx.z & 3) : blockIdx.z;
    const __half* whi  = (DUAL && p) ? whiB  : whiA;
    const float*  bias = (DUAL && p) ? biasB : biasA;
    __half*       out  = (DUAL && p) ? outB  : outA;
    const float   scale= (DUAL && p) ? scaleB: scaleA;
    const __half* Xb = X + (size_t)b * Cn * Nn;

    float acc[32][4] = {};   // [mi4 * 8 + j8][4]

    proj_issue(sb, 0, whi, Xb, h0, n0, 0, tid);
    CP_COMMIT();
    proj_issue(sb, 1, whi, Xb, h0, n0, 32, tid);
    CP_COMMIT();

    if (MODE == 0) {
        // warps 2(h) x 4(n): 64h x 64n per warp. A = W (ldm4), B = X (ldm4t).
        const int wh = (w & 1) * 64;
        const int wn = (w >> 1) * 64;
        const uint32_t aW = (uint32_t)((wh + (l & 15)) * 80 + (l >> 4) * 16);
        const uint32_t bX = (uint32_t)((((l >> 3) & 1) * 8 + (l & 7)) * 528 + (wn + (l >> 4) * 8) * 2);

        for (int ck = 0; ck < 8; ck++) {
            if (ck < 6) CP_WAIT1(); else CP_WAIT0();
            __syncthreads();
            if (ck <= 5) { proj_issue(sb, (ck + 2) % 3, whi, Xb, h0, n0, (ck + 2) * 32, tid);
                           CP_COMMIT(); }
            const uint32_t bb = sb + (ck % 3) * PJ_BUF;
            #pragma unroll
            for (int ks = 0; ks < 2; ks++) {
                uint32_t q[4][4];
                #pragma unroll
                for (int jj = 0; jj < 4; jj++)
                    ldm4t(q[jj], bb + PJ_X + bX + ks * 8448 + jj * 32);
                uint32_t a[4][4];
                #pragma unroll
                for (int mi = 0; mi < 4; mi++)
                    ldm4(a[mi], bb + aW + mi * 1280 + ks * 32);
                #pragma unroll
                for (int mi = 0; mi < 4; mi++)
                    #pragma unroll
                    for (int jj = 0; jj < 4; jj++) {
                        mma16816(acc[mi * 8 + jj * 2],     a[mi], q[jj][0], q[jj][1]);
                        mma16816(acc[mi * 8 + jj * 2 + 1], a[mi], q[jj][2], q[jj][3]);
                    }
            }
        }
        // epilogue: out[b][h][n]
        #pragma unroll
        for (int mi = 0; mi < 4; mi++) {
            int h = h0 + wh + mi * 16 + g;
            float bv0 = bias[h];
            float bv1 = bias[h + 8];
            #pragma unroll
            for (int j = 0; j < 8; j++) {
                int n = n0 + wn + j * 8 + 2 * t;
                float* a = acc[mi * 8 + j];
                *(uint32_t*)(out + ((size_t)(b * Hn + h)) * Nn + n) =
                    pack2((a[0] + bv0) * scale, (a[1] + bv0) * scale);
                *(uint32_t*)(out + ((size_t)(b * Hn + h + 8)) * Nn + n) =
                    pack2((a[2] + bv1) * scale, (a[3] + bv1) * scale);
            }
        }
    } else {
        // warps 4(n) x 2(h): 64n x 64h per warp. A = X (ldm4t), B = W (ldm4).
        const int wn = (w >> 1) * 64;
        const int wh = (w & 1) * 64;
        const uint32_t aX = (uint32_t)(((l >> 4) * 8 + (l & 7)) * 528 + (wn + ((l >> 3) & 1) * 8) * 2);
        const uint32_t bW = (uint32_t)((wh + ((l >> 4) << 3) + (l & 7)) * 80 + ((l >> 3) & 1) * 16);

        for (int ck = 0; ck < 8; ck++) {
            if (ck < 6) CP_WAIT1(); else CP_WAIT0();
            __syncthreads();
            if (ck <= 5) { proj_issue(sb, (ck + 2) % 3, whi, Xb, h0, n0, (ck + 2) * 32, tid);
                           CP_COMMIT(); }
            const uint32_t bb = sb + (ck % 3) * PJ_BUF;
            #pragma unroll
            for (int ks = 0; ks < 2; ks++) {
                uint32_t a[4][4];
                #pragma unroll
                for (int mi = 0; mi < 4; mi++)
                    ldm4t(a[mi], bb + PJ_X + aX + ks * 8448 + mi * 32);
                uint32_t qq[4][4];
                #pragma unroll
                for (int jj = 0; jj < 4; jj++)
                    ldm4(qq[jj], bb + bW + jj * 1280 + ks * 32);
                #pragma unroll
                for (int mi = 0; mi < 4; mi++)
                    #pragma unroll
                    for (int jj = 0; jj < 4; jj++) {
                        mma16816(acc[mi * 8 + jj * 2],     a[mi], qq[jj][0], qq[jj][1]);
                        mma16816(acc[mi * 8 + jj * 2 + 1], a[mi], qq[jj][2], qq[jj][3]);
                    }
            }
        }
        // epilogue: out[b][n][h]
        float bvj[8][2];
        #pragma unroll
        for (int j = 0; j < 8; j++) {
            bvj[j][0] = bias[h0 + wh + j * 8 + 2 * t];
            bvj[j][1] = bias[h0 + wh + j * 8 + 2 * t + 1];
        }
        #pragma unroll
        for (int mi = 0; mi < 4; mi++) {
            int nr = n0 + wn + mi * 16 + g;
            #pragma unroll
            for (int j = 0; j < 8; j++) {
                float* a = acc[mi * 8 + j];
                int hc = h0 + wh + j * 8 + 2 * t;
                *(uint32_t*)(out + ((size_t)(b * Nn + nr)) * Hn + hc) =
                    pack2((a[0] + bvj[j][0]) * scale, (a[1] + bvj[j][1]) * scale);
                *(uint32_t*)(out + ((size_t)(b * Nn + nr + 8)) * Hn + hc) =
                    pack2((a[2] + bvj[j][0]) * scale, (a[3] + bvj[j][1]) * scale);
            }
        }
    }
}

// ---------------------------------------------------------------------------
// Grouped conv1d fp16 (unchanged)
// ---------------------------------------------------------------------------
__global__ __launch_bounds__(256) void gconv16_kernel(
    const float* __restrict__ W2, const float* __restrict__ b2)
{
    __shared__ __half xs[8][536];
    __shared__ float ws[192];
    __shared__ float bs[8];

    const int tid = threadIdx.x;
    const int n0 = blockIdx.x * 512;
    const int gr = blockIdx.y;
    const int b  = blockIdx.z;

    if (tid < 192) ws[tid] = W2[gr * 192 + tid];
    if (tid < 8)   bs[tid] = b2[gr * 8 + tid];

    const __half* in = g_v1h + ((size_t)b * Hn + gr * 8) * Nn;
    for (int idx = tid; idx < 8 * 66; idx += 256) {
        int r = idx / 66, c = idx % 66;
        int gn = n0 - 8 + c * 8;
        if (gn >= 0 && gn + 8 <= Nn) {
            *(uint4*)&xs[r][c * 8] = *(const uint4*)(in + (size_t)r * Nn + gn);
        } else {
            #pragma unroll
            for (int j = 0; j < 8; j++) {
                int n = gn + j;
                xs[r][c * 8 + j] = (n >= 0 && n < Nn) ? in[(size_t)r * Nn + n] : __half(0.f);
            }
        }
    }
    __syncthreads();

    __half* ob = g_v2h + ((size_t)b * Hn + gr * 8) * Nn + n0;
    #pragma unroll
    for (int k = 0; k < 2; k++) {
        int n = tid + k * 256;
        float xm[8], x0[8], xp[8];
        #pragma unroll
        for (int i = 0; i < 8; i++) {
            xm[i] = __half2float(xs[i][8 + n - 1]);
            x0[i] = __half2float(xs[i][8 + n]);
            xp[i] = __half2float(xs[i][8 + n + 1]);
        }
        #pragma unroll
        for (int h = 0; h < 8; h++) {
            float acc = bs[h];
            #pragma unroll
            for (int i = 0; i < 8; i++) {
                acc = fmaf(ws[h * 24 + i * 3 + 0], xm[i], acc);
                acc = fmaf(ws[h * 24 + i * 3 + 1], x0[i], acc);
                acc = fmaf(ws[h * 24 + i * 3 + 2], xp[i], acc);
            }
            ob[(size_t)h * Nn + n] = __float2half_rn(fmaxf(acc, 0.f));
        }
    }
}

// ---------------------------------------------------------------------------
// Fused HMMA attention (unchanged from R12)
// ---------------------------------------------------------------------------
#define OFF_Q   0
#define OFF_K   65536
#define OFF_V   131072
#define OFF_E   196608
#define OFF_CS  229376
#define AT_SMEM 230400
#define KBUF    32768
#define VBUF    32768
#define EBUF    16384
#define EXP_BIAS 5.7707802f   /* 4 * log2(e) */

__device__ __forceinline__ void issue_k(uint32_t sb, int buf, const __half* kb, int n0, int tid) {
    uint32_t kd = sb + OFF_K + buf * KBUF;
    #pragma unroll
    for (int i = 0; i < 8; i++) {
        int ch = tid + i * 256;
        int r = ch >> 5, c = ch & 31;
        CP16(kd + r * 512 + ((c ^ (r & 7)) << 4), kb + (size_t)(n0 + r) * Hn + c * 8);
    }
}
__device__ __forceinline__ void issue_v(uint32_t sb, int buf, const __half* vb, int n0, int tid) {
    uint32_t vd = sb + OFF_V + buf * VBUF;
    #pragma unroll
    for (int i = 0; i < 8; i++) {
        int ch = tid + i * 256;
        int r = ch >> 3, c = ch & 7;
        CP16(vd + r * 128 + ((c ^ (r & 7)) << 4), vb + (size_t)r * Nn + n0 + c * 8);
    }
}

#define GEMM1_BODY(kbase) do {                                              \
    _Pragma("unroll")                                                       \
    for (int ks = 0; ks < 16; ks++) {                                       \
        uint32_t a0[4], a1[4], p[4], q[4];                                  \
        ldm4(a0, qrow + (((ks * 2) ^ mq) << 4));                            \
        ldm4(a1, qrow + 16 * 512 + (((ks * 2) ^ mq) << 4));                 \
        ldm4(p, (kbase) + krow_off + (((ks * 2) ^ mk) << 4));               \
        ldm4(q, (kbase) + krow_off + 16 * 512 + (((ks * 2) ^ mk) << 4));    \
        mma16816(acc1[0], a0, p[0], p[1]);                                  \
        mma16816(acc1[1], a0, p[2], p[3]);                                  \
        mma16816(acc1[2], a0, q[0], q[1]);                                  \
        mma16816(acc1[3], a0, q[2], q[3]);                                  \
        mma16816(acc1[4], a1, p[0], p[1]);                                  \
        mma16816(acc1[5], a1, p[2], p[3]);                                  \
        mma16816(acc1[6], a1, q[0], q[1]);                                  \
        mma16816(acc1[7], a1, q[2], q[3]);                                  \
    } } while (0)

#define EPI_UNIT(ebase, u) do {                                             \
    const int _mt = (u) >> 2, _nt = (u) & 3;                                \
    float* _a = acc1[_mt * 4 + _nt];                                        \
    float e00 = ex2(_a[0] - EXP_BIAS);                                      \
    float e01 = ex2(_a[1] - EXP_BIAS);                                      \
    float e10 = ex2(_a[2] - EXP_BIAS);                                      \
    float e11 = ex2(_a[3] - EXP_BIAS);                                      \
    cs[_mt][0] += e00 + e01;                                                \
    cs[_mt][1] += e10 + e11;                                                \
    const uint32_t _erA = eRow0 + (uint32_t)(_mt * 2048);                   \
    const uint32_t _cof = ((eCh ^ (uint32_t)_nt) << 4);                     \
    *(uint32_t*)(smem + (ebase) + _erA + _cof) = pack2(e00, e01);           \
    *(uint32_t*)(smem + (ebase) + _erA + 1024 + _cof) = pack2(e10, e11);    \
    } while (0)

#define EPI_BODY(ebase) do {                                                \
    EPI_UNIT(ebase, 0); EPI_UNIT(ebase, 1); EPI_UNIT(ebase, 2);             \
    EPI_UNIT(ebase, 3); EPI_UNIT(ebase, 4); EPI_UNIT(ebase, 5);             \
    EPI_UNIT(ebase, 6); EPI_UNIT(ebase, 7); } while (0)

#define G2_CHUNK(ebase, vbase, ks) do {                                     \
    uint32_t af[4][4];                                                      \
    _Pragma("unroll")                                                       \
    for (int mt = 0; mt < 4; mt++)                                          \
        ldm4(af[mt], (ebase) + erow_off + mt * 2048 + ((((ks) * 2) ^ me) << 4)); \
    _Pragma("unroll")                                                       \
    for (int j = 0; j < 4; j++) {                                           \
        uint32_t bbv[4];                                                    \
        ldm4(bbv, (vbase) + vrow_off + j * 2048 + ((((ks) * 2) ^ mv) << 4)); \
        _Pragma("unroll")                                                   \
        for (int mt = 0; mt < 4; mt++) {                                    \
            mma16816(acc2[mt * 8 + j * 2],     af[mt], bbv[0], bbv[1]);     \
            mma16816(acc2[mt * 8 + j * 2 + 1], af[mt], bbv[2], bbv[3]);     \
        }                                                                   \
    } } while (0)

__global__ __launch_bounds__(256, 1)
void attn_kernel(const __half* __restrict__ qt, const __half* __restrict__ kt,
                 const __half* __restrict__ vh, float* __restrict__ out)
{
    extern __shared__ char smem[];
    const int tid  = threadIdx.x;
    const int l    = tid & 31;
    const int w    = tid >> 5;
    const int m0 = blockIdx.x * 128;
    const int b  = blockIdx.y;
    const uint32_t sb = smem_u32(smem);
    const int g = l >> 2;
    const int t = l & 3;

    const int wm1 = (w >> 1) * 32;
    const int wn1 = (w & 1) * 32;
    const int wm2 = (w & 1) * 64;
    const int wo2 = (w >> 1) * 64;

    const __half* kb = kt + (size_t)b * Nn * Hn;
    const __half* vb = vh + (size_t)b * On * Nn;

    #pragma unroll
    for (int i = 0; i < 16; i++) {
        int ch = tid + i * 256;
        int r = ch >> 5, c = ch & 31;
        *(float4*)(smem + OFF_Q + r * 512 + ((c ^ (r & 7)) << 4)) =
            *(const float4*)(qt + ((size_t)(b * Nn + m0 + r)) * Hn + c * 8);
    }
    issue_k(sb, 0, kb, 0, tid);
    issue_v(sb, 0, vb, 0, tid);
    CP_COMMIT();
    issue_k(sb, 1, kb, 64, tid);
    CP_COMMIT();

    const uint32_t qrow = sb + OFF_Q + (uint32_t)((wm1 + (l & 15)) * 512);
    const uint32_t mq   = (uint32_t)(((l >> 4) & 1) ^ (l & 7));
    const uint32_t krow_off = (uint32_t)((wn1 + ((l >> 4) << 3) + (l & 7)) * 512);
    const uint32_t mk   = (uint32_t)(((l >> 3) & 1) ^ (l & 7));
    const uint32_t erow_off = (uint32_t)((wm2 + (l & 15)) * 128);
    const uint32_t me   = (uint32_t)(((l >> 4) & 1) ^ (l & 7));
    const uint32_t vrow_off = (uint32_t)((wo2 + ((l >> 4) << 3) + (l & 7)) * 128);
    const uint32_t mv   = (uint32_t)(((l >> 3) & 1) ^ (l & 7));
    const uint32_t eRow0 = (uint32_t)((wm1 + g) * 128 + 4 * t);
    const uint32_t eCh   = (uint32_t)((wn1 >> 3) ^ g);

    float acc2[32][4] = {};
    float cs[2][2] = {};
    float acc1[8][4];

    CP_WAIT0();
    __syncthreads();
    #pragma unroll
    for (int i = 0; i < 8; i++)
        #pragma unroll
        for (int j = 0; j < 4; j++) acc1[i][j] = 0.f;
    GEMM1_BODY(sb + OFF_K + 0 * KBUF);
    EPI_BODY(OFF_E + 0 * EBUF);
    __syncthreads();

    for (int it = 0; it < 63; it++) {
        issue_v(sb, (it + 1) & 1, vb, (it + 1) * 64, tid);
        if (it + 2 < 64) issue_k(sb, it & 1, kb, (it + 2) * 64, tid);
        CP_COMMIT();

        #pragma unroll
        for (int i = 0; i < 8; i++)
            #pragma unroll
            for (int j = 0; j < 4; j++) acc1[i][j] = 0.f;
        GEMM1_BODY(sb + OFF_K + ((it + 1) & 1) * KBUF);

        {
            const uint32_t e2 = sb + OFF_E + (it & 1) * EBUF;
            const uint32_t v2 = sb + OFF_V + (it & 1) * VBUF;
            const uint32_t eW = OFF_E + ((it + 1) & 1) * EBUF;
            G2_CHUNK(e2, v2, 0); EPI_UNIT(eW, 0); EPI_UNIT(eW, 1);
            G2_CHUNK(e2, v2, 1); EPI_UNIT(eW, 2); EPI_UNIT(eW, 3);
            G2_CHUNK(e2, v2, 2); EPI_UNIT(eW, 4); EPI_UNIT(eW, 5);
            G2_CHUNK(e2, v2, 3); EPI_UNIT(eW, 6); EPI_UNIT(eW, 7);
        }

        CP_WAIT0();
        __syncthreads();
    }

    {
        const uint32_t e2 = sb + OFF_E + 1 * EBUF;
        const uint32_t v2 = sb + OFF_V + 1 * VBUF;
        G2_CHUNK(e2, v2, 0); G2_CHUNK(e2, v2, 1);
        G2_CHUNK(e2, v2, 2); G2_CHUNK(e2, v2, 3);
    }

    float* CS = (float*)(smem + OFF_CS);
    #pragma unroll
    for (int mt = 0; mt < 2; mt++)
        #pragma unroll
        for (int h = 0; h < 2; h++) {
            float v = cs[mt][h];
            v += __shfl_xor_sync(0xFFFFFFFFu, v, 1);
            v += __shfl_xor_sync(0xFFFFFFFFu, v, 2);
            if (t == 0) CS[(w & 1) * 128 + wm1 + mt * 16 + g + h * 8] = v;
        }
    __syncthreads();

    float inv[4][2];
    #pragma unroll
    for (int mt = 0; mt < 4; mt++) {
        int r = wm2 + mt * 16 + g;
        inv[mt][0] = 1.f / (CS[r] + CS[128 + r]);
        inv[mt][1] = 1.f / (CS[r + 8] + CS[128 + r + 8]);
    }

    #pragma unroll
    for (int mt = 0; mt < 4; mt++) {
        const int mcol = wm2 + mt * 16 + g;
        #pragma unroll
        for (int ot = 0; ot < 8; ot++) {
            const int o = wo2 + ot * 8 + 2 * t;
            const float* a = acc2[mt * 8 + ot];
            float* p0 = out + ((size_t)(b * On + o)) * Nn + m0;
            float* p1 = p0 + Nn;
            p0[mcol]     = a[0] * inv[mt][0];
            p1[mcol]     = a[1] * inv[mt][0];
            p0[mcol + 8] = a[2] * inv[mt][1];
            p1[mcol + 8] = a[3] * inv[mt][1];
        }
    }
}

// ---------------------------------------------------------------------------
extern "C" void kernel_launch(void* const* d_in, const int* in_sizes, int n_in,
                              void* d_out, int out_size)
{
    const float* x  = (const float*)d_in[0];
    const float* Wk = (const float*)d_in[1];
    const float* bk = (const float*)d_in[2];
    const float* Wq = (const float*)d_in[3];
    const float* bq = (const float*)d_in[4];
    const float* W1 = (const float*)d_in[5];
    const float* b1 = (const float*)d_in[6];
    const float* W2 = (const float*)d_in[7];
    const float* b2 = (const float*)d_in[8];
    const float* W3 = (const float*)d_in[9];
    const float* b3 = (const float*)d_in[10];
    float* out = (float*)d_out;

    __half *x16, *whi, *ktp, *qtp, *v1h, *v2h, *vhp;
    cudaGetSymbolAddress((void**)&x16, g_x16);
    cudaGetSymbolAddress((void**)&whi, g_whi);
    cudaGetSymbolAddress((void**)&ktp, g_kt);
    cudaGetSymbolAddress((void**)&qtp, g_qt);
    cudaGetSymbolAddress((void**)&v1h, g_v1h);
    cudaGetSymbolAddress((void**)&v2h, g_v2h);
    cudaGetSymbolAddress((void**)&vhp, g_vh);

    cudaFuncSetAttribute(proj16_kernel<0,0>, cudaFuncAttributeMaxDynamicSharedMemorySize, PJ_SMEM);
    cudaFuncSetAttribute(proj16_kernel<1,1>, cudaFuncAttributeMaxDynamicSharedMemorySize, PJ_SMEM);
    cudaFuncSetAttribute(attn_kernel, cudaFuncAttributeMaxDynamicSharedMemorySize, AT_SMEM);

    x16_kernel<<<4096, 256>>>(x);
    wprep_kernel<<<dim3(256, 4), 256>>>(Wk, Wq, W1, W3);

    const float LOG2E = 1.4426950408889634f;
    proj16_kernel<1,1><<<dim3(Nn / 256, Hn / 128, 2 * Bn), 256, PJ_SMEM>>>(
        whi + 0 * 65536, bk, x16, ktp, 1.0f,
        whi + 1 * 65536, bq, qtp, LOG2E);
    proj16_kernel<0,0><<<dim3(Nn / 256, Hn / 128, Bn), 256, PJ_SMEM>>>(
        whi + 2 * 65536, b1, x16, v1h, 1.0f,
        nullptr, nullptr, nullptr, 0.f);
    gconv16_kernel<<<dim3(Nn / 512, 32, Bn), 256>>>(W2, b2);
    proj16_kernel<0,0><<<dim3(Nn / 256, Hn / 128, Bn), 256, PJ_SMEM>>>(
        whi + 3 * 65536, b3, v2h, vhp, 1.0f,
        nullptr, nullptr, nullptr, 0.f);
    attn_kernel<<<dim3(Nn / 128, Bn), 256, AT_SMEM>>>(qtp, ktp, vhp, out);
}